// round 6
// baseline (speedup 1.0000x reference)
#include <cuda_runtime.h>
#include <math.h>
#include <stdint.h>

#define BATCH 2
#define SEQ   2048
#define DMODEL 1024
#define HEADS 16
#define HDIM  64
#define MROWS (BATCH * SEQ)          // 4096
#define NQKV  (3 * DMODEL)           // 3072

// Scratch
__device__ float g_qkv[(size_t)3 * BATCH * HEADS * SEQ * HDIM];   // [part][bh][s][hd]
__device__ float g_attn[(size_t)BATCH * HEADS * SEQ * HDIM];      // [bh][s][hd]
__device__ float g_xc[(size_t)MROWS * DMODEL];                    // tf32-rounded X
__device__ float g_wqkvc[(size_t)NQKV * DMODEL];                  // tf32-rounded w_qkv
__device__ float g_wprojc[(size_t)DMODEL * DMODEL];               // tf32-rounded w_proj

__device__ __forceinline__ float f2tf_f(float x) {
    uint32_t r;
    asm("cvt.rna.tf32.f32 %0, %1;" : "=r"(r) : "f"(x));
    return __uint_as_float(r);
}
#define FU(x) __float_as_uint(x)
#define F4E(v, e) (((const float*)&(v))[e])

// D = A(16x8 row) * B(8x8 col) + D, tf32 in, fp32 accum
__device__ __forceinline__ void mma8(float* c, const uint32_t* a, const uint32_t* b) {
    asm volatile(
        "mma.sync.aligned.m16n8k8.row.col.f32.tf32.tf32.f32 "
        "{%0,%1,%2,%3}, {%4,%5,%6,%7}, {%8,%9}, {%0,%1,%2,%3};"
        : "+f"(c[0]), "+f"(c[1]), "+f"(c[2]), "+f"(c[3])
        : "r"(a[0]), "r"(a[1]), "r"(a[2]), "r"(a[3]), "r"(b[0]), "r"(b[1]));
}

// Permutation within a 32-wide k block: k = ks*8 + t + 4h  ->  pos = t*8 + ks*2 + h
__device__ __forceinline__ int perm64c(int c) {
    return ((c >> 5) << 5) + (c & 3) * 8 + ((c >> 3) & 3) * 2 + ((c >> 2) & 1);
}

// ---------------------------------------------------------------------------
// Kernel 0: one-shot tf32 rounding of X, w_qkv, w_proj.
// ---------------------------------------------------------------------------
#define N_X4  (MROWS * DMODEL / 4)         // 1048576
#define N_WQ4 (NQKV * DMODEL / 4)          // 786432
#define N_WP4 (DMODEL * DMODEL / 4)        // 262144
__global__ __launch_bounds__(256) void prep_kernel(
    const float* __restrict__ X, const float* __restrict__ Wq,
    const float* __restrict__ Wp)
{
    int i = blockIdx.x * blockDim.x + threadIdx.x;
    const float4* src;
    float4* dst;
    int off;
    if (i < N_X4)                  { src = (const float4*)X;  dst = (float4*)g_xc;     off = i; }
    else if (i < N_X4 + N_WQ4)     { src = (const float4*)Wq; dst = (float4*)g_wqkvc;  off = i - N_X4; }
    else                           { src = (const float4*)Wp; dst = (float4*)g_wprojc; off = i - N_X4 - N_WQ4; }
    float4 v = src[off];
    v.x = f2tf_f(v.x); v.y = f2tf_f(v.y); v.z = f2tf_f(v.z); v.w = f2tf_f(v.w);
    dst[off] = v;
}

// ---------------------------------------------------------------------------
// Kernel 1: QKV GEMM (pre-converted operands, no cvt in loop).
// CTA 128x64, k-tile 32, 8 warps (4m x 2n), warp 32x32.
// ---------------------------------------------------------------------------
__global__ __launch_bounds__(256, 2) void qkv_gemm_tf32(const float* __restrict__ bias)
{
    __shared__ float As[128 * 36];
    __shared__ float Bs[64 * 36];

    const float* __restrict__ X = g_xc;
    const float* __restrict__ W = g_wqkvc;

    const int tid = threadIdx.x;
    const int warp = tid >> 5, lane = tid & 31;
    const int g = lane >> 2, t = lane & 3;
    const int wm = (warp >> 1) * 32, wn = (warp & 1) * 32;
    const int mBase = blockIdx.y * 128, nBase = blockIdx.x * 64;
    const bool isV = (nBase >> 10) == 2;

    float acc[2][4][4];
#pragma unroll
    for (int mt = 0; mt < 2; mt++)
#pragma unroll
        for (int nt = 0; nt < 4; nt++)
#pragma unroll
            for (int i = 0; i < 4; i++) acc[mt][nt][i] = 0.0f;

    float4 ra[4], rb[2];
#pragma unroll
    for (int i = 0; i < 4; i++) {
        int idx = tid + i * 256, row = idx >> 3, q = idx & 7;
        ra[i] = *(const float4*)&X[(size_t)(mBase + row) * DMODEL + q * 4];
    }
#pragma unroll
    for (int i = 0; i < 2; i++) {
        int idx = tid + i * 256, row = idx >> 3, q = idx & 7;
        rb[i] = *(const float4*)&W[(size_t)(nBase + row) * DMODEL + q * 4];
    }
#pragma unroll
    for (int i = 0; i < 4; i++) {
        int idx = tid + i * 256, row = idx >> 3, q = idx & 7;
        int base = row * 36 + (q >> 1) * 2 + (q & 1);
        As[base + 0] = ra[i].x; As[base + 8] = ra[i].y;
        As[base + 16] = ra[i].z; As[base + 24] = ra[i].w;
    }
#pragma unroll
    for (int i = 0; i < 2; i++) {
        int idx = tid + i * 256, row = idx >> 3, q = idx & 7;
        int base = row * 36 + (q >> 1) * 2 + (q & 1);
        Bs[base + 0] = rb[i].x; Bs[base + 8] = rb[i].y;
        Bs[base + 16] = rb[i].z; Bs[base + 24] = rb[i].w;
    }
    __syncthreads();

    for (int kb = 0; kb < DMODEL; kb += 32) {
        if (kb + 32 < DMODEL) {
#pragma unroll
            for (int i = 0; i < 4; i++) {
                int idx = tid + i * 256, row = idx >> 3, q = idx & 7;
                ra[i] = *(const float4*)&X[(size_t)(mBase + row) * DMODEL + kb + 32 + q * 4];
            }
#pragma unroll
            for (int i = 0; i < 2; i++) {
                int idx = tid + i * 256, row = idx >> 3, q = idx & 7;
                rb[i] = *(const float4*)&W[(size_t)(nBase + row) * DMODEL + kb + 32 + q * 4];
            }
        }
#pragma unroll
        for (int kh = 0; kh < 2; kh++) {
            float4 a4[2][2], b4[4];
#pragma unroll
            for (int mt = 0; mt < 2; mt++) {
                a4[mt][0] = *(const float4*)&As[(wm + mt * 16 + g) * 36 + t * 8 + kh * 4];
                a4[mt][1] = *(const float4*)&As[(wm + mt * 16 + g + 8) * 36 + t * 8 + kh * 4];
            }
#pragma unroll
            for (int nt = 0; nt < 4; nt++)
                b4[nt] = *(const float4*)&Bs[(wn + nt * 8 + g) * 36 + t * 8 + kh * 4];
#pragma unroll
            for (int ks2 = 0; ks2 < 2; ks2++) {
                const int e = ks2 * 2;
#pragma unroll
                for (int mt = 0; mt < 2; mt++) {
                    uint32_t a[4] = { FU(F4E(a4[mt][0], e)),     FU(F4E(a4[mt][1], e)),
                                      FU(F4E(a4[mt][0], e + 1)), FU(F4E(a4[mt][1], e + 1)) };
#pragma unroll
                    for (int nt = 0; nt < 4; nt++) {
                        uint32_t b[2] = { FU(F4E(b4[nt], e)), FU(F4E(b4[nt], e + 1)) };
                        mma8(acc[mt][nt], a, b);
                    }
                }
            }
        }
        __syncthreads();
        if (kb + 32 < DMODEL) {
#pragma unroll
            for (int i = 0; i < 4; i++) {
                int idx = tid + i * 256, row = idx >> 3, q = idx & 7;
                int base = row * 36 + (q >> 1) * 2 + (q & 1);
                As[base + 0] = ra[i].x; As[base + 8] = ra[i].y;
                As[base + 16] = ra[i].z; As[base + 24] = ra[i].w;
            }
#pragma unroll
            for (int i = 0; i < 2; i++) {
                int idx = tid + i * 256, row = idx >> 3, q = idx & 7;
                int base = row * 36 + (q >> 1) * 2 + (q & 1);
                Bs[base + 0] = rb[i].x; Bs[base + 8] = rb[i].y;
                Bs[base + 16] = rb[i].z; Bs[base + 24] = rb[i].w;
            }
            __syncthreads();
        }
    }

    // Epilogue: bias, V pre-rounded to tf32, scatter to g_qkv[part][bh][s][hd]
#pragma unroll
    for (int mt = 0; mt < 2; mt++)
#pragma unroll
        for (int half = 0; half < 2; half++) {
            int row = mBase + wm + mt * 16 + g + half * 8;
            int bb = row >> 11, s = row & 2047;
#pragma unroll
            for (int nt = 0; nt < 4; nt++) {
                int col = nBase + wn + nt * 8 + 2 * t;
                float v0 = acc[mt][nt][half * 2 + 0] + bias[col];
                float v1 = acc[mt][nt][half * 2 + 1] + bias[col + 1];
                if (isV) { v0 = f2tf_f(v0); v1 = f2tf_f(v1); }
                int part = col >> 10, h = (col >> 6) & 15, hd = col & 63;
                size_t off = ((size_t)((part * BATCH + bb) * HEADS + h) * SEQ + s) * HDIM + hd;
                *(float2*)&g_qkv[off] = make_float2(v0, v1);
            }
        }
}

// ---------------------------------------------------------------------------
// Kernel 2: per-head LayerNorm (Hd=64), fold 1/sqrt(Hd) into Q, output tf32.
// ---------------------------------------------------------------------------
__global__ __launch_bounds__(256) void ln_kernel(
    const float* __restrict__ qg, const float* __restrict__ qb,
    const float* __restrict__ kg, const float* __restrict__ kb)
{
    int warp = (blockIdx.x * blockDim.x + threadIdx.x) >> 5;
    int lane = threadIdx.x & 31;
    float* base = g_qkv + (size_t)warp * 64;
    int part = warp >> 16;
    const float* gamma = (part == 0) ? qg : kg;
    const float* beta  = (part == 0) ? qb : kb;
    const float postscale = (part == 0) ? 0.125f : 1.0f;

    float x0 = base[lane], x1 = base[lane + 32];
    float s = x0 + x1;
#pragma unroll
    for (int o = 16; o >= 1; o >>= 1) s += __shfl_xor_sync(0xffffffffu, s, o);
    float mu = s * (1.0f / 64.0f);
    float d0 = x0 - mu, d1 = x1 - mu;
    float v = d0 * d0 + d1 * d1;
#pragma unroll
    for (int o = 16; o >= 1; o >>= 1) v += __shfl_xor_sync(0xffffffffu, v, o);
    float r = rsqrtf(v * (1.0f / 64.0f) + 1e-5f);
    float y0 = (d0 * r * gamma[lane]      + beta[lane])      * postscale;
    float y1 = (d1 * r * gamma[lane + 32] + beta[lane + 32]) * postscale;
    base[lane]      = f2tf_f(y0);
    base[lane + 32] = f2tf_f(y1);
}

// ---------------------------------------------------------------------------
// Kernel 3: flash attention (operands already tf32). Br=128, Bc=64, 8 warps,
// warp 16 rows x 64 keys, 2 CTAs/SM.
// ---------------------------------------------------------------------------
#define AT_STR 68
#define ATTN_SMEM ((128 * AT_STR + 64 * AT_STR + 64 * AT_STR + 128 * AT_STR) * 4)

__global__ __launch_bounds__(256, 2) void attn_tf32_kernel()
{
    extern __shared__ float smem[];
    float* Qs = smem;                    // [128][68] row-major, k-permuted
    float* Ks = Qs + 128 * AT_STR;       // [64][68]
    float* Vt = Ks + 64 * AT_STR;        // [64][68]  hd-major, key-permuted
    float* Ps = Vt + 64 * AT_STR;        // [128][68]

    const int tid = threadIdx.x;
    const int warp = tid >> 5, lane = tid & 31;
    const int g = lane >> 2, t = lane & 3;
    const int wm = warp * 16;
    const int bh = blockIdx.y;
    const int qbase = blockIdx.x * 128;

    const float* Qg = g_qkv + (size_t)bh        * (SEQ * HDIM);
    const float* Kg = g_qkv + (size_t)(32 + bh) * (SEQ * HDIM);
    const float* Vg = g_qkv + (size_t)(64 + bh) * (SEQ * HDIM);

#pragma unroll
    for (int i = 0; i < 8; i++) {
        int idx = tid + i * 256, row = idx >> 4, q = idx & 15;
        float4 v = *(const float4*)&Qg[(size_t)(qbase + row) * HDIM + q * 4];
        int base = row * AT_STR + (q >> 3) * 32 + ((q & 7) >> 1) * 2 + (q & 1);
        Qs[base + 0] = v.x; Qs[base + 8] = v.y;
        Qs[base + 16] = v.z; Qs[base + 24] = v.w;
    }

    float m_i[2] = {-1e30f, -1e30f}, l_i[2] = {0.0f, 0.0f};
    float o[8][4];
#pragma unroll
    for (int nt = 0; nt < 8; nt++)
#pragma unroll
        for (int i = 0; i < 4; i++) o[nt][i] = 0.0f;

    for (int kt = 0; kt < SEQ; kt += 64) {
        __syncthreads();
#pragma unroll
        for (int i = 0; i < 4; i++) {
            int idx = tid + i * 256, key = idx >> 4, q = idx & 15;
            float4 v = *(const float4*)&Kg[(size_t)(kt + key) * HDIM + q * 4];
            int base = key * AT_STR + (q >> 3) * 32 + ((q & 7) >> 1) * 2 + (q & 1);
            Ks[base + 0] = v.x; Ks[base + 8] = v.y;
            Ks[base + 16] = v.z; Ks[base + 24] = v.w;
        }
#pragma unroll
        for (int i = 0; i < 4; i++) {
            int idx = tid + i * 256, key = idx >> 4, q = idx & 15;
            float4 v = *(const float4*)&Vg[(size_t)(kt + key) * HDIM + q * 4];
            int pc = perm64c(key);
            Vt[(q * 4 + 0) * AT_STR + pc] = v.x;
            Vt[(q * 4 + 1) * AT_STR + pc] = v.y;
            Vt[(q * 4 + 2) * AT_STR + pc] = v.z;
            Vt[(q * 4 + 3) * AT_STR + pc] = v.w;
        }
        __syncthreads();

        float s[8][4];
#pragma unroll
        for (int nt = 0; nt < 8; nt++)
#pragma unroll
            for (int i = 0; i < 4; i++) s[nt][i] = 0.0f;

#pragma unroll
        for (int sb = 0; sb < 2; sb++)
#pragma unroll
            for (int kh = 0; kh < 2; kh++) {
                int off = sb * 32 + t * 8 + kh * 4;
                float4 qa0 = *(const float4*)&Qs[(wm + g) * AT_STR + off];
                float4 qa1 = *(const float4*)&Qs[(wm + g + 8) * AT_STR + off];
                float4 kb4[8];
#pragma unroll
                for (int nt = 0; nt < 8; nt++)
                    kb4[nt] = *(const float4*)&Ks[(nt * 8 + g) * AT_STR + off];
#pragma unroll
                for (int ks2 = 0; ks2 < 2; ks2++) {
                    const int e = ks2 * 2;
                    uint32_t a[4] = { FU(F4E(qa0, e)), FU(F4E(qa1, e)),
                                      FU(F4E(qa0, e + 1)), FU(F4E(qa1, e + 1)) };
#pragma unroll
                    for (int nt = 0; nt < 8; nt++) {
                        uint32_t b[2] = { FU(F4E(kb4[nt], e)), FU(F4E(kb4[nt], e + 1)) };
                        mma8(s[nt], a, b);
                    }
                }
            }

#pragma unroll
        for (int slot = 0; slot < 2; slot++) {
            float mx = -1e30f;
#pragma unroll
            for (int nt = 0; nt < 8; nt++) {
                mx = fmaxf(mx, s[nt][slot * 2 + 0]);
                mx = fmaxf(mx, s[nt][slot * 2 + 1]);
            }
            mx = fmaxf(mx, __shfl_xor_sync(0xffffffffu, mx, 1));
            mx = fmaxf(mx, __shfl_xor_sync(0xffffffffu, mx, 2));
            float mnew = fmaxf(m_i[slot], mx);
            float alpha = __expf(m_i[slot] - mnew);
            float rs = 0.0f;
#pragma unroll
            for (int nt = 0; nt < 8; nt++) {
                float p0 = __expf(s[nt][slot * 2 + 0] - mnew);
                float p1 = __expf(s[nt][slot * 2 + 1] - mnew);
                s[nt][slot * 2 + 0] = p0;
                s[nt][slot * 2 + 1] = p1;
                rs += p0 + p1;
            }
            rs += __shfl_xor_sync(0xffffffffu, rs, 1);
            rs += __shfl_xor_sync(0xffffffffu, rs, 2);
            l_i[slot] = l_i[slot] * alpha + rs;
            m_i[slot] = mnew;
#pragma unroll
            for (int nt = 0; nt < 8; nt++) {
                o[nt][slot * 2 + 0] *= alpha;
                o[nt][slot * 2 + 1] *= alpha;
            }
        }

#pragma unroll
        for (int slot = 0; slot < 2; slot++) {
            int row = wm + g + slot * 8;
#pragma unroll
            for (int nt = 0; nt < 8; nt++) {
#pragma unroll
                for (int j = 0; j < 2; j++) {
                    int c = nt * 8 + 2 * t + j;
                    Ps[row * AT_STR + perm64c(c)] = f2tf_f(s[nt][slot * 2 + j]);
                }
            }
        }
        __syncwarp();

#pragma unroll
        for (int sb = 0; sb < 2; sb++)
#pragma unroll
            for (int kh = 0; kh < 2; kh++) {
                int off = sb * 32 + t * 8 + kh * 4;
                float4 pa0 = *(const float4*)&Ps[(wm + g) * AT_STR + off];
                float4 pa1 = *(const float4*)&Ps[(wm + g + 8) * AT_STR + off];
                float4 vb4[8];
#pragma unroll
                for (int nt = 0; nt < 8; nt++)
                    vb4[nt] = *(const float4*)&Vt[(nt * 8 + g) * AT_STR + off];
#pragma unroll
                for (int ks2 = 0; ks2 < 2; ks2++) {
                    const int e = ks2 * 2;
                    uint32_t a[4] = { FU(F4E(pa0, e)), FU(F4E(pa1, e)),
                                      FU(F4E(pa0, e + 1)), FU(F4E(pa1, e + 1)) };
#pragma unroll
                    for (int nt = 0; nt < 8; nt++) {
                        uint32_t b[2] = { FU(F4E(vb4[nt], e)), FU(F4E(vb4[nt], e + 1)) };
                        mma8(o[nt], a, b);
                    }
                }
            }
    }

    // Normalize, tf32-round, write (proj consumes tf32)
    float* Og = g_attn + (size_t)bh * (SEQ * HDIM);
#pragma unroll
    for (int slot = 0; slot < 2; slot++) {
        float inv = 1.0f / l_i[slot];
        int row = qbase + wm + g + slot * 8;
#pragma unroll
        for (int nt = 0; nt < 8; nt++) {
            float2 r = make_float2(f2tf_f(o[nt][slot * 2 + 0] * inv),
                                   f2tf_f(o[nt][slot * 2 + 1] * inv));
            *(float2*)&Og[(size_t)row * HDIM + nt * 8 + 2 * t] = r;
        }
    }
}

// ---------------------------------------------------------------------------
// Kernel 4: projection GEMM (pre-converted operands).
// ---------------------------------------------------------------------------
__global__ __launch_bounds__(256, 2) void proj_gemm_tf32(
    const float* __restrict__ bp, float* __restrict__ out)
{
    __shared__ float As[128 * 36];
    __shared__ float Bs[64 * 36];

    const float* __restrict__ Wp = g_wprojc;

    const int tid = threadIdx.x;
    const int warp = tid >> 5, lane = tid & 31;
    const int g = lane >> 2, t = lane & 3;
    const int wm = (warp >> 1) * 32, wn = (warp & 1) * 32;
    const int mBase = blockIdx.y * 128, nBase = blockIdx.x * 64;

    float acc[2][4][4];
#pragma unroll
    for (int mt = 0; mt < 2; mt++)
#pragma unroll
        for (int nt = 0; nt < 4; nt++)
#pragma unroll
            for (int i = 0; i < 4; i++) acc[mt][nt][i] = 0.0f;

    float4 ra[4], rb[2];
    auto loadA = [&](int kb, int i) -> float4 {
        int idx = tid + i * 256, row = idx >> 3, q = idx & 7;
        int m = mBase + row, k = kb + q * 4;
        int b = m >> 11, s = m & 2047, h = k >> 6, hd = k & 63;
        return *(const float4*)&g_attn[((size_t)(b * HEADS + h) * SEQ + s) * HDIM + hd];
    };

#pragma unroll
    for (int i = 0; i < 4; i++) ra[i] = loadA(0, i);
#pragma unroll
    for (int i = 0; i < 2; i++) {
        int idx = tid + i * 256, row = idx >> 3, q = idx & 7;
        rb[i] = *(const float4*)&Wp[(size_t)(nBase + row) * DMODEL + q * 4];
    }
#pragma unroll
    for (int i = 0; i < 4; i++) {
        int idx = tid + i * 256, row = idx >> 3, q = idx & 7;
        int base = row * 36 + (q >> 1) * 2 + (q & 1);
        As[base + 0] = ra[i].x; As[base + 8] = ra[i].y;
        As[base + 16] = ra[i].z; As[base + 24] = ra[i].w;
    }
#pragma unroll
    for (int i = 0; i < 2; i++) {
        int idx = tid + i * 256, row = idx >> 3, q = idx & 7;
        int base = row * 36 + (q >> 1) * 2 + (q & 1);
        Bs[base + 0] = rb[i].x; Bs[base + 8] = rb[i].y;
        Bs[base + 16] = rb[i].z; Bs[base + 24] = rb[i].w;
    }
    __syncthreads();

    for (int kb = 0; kb < DMODEL; kb += 32) {
        if (kb + 32 < DMODEL) {
#pragma unroll
            for (int i = 0; i < 4; i++) ra[i] = loadA(kb + 32, i);
#pragma unroll
            for (int i = 0; i < 2; i++) {
                int idx = tid + i * 256, row = idx >> 3, q = idx & 7;
                rb[i] = *(const float4*)&Wp[(size_t)(nBase + row) * DMODEL + kb + 32 + q * 4];
            }
        }
#pragma unroll
        for (int kh = 0; kh < 2; kh++) {
            float4 a4[2][2], b4[4];
#pragma unroll
            for (int mt = 0; mt < 2; mt++) {
                a4[mt][0] = *(const float4*)&As[(wm + mt * 16 + g) * 36 + t * 8 + kh * 4];
                a4[mt][1] = *(const float4*)&As[(wm + mt * 16 + g + 8) * 36 + t * 8 + kh * 4];
            }
#pragma unroll
            for (int nt = 0; nt < 4; nt++)
                b4[nt] = *(const float4*)&Bs[(wn + nt * 8 + g) * 36 + t * 8 + kh * 4];
#pragma unroll
            for (int ks2 = 0; ks2 < 2; ks2++) {
                const int e = ks2 * 2;
#pragma unroll
                for (int mt = 0; mt < 2; mt++) {
                    uint32_t a[4] = { FU(F4E(a4[mt][0], e)),     FU(F4E(a4[mt][1], e)),
                                      FU(F4E(a4[mt][0], e + 1)), FU(F4E(a4[mt][1], e + 1)) };
#pragma unroll
                    for (int nt = 0; nt < 4; nt++) {
                        uint32_t b[2] = { FU(F4E(b4[nt], e)), FU(F4E(b4[nt], e + 1)) };
                        mma8(acc[mt][nt], a, b);
                    }
                }
            }
        }
        __syncthreads();
        if (kb + 32 < DMODEL) {
#pragma unroll
            for (int i = 0; i < 4; i++) {
                int idx = tid + i * 256, row = idx >> 3, q = idx & 7;
                int base = row * 36 + (q >> 1) * 2 + (q & 1);
                As[base + 0] = ra[i].x; As[base + 8] = ra[i].y;
                As[base + 16] = ra[i].z; As[base + 24] = ra[i].w;
            }
#pragma unroll
            for (int i = 0; i < 2; i++) {
                int idx = tid + i * 256, row = idx >> 3, q = idx & 7;
                int base = row * 36 + (q >> 1) * 2 + (q & 1);
                Bs[base + 0] = rb[i].x; Bs[base + 8] = rb[i].y;
                Bs[base + 16] = rb[i].z; Bs[base + 24] = rb[i].w;
            }
            __syncthreads();
        }
    }

#pragma unroll
    for (int mt = 0; mt < 2; mt++)
#pragma unroll
        for (int half = 0; half < 2; half++) {
            int row = mBase + wm + mt * 16 + g + half * 8;
#pragma unroll
            for (int nt = 0; nt < 4; nt++) {
                int col = nBase + wn + nt * 8 + 2 * t;
                float2 r = make_float2(acc[mt][nt][half * 2 + 0] + bp[col],
                                       acc[mt][nt][half * 2 + 1] + bp[col + 1]);
                *(float2*)&out[(size_t)row * DMODEL + col] = r;
            }
        }
}

// ---------------------------------------------------------------------------
// Launch. Inputs: 0:x 1:w_qkv 2:b_qkv 3:w_proj 4:b_proj 5:qg 6:qb 7:kg 8:kb
// ---------------------------------------------------------------------------
extern "C" void kernel_launch(void* const* d_in, const int* in_sizes, int n_in,
                              void* d_out, int out_size)
{
    const float* x      = (const float*)d_in[0];
    const float* w_qkv  = (const float*)d_in[1];
    const float* b_qkv  = (const float*)d_in[2];
    const float* w_proj = (const float*)d_in[3];
    const float* b_proj = (const float*)d_in[4];
    const float* q_g    = (const float*)d_in[5];
    const float* q_b    = (const float*)d_in[6];
    const float* k_g    = (const float*)d_in[7];
    const float* k_b    = (const float*)d_in[8];
    float* out = (float*)d_out;

    cudaFuncSetAttribute(attn_tf32_kernel,
                         cudaFuncAttributeMaxDynamicSharedMemorySize, ATTN_SMEM);

    int prep_total = N_X4 + N_WQ4 + N_WP4;
    prep_kernel<<<prep_total / 256, 256>>>(x, w_qkv, w_proj);

    dim3 g1(NQKV / 64, MROWS / 128);    // (48, 32)
    qkv_gemm_tf32<<<g1, 256>>>(b_qkv);

    ln_kernel<<<131072 / 8, 256>>>(q_g, q_b, k_g, k_b);

    dim3 g3(SEQ / 128, BATCH * HEADS);  // (16, 32)
    attn_tf32_kernel<<<g3, 256, ATTN_SMEM>>>();

    dim3 g4(DMODEL / 64, MROWS / 128);  // (16, 32)
    proj_gemm_tf32<<<g4, 256>>>(b_proj, out);
}

// round 8
// speedup vs baseline: 1.9783x; 1.9783x over previous
#include <cuda_runtime.h>
#include <cuda_fp16.h>
#include <math.h>
#include <stdint.h>

#define BATCH 2
#define SEQ   2048
#define DMODEL 1024
#define HEADS 16
#define HDIM  64
#define MROWS (BATCH * SEQ)          // 4096
#define NQKV  (3 * DMODEL)           // 3072
#define BH    (BATCH * HEADS)        // 32

// fp32 scratch: Q,K parts of qkv (LN input), [part2][b][h][s][hd]
__device__ float g_qkv[(size_t)2 * BATCH * HEADS * SEQ * HDIM];
// half scratch, stored as half2 "units" (uint32), k-permuted for mma fragments
__device__ uint32_t g_xh [(size_t)MROWS * 512];      // X        [4096][512u]
__device__ uint32_t g_wqh[(size_t)NQKV * 512];       // w_qkv    [3072][512u]
__device__ uint32_t g_wph[(size_t)DMODEL * 512];     // w_proj   [1024][512u]
__device__ uint32_t g_qh [(size_t)BH * SEQ * 32];    // Q (LN'd, *0.125) [bh][s][32u]
__device__ uint32_t g_kh [(size_t)BH * SEQ * 32];    // K (LN'd)         [bh][s][32u]
__device__ __half   g_vTh[(size_t)BH * HDIM * SEQ];  // V transposed [bh][hd][s] key-permuted
__device__ uint32_t g_oh [(size_t)MROWS * 512];      // attn out [4096][512u] dmodel-permuted

__device__ __forceinline__ uint32_t f2h2(float a, float b) {
    __half2 h = __floats2half2_rn(a, b);
    return *reinterpret_cast<uint32_t*>(&h);
}
// position of half2-unit u (0..15) within a 32-float k-block
__device__ __forceinline__ int p16(int u) {
    return ((u & 3) << 2) | ((u >> 3) << 1) | ((u >> 2) & 1);
}

// D += A(16x16) * B(16x8), fp16 in, fp32 accum
__device__ __forceinline__ void mma16(float* c, uint32_t a0, uint32_t a1,
                                      uint32_t a2, uint32_t a3,
                                      uint32_t b0, uint32_t b1) {
    asm volatile(
        "mma.sync.aligned.m16n8k16.row.col.f32.f16.f16.f32 "
        "{%0,%1,%2,%3}, {%4,%5,%6,%7}, {%8,%9}, {%0,%1,%2,%3};"
        : "+f"(c[0]), "+f"(c[1]), "+f"(c[2]), "+f"(c[3])
        : "r"(a0), "r"(a1), "r"(a2), "r"(a3), "r"(b0), "r"(b1));
}

// ---------------------------------------------------------------------------
// Kernel 0: fp32 -> permuted half for X, w_qkv, w_proj.
// Each thread builds one uint4 (4 units = positions 4c..4c+3 of one k-block).
// ---------------------------------------------------------------------------
#define NU4_X  (MROWS * 128)    // 524288  (128 uint4 per 1024-wide row)
#define NU4_WQ (NQKV * 128)     // 393216
#define NU4_WP (DMODEL * 128)   // 131072
#define NU4_TOT (NU4_X + NU4_WQ + NU4_WP)   // 1048576

__global__ __launch_bounds__(256) void prep_kernel(
    const float* __restrict__ X, const float* __restrict__ Wq,
    const float* __restrict__ Wp)
{
    int gi = blockIdx.x * 256 + threadIdx.x;
    const float* src; uint4* dst; int li;
    if (gi < NU4_X)                { src = X;  dst = (uint4*)g_xh;  li = gi; }
    else if (gi < NU4_X + NU4_WQ)  { src = Wq; dst = (uint4*)g_wqh; li = gi - NU4_X; }
    else                           { src = Wp; dst = (uint4*)g_wph; li = gi - NU4_X - NU4_WQ; }
    int row = li >> 7, rem = li & 127, b = rem >> 2, c = rem & 3;
    const float* base = src + (size_t)row * DMODEL + b * 32 + 2 * c;
    float2 f0 = *(const float2*)(base + 0);
    float2 f1 = *(const float2*)(base + 8);
    float2 f2 = *(const float2*)(base + 16);
    float2 f3 = *(const float2*)(base + 24);
    uint4 o;
    o.x = f2h2(f0.x, f0.y); o.y = f2h2(f1.x, f1.y);
    o.z = f2h2(f2.x, f2.y); o.w = f2h2(f3.x, f3.y);
    dst[li] = o;
}

// ---------------------------------------------------------------------------
// Kernel 1: QKV GEMM fp16. CTA 128x64, k-tile 32 (16 units), 8 warps 4m x 2n,
// warp 32x32. Q,K -> fp32 g_qkv; V -> transposed permuted half g_vTh.
// ---------------------------------------------------------------------------
__global__ __launch_bounds__(256, 2) void qkv_gemm_h(const float* __restrict__ bias)
{
    __shared__ __align__(16) uint32_t As[128 * 16];
    __shared__ __align__(16) uint32_t Bs[64 * 16];

    const int tid = threadIdx.x;
    const int warp = tid >> 5, lane = tid & 31;
    const int g = lane >> 2, t = lane & 3;
    const int wm = (warp >> 1) * 32, wn = (warp & 1) * 32;
    const int mBase = blockIdx.y * 128, nBase = blockIdx.x * 64;
    const bool isV = (nBase >> 10) == 2;

    float acc[2][4][4];
#pragma unroll
    for (int mt = 0; mt < 2; mt++)
#pragma unroll
        for (int nt = 0; nt < 4; nt++)
#pragma unroll
            for (int i = 0; i < 4; i++) acc[mt][nt][i] = 0.0f;

    // fill indices: A: idx 0..511 -> row=idx>>2, c=idx&3 ; B: 0..255
    const int ar0 = tid >> 2, ac0 = tid & 3;
    const int ar1 = (tid + 256) >> 2, ac1 = tid & 3;
    const int br = tid >> 2, bc = tid & 3;

    uint4 ra0, ra1, rb0;
    ra0 = *(const uint4*)&g_xh[(size_t)(mBase + ar0) * 512 + ac0 * 4];
    ra1 = *(const uint4*)&g_xh[(size_t)(mBase + ar1) * 512 + ac1 * 4];
    rb0 = *(const uint4*)&g_wqh[(size_t)(nBase + br) * 512 + bc * 4];
    *(uint4*)&As[ar0 * 16 + ac0 * 4] = ra0;
    *(uint4*)&As[ar1 * 16 + ac1 * 4] = ra1;
    *(uint4*)&Bs[br * 16 + bc * 4] = rb0;
    __syncthreads();

    for (int kb = 0; kb < DMODEL; kb += 32) {
        int ub = (kb >> 1) + 16;   // next k-tile unit base
        if (kb + 32 < DMODEL) {
            ra0 = *(const uint4*)&g_xh[(size_t)(mBase + ar0) * 512 + ub + ac0 * 4];
            ra1 = *(const uint4*)&g_xh[(size_t)(mBase + ar1) * 512 + ub + ac1 * 4];
            rb0 = *(const uint4*)&g_wqh[(size_t)(nBase + br) * 512 + ub + bc * 4];
        }
        uint4 af[2][2], bf[4];
#pragma unroll
        for (int mt = 0; mt < 2; mt++) {
            af[mt][0] = *(const uint4*)&As[(wm + mt * 16 + g) * 16 + t * 4];
            af[mt][1] = *(const uint4*)&As[(wm + mt * 16 + g + 8) * 16 + t * 4];
        }
#pragma unroll
        for (int nt = 0; nt < 4; nt++)
            bf[nt] = *(const uint4*)&Bs[(wn + nt * 8 + g) * 16 + t * 4];
#pragma unroll
        for (int mt = 0; mt < 2; mt++)
#pragma unroll
            for (int nt = 0; nt < 4; nt++) {
                mma16(acc[mt][nt], af[mt][0].x, af[mt][1].x, af[mt][0].y, af[mt][1].y,
                      bf[nt].x, bf[nt].y);
                mma16(acc[mt][nt], af[mt][0].z, af[mt][1].z, af[mt][0].w, af[mt][1].w,
                      bf[nt].z, bf[nt].w);
            }
        __syncthreads();
        if (kb + 32 < DMODEL) {
            *(uint4*)&As[ar0 * 16 + ac0 * 4] = ra0;
            *(uint4*)&As[ar1 * 16 + ac1 * 4] = ra1;
            *(uint4*)&Bs[br * 16 + bc * 4] = rb0;
            __syncthreads();
        }
    }

    // Epilogue
#pragma unroll
    for (int mt = 0; mt < 2; mt++)
#pragma unroll
        for (int hf = 0; hf < 2; hf++) {
            int row = mBase + wm + mt * 16 + g + hf * 8;
            int bb = row >> 11, s = row & 2047;
#pragma unroll
            for (int nt = 0; nt < 4; nt++) {
                int col = nBase + wn + nt * 8 + 2 * t;
                float v0 = acc[mt][nt][hf * 2 + 0] + bias[col];
                float v1 = acc[mt][nt][hf * 2 + 1] + bias[col + 1];
                int part = col >> 10, h = (col >> 6) & 15, hd = col & 63;
                if (!isV) {
                    size_t off = ((size_t)((part * BATCH + bb) * HEADS + h) * SEQ + s) * HDIM + hd;
                    *(float2*)&g_qkv[off] = make_float2(v0, v1);
                } else {
                    int bhv = bb * HEADS + h;
                    int u = (s & 31) >> 1, hh = s & 1;
                    int ph = (s & ~31) + p16(u) * 2 + hh;
                    g_vTh[((size_t)(bhv * HDIM + hd)     * SEQ) + ph] = __float2half_rn(v0);
                    g_vTh[((size_t)(bhv * HDIM + hd + 1) * SEQ) + ph] = __float2half_rn(v1);
                }
            }
        }
}

// ---------------------------------------------------------------------------
// Kernel 2: per-head LayerNorm; Q gets *0.125; outputs permuted half.
// One warp per row; lane handles hd pair (2l, 2l+1).
// ---------------------------------------------------------------------------
__global__ __launch_bounds__(256) void ln_kernel(
    const float* __restrict__ qg, const float* __restrict__ qb,
    const float* __restrict__ kg, const float* __restrict__ kb)
{
    int wrow = (blockIdx.x * blockDim.x + threadIdx.x) >> 5;   // 0..131071
    int lane = threadIdx.x & 31;
    int part = wrow >> 16;                    // 0=Q 1=K
    int rowqk = wrow & 65535;                 // bh*2048+s
    const float* src = g_qkv + (size_t)wrow * 64;
    const float* gamma = (part == 0) ? qg : kg;
    const float* beta  = (part == 0) ? qb : kb;
    uint32_t* dst = ((part == 0) ? g_qh : g_kh) + (size_t)rowqk * 32;
    const float sc = (part == 0) ? 0.125f : 1.0f;

    float2 x = *(const float2*)&src[2 * lane];
    float s = x.x + x.y;
#pragma unroll
    for (int o = 16; o >= 1; o >>= 1) s += __shfl_xor_sync(0xffffffffu, s, o);
    float mu = s * (1.0f / 64.0f);
    float d0 = x.x - mu, d1 = x.y - mu;
    float v = d0 * d0 + d1 * d1;
#pragma unroll
    for (int o = 16; o >= 1; o >>= 1) v += __shfl_xor_sync(0xffffffffu, v, o);
    float r = rsqrtf(v * (1.0f / 64.0f) + 1e-5f);
    float2 gm = *(const float2*)&gamma[2 * lane];
    float2 bt = *(const float2*)&beta[2 * lane];
    float y0 = (d0 * r * gm.x + bt.x) * sc;
    float y1 = (d1 * r * gm.y + bt.y) * sc;
    int outpos = ((lane >> 4) << 4) + p16(lane & 15);
    dst[outpos] = f2h2(y0, y1);
}

// ---------------------------------------------------------------------------
// Kernel 3: flash attention fp16. Br=128, Bc=64, 8 warps, warp 16 rows x 64 keys.
// Rows = 32 units, XOR-swizzled by row parity. smem 48KB.
// ---------------------------------------------------------------------------
#define ATTN_SMEM ((128 * 32 + 64 * 32 + 64 * 32 + 128 * 32) * 4)   // 49152

__global__ __launch_bounds__(256, 2) void attn_h_kernel()
{
    extern __shared__ __align__(16) uint32_t smem[];
    uint32_t* Qs = smem;             // [128][32u]
    uint32_t* Ks = Qs + 128 * 32;    // [64][32u]
    uint32_t* Vt = Ks + 64 * 32;     // [64 hd][32u keys]
    uint32_t* Ps = Vt + 64 * 32;     // [128][32u]

    const int tid = threadIdx.x;
    const int warp = tid >> 5, lane = tid & 31;
    const int g = lane >> 2, t = lane & 3;
    const int wm = warp * 16;
    const int bh = blockIdx.y;
    const int qbase = blockIdx.x * 128;

    const uint32_t* Qg = g_qh + (size_t)(bh * SEQ) * 32;
    const uint32_t* Kg = g_kh + (size_t)(bh * SEQ) * 32;
    const __half*   Vg = g_vTh + (size_t)bh * HDIM * SEQ;

    // Q fill: 128 rows x 8 chunks
#pragma unroll
    for (int i = 0; i < 4; i++) {
        int idx = tid + i * 256, row = idx >> 3, c = idx & 7;
        uint4 v = *(const uint4*)&Qg[(size_t)(qbase + row) * 32 + c * 4];
        *(uint4*)&Qs[row * 32 + ((c * 4) ^ ((row & 1) * 16))] = v;
    }

    float m_i[2] = {-1e30f, -1e30f}, l_i[2] = {0.0f, 0.0f};
    float o[8][4];
#pragma unroll
    for (int nt = 0; nt < 8; nt++)
#pragma unroll
        for (int i = 0; i < 4; i++) o[nt][i] = 0.0f;

    for (int kt = 0; kt < SEQ; kt += 64) {
        __syncthreads();
        // K fill: 64 rows x 8 chunks
#pragma unroll
        for (int i = 0; i < 2; i++) {
            int idx = tid + i * 256, row = idx >> 3, c = idx & 7;
            uint4 v = *(const uint4*)&Kg[(size_t)(kt + row) * 32 + c * 4];
            *(uint4*)&Ks[row * 32 + ((c * 4) ^ ((row & 1) * 16))] = v;
        }
        // V fill: 64 hd-rows x 8 chunks (keys already permuted in gmem)
#pragma unroll
        for (int i = 0; i < 2; i++) {
            int idx = tid + i * 256, hd = idx >> 3, c = idx & 7;
            uint4 v = *(const uint4*)(Vg + (size_t)hd * SEQ + kt + c * 8);
            *(uint4*)&Vt[hd * 32 + ((c * 4) ^ ((hd & 1) * 16))] = v;
        }
        __syncthreads();

        // S = Q K^T
        float s[8][4];
#pragma unroll
        for (int nt = 0; nt < 8; nt++)
#pragma unroll
            for (int i = 0; i < 4; i++) s[nt][i] = 0.0f;

#pragma unroll
        for (int b2 = 0; b2 < 2; b2++) {
            int r0 = wm + g, r1 = wm + g + 8;
            uint4 qa0 = *(const uint4*)&Qs[r0 * 32 + (((b2 << 4) ^ ((r0 & 1) << 4)) + t * 4)];
            uint4 qa1 = *(const uint4*)&Qs[r1 * 32 + (((b2 << 4) ^ ((r1 & 1) << 4)) + t * 4)];
#pragma unroll
            for (int nt = 0; nt < 8; nt++) {
                int rn = nt * 8 + g;
                uint4 kb = *(const uint4*)&Ks[rn * 32 + (((b2 << 4) ^ ((rn & 1) << 4)) + t * 4)];
                mma16(s[nt], qa0.x, qa1.x, qa0.y, qa1.y, kb.x, kb.y);
                mma16(s[nt], qa0.z, qa1.z, qa0.w, qa1.w, kb.z, kb.w);
            }
        }

        // online softmax (scale folded into Q)
#pragma unroll
        for (int slot = 0; slot < 2; slot++) {
            float mx = -1e30f;
#pragma unroll
            for (int nt = 0; nt < 8; nt++) {
                mx = fmaxf(mx, s[nt][slot * 2 + 0]);
                mx = fmaxf(mx, s[nt][slot * 2 + 1]);
            }
            mx = fmaxf(mx, __shfl_xor_sync(0xffffffffu, mx, 1));
            mx = fmaxf(mx, __shfl_xor_sync(0xffffffffu, mx, 2));
            float mnew = fmaxf(m_i[slot], mx);
            float alpha = __expf(m_i[slot] - mnew);
            float rs = 0.0f;
#pragma unroll
            for (int nt = 0; nt < 8; nt++) {
                float p0 = __expf(s[nt][slot * 2 + 0] - mnew);
                float p1 = __expf(s[nt][slot * 2 + 1] - mnew);
                s[nt][slot * 2 + 0] = p0;
                s[nt][slot * 2 + 1] = p1;
                rs += p0 + p1;
            }
            rs += __shfl_xor_sync(0xffffffffu, rs, 1);
            rs += __shfl_xor_sync(0xffffffffu, rs, 2);
            l_i[slot] = l_i[slot] * alpha + rs;
            m_i[slot] = mnew;
#pragma unroll
            for (int nt = 0; nt < 8; nt++) {
                o[nt][slot * 2 + 0] *= alpha;
                o[nt][slot * 2 + 1] *= alpha;
            }
        }

        // P -> Ps (half2 of adjacent keys), warp-private rows
#pragma unroll
        for (int slot = 0; slot < 2; slot++) {
            int row = wm + g + slot * 8;
#pragma unroll
            for (int nt = 0; nt < 8; nt++) {
                int u = nt * 4 + t;
                int pos = ((u >> 4) << 4) + p16(u & 15);
                Ps[row * 32 + (pos ^ ((row & 1) << 4))] =
                    f2h2(s[nt][slot * 2 + 0], s[nt][slot * 2 + 1]);
            }
        }
        __syncwarp();

        // O += P V
#pragma unroll
        for (int b2 = 0; b2 < 2; b2++) {
            int r0 = wm + g, r1 = wm + g + 8;
            uint4 pa0 = *(const uint4*)&Ps[r0 * 32 + (((b2 << 4) ^ ((r0 & 1) << 4)) + t * 4)];
            uint4 pa1 = *(const uint4*)&Ps[r1 * 32 + (((b2 << 4) ^ ((r1 & 1) << 4)) + t * 4)];
#pragma unroll
            for (int nt = 0; nt < 8; nt++) {
                int rn = nt * 8 + g;
                uint4 vb = *(const uint4*)&Vt[rn * 32 + (((b2 << 4) ^ ((rn & 1) << 4)) + t * 4)];
                mma16(o[nt], pa0.x, pa1.x, pa0.y, pa1.y, vb.x, vb.y);
                mma16(o[nt], pa0.z, pa1.z, pa0.w, pa1.w, vb.z, vb.w);
            }
        }
    }

    // epilogue: normalize, write permuted half to g_oh [m][512u]
    int b = bh >> 4, h = bh & 15;
#pragma unroll
    for (int slot = 0; slot < 2; slot++) {
        float inv = 1.0f / l_i[slot];
        int row = wm + g + slot * 8;
        size_t m = (size_t)b * SEQ + qbase + row;
#pragma unroll
        for (int nt = 0; nt < 8; nt++) {
            int u = nt * 4 + t;
            int outpos = h * 32 + ((u >> 4) << 4) + p16(u & 15);
            g_oh[m * 512 + outpos] =
                f2h2(o[nt][slot * 2 + 0] * inv, o[nt][slot * 2 + 1] * inv);
        }
    }
}

// ---------------------------------------------------------------------------
// Kernel 4: projection GEMM fp16, fp32 out.
// ---------------------------------------------------------------------------
__global__ __launch_bounds__(256, 2) void proj_gemm_h(
    const float* __restrict__ bp, float* __restrict__ out)
{
    __shared__ __align__(16) uint32_t As[128 * 16];
    __shared__ __align__(16) uint32_t Bs[64 * 16];

    const int tid = threadIdx.x;
    const int warp = tid >> 5, lane = tid & 31;
    const int g = lane >> 2, t = lane & 3;
    const int wm = (warp >> 1) * 32, wn = (warp & 1) * 32;
    const int mBase = blockIdx.y * 128, nBase = blockIdx.x * 64;

    float acc[2][4][4];
#pragma unroll
    for (int mt = 0; mt < 2; mt++)
#pragma unroll
        for (int nt = 0; nt < 4; nt++)
#pragma unroll
            for (int i = 0; i < 4; i++) acc[mt][nt][i] = 0.0f;

    const int ar0 = tid >> 2, ac0 = tid & 3;
    const int ar1 = (tid + 256) >> 2, ac1 = tid & 3;
    const int br = tid >> 2, bc = tid & 3;

    uint4 ra0, ra1, rb0;
    ra0 = *(const uint4*)&g_oh[(size_t)(mBase + ar0) * 512 + ac0 * 4];
    ra1 = *(const uint4*)&g_oh[(size_t)(mBase + ar1) * 512 + ac1 * 4];
    rb0 = *(const uint4*)&g_wph[(size_t)(nBase + br) * 512 + bc * 4];
    *(uint4*)&As[ar0 * 16 + ac0 * 4] = ra0;
    *(uint4*)&As[ar1 * 16 + ac1 * 4] = ra1;
    *(uint4*)&Bs[br * 16 + bc * 4] = rb0;
    __syncthreads();

    for (int kb = 0; kb < DMODEL; kb += 32) {
        int ub = (kb >> 1) + 16;
        if (kb + 32 < DMODEL) {
            ra0 = *(const uint4*)&g_oh[(size_t)(mBase + ar0) * 512 + ub + ac0 * 4];
            ra1 = *(const uint4*)&g_oh[(size_t)(mBase + ar1) * 512 + ub + ac1 * 4];
            rb0 = *(const uint4*)&g_wph[(size_t)(nBase + br) * 512 + ub + bc * 4];
        }
        uint4 af[2][2], bf[4];
#pragma unroll
        for (int mt = 0; mt < 2; mt++) {
            af[mt][0] = *(const uint4*)&As[(wm + mt * 16 + g) * 16 + t * 4];
            af[mt][1] = *(const uint4*)&As[(wm + mt * 16 + g + 8) * 16 + t * 4];
        }
#pragma unroll
        for (int nt = 0; nt < 4; nt++)
            bf[nt] = *(const uint4*)&Bs[(wn + nt * 8 + g) * 16 + t * 4];
#pragma unroll
        for (int mt = 0; mt < 2; mt++)
#pragma unroll
            for (int nt = 0; nt < 4; nt++) {
                mma16(acc[mt][nt], af[mt][0].x, af[mt][1].x, af[mt][0].y, af[mt][1].y,
                      bf[nt].x, bf[nt].y);
                mma16(acc[mt][nt], af[mt][0].z, af[mt][1].z, af[mt][0].w, af[mt][1].w,
                      bf[nt].z, bf[nt].w);
            }
        __syncthreads();
        if (kb + 32 < DMODEL) {
            *(uint4*)&As[ar0 * 16 + ac0 * 4] = ra0;
            *(uint4*)&As[ar1 * 16 + ac1 * 4] = ra1;
            *(uint4*)&Bs[br * 16 + bc * 4] = rb0;
            __syncthreads();
        }
    }

#pragma unroll
    for (int mt = 0; mt < 2; mt++)
#pragma unroll
        for (int hf = 0; hf < 2; hf++) {
            int row = mBase + wm + mt * 16 + g + hf * 8;
#pragma unroll
            for (int nt = 0; nt < 4; nt++) {
                int col = nBase + wn + nt * 8 + 2 * t;
                float2 r = make_float2(acc[mt][nt][hf * 2 + 0] + bp[col],
                                       acc[mt][nt][hf * 2 + 1] + bp[col + 1]);
                *(float2*)&out[(size_t)row * DMODEL + col] = r;
            }
        }
}

// ---------------------------------------------------------------------------
// Launch. Inputs: 0:x 1:w_qkv 2:b_qkv 3:w_proj 4:b_proj 5:qg 6:qb 7:kg 8:kb
// ---------------------------------------------------------------------------
extern "C" void kernel_launch(void* const* d_in, const int* in_sizes, int n_in,
                              void* d_out, int out_size)
{
    const float* x      = (const float*)d_in[0];
    const float* w_qkv  = (const float*)d_in[1];
    const float* b_qkv  = (const float*)d_in[2];
    const float* w_proj = (const float*)d_in[3];
    const float* b_proj = (const float*)d_in[4];
    const float* q_g    = (const float*)d_in[5];
    const float* q_b    = (const float*)d_in[6];
    const float* k_g    = (const float*)d_in[7];
    const float* k_b    = (const float*)d_in[8];
    float* out = (float*)d_out;

    cudaFuncSetAttribute(attn_h_kernel,
                         cudaFuncAttributeMaxDynamicSharedMemorySize, ATTN_SMEM);

    prep_kernel<<<NU4_TOT / 256, 256>>>(x, w_qkv, w_proj);

    dim3 g1(NQKV / 64, MROWS / 128);    // (48, 32)
    qkv_gemm_h<<<g1, 256>>>(b_qkv);

    ln_kernel<<<131072 / 8, 256>>>(q_g, q_b, k_g, k_b);

    dim3 g3(SEQ / 128, BH);             // (16, 32)
    attn_h_kernel<<<g3, 256, ATTN_SMEM>>>();

    dim3 g4(DMODEL / 64, MROWS / 128);  // (16, 32)
    proj_gemm_h<<<g4, 256>>>(b_proj, out);
}

// round 9
// speedup vs baseline: 2.1513x; 1.0874x over previous
#include <cuda_runtime.h>
#include <cuda_fp16.h>
#include <math.h>
#include <stdint.h>

#define BATCH 2
#define SEQ   2048
#define DMODEL 1024
#define HEADS 16
#define HDIM  64
#define MROWS (BATCH * SEQ)          // 4096
#define NQKV  (3 * DMODEL)           // 3072
#define BH    (BATCH * HEADS)        // 32

// fp32 scratch: Q,K parts of qkv (LN input)
__device__ float g_qkv[(size_t)2 * BATCH * HEADS * SEQ * HDIM];
// half scratch as half2 units (uint32), k-permuted for mma fragments
__device__ uint32_t g_xh [(size_t)MROWS * 512];
__device__ uint32_t g_wqh[(size_t)NQKV * 512];
__device__ uint32_t g_wph[(size_t)DMODEL * 512];
__device__ uint32_t g_qh [(size_t)BH * SEQ * 32];    // Q (LN'd, *0.125*log2e)
__device__ uint32_t g_kh [(size_t)BH * SEQ * 32];    // K (LN'd)
__device__ __half   g_vTh[(size_t)BH * HDIM * SEQ];  // V transposed, key-permuted
__device__ uint32_t g_oh [(size_t)MROWS * 512];      // attn out, dmodel-permuted

__device__ __forceinline__ uint32_t f2h2(float a, float b) {
    __half2 h = __floats2half2_rn(a, b);
    return *reinterpret_cast<uint32_t*>(&h);
}
__device__ __forceinline__ float ex2f(float x) {
    float r;
    asm("ex2.approx.ftz.f32 %0, %1;" : "=f"(r) : "f"(x));
    return r;
}
// position of half2-unit u (0..15) within a 32-float k-block
__device__ __forceinline__ int p16(int u) {
    return ((u & 3) << 2) | ((u >> 3) << 1) | ((u >> 2) & 1);
}
__device__ __forceinline__ void cpa16(uint32_t saddr, const void* gaddr) {
    asm volatile("cp.async.cg.shared.global [%0], [%1], 16;" :: "r"(saddr), "l"(gaddr) : "memory");
}
#define CP_COMMIT() asm volatile("cp.async.commit_group;" ::: "memory")

// D += A(16x16) * B(16x8), fp16 in, fp32 accum
__device__ __forceinline__ void mma16(float* c, uint32_t a0, uint32_t a1,
                                      uint32_t a2, uint32_t a3,
                                      uint32_t b0, uint32_t b1) {
    asm volatile(
        "mma.sync.aligned.m16n8k16.row.col.f32.f16.f16.f32 "
        "{%0,%1,%2,%3}, {%4,%5,%6,%7}, {%8,%9}, {%0,%1,%2,%3};"
        : "+f"(c[0]), "+f"(c[1]), "+f"(c[2]), "+f"(c[3])
        : "r"(a0), "r"(a1), "r"(a2), "r"(a3), "r"(b0), "r"(b1));
}

// ---------------------------------------------------------------------------
// Kernel 0: fp32 -> permuted half for X, w_qkv, w_proj.
// ---------------------------------------------------------------------------
#define NU4_X  (MROWS * 128)
#define NU4_WQ (NQKV * 128)
#define NU4_WP (DMODEL * 128)
#define NU4_TOT (NU4_X + NU4_WQ + NU4_WP)

__global__ __launch_bounds__(256) void prep_kernel(
    const float* __restrict__ X, const float* __restrict__ Wq,
    const float* __restrict__ Wp)
{
    int gi = blockIdx.x * 256 + threadIdx.x;
    const float* src; uint4* dst; int li;
    if (gi < NU4_X)                { src = X;  dst = (uint4*)g_xh;  li = gi; }
    else if (gi < NU4_X + NU4_WQ)  { src = Wq; dst = (uint4*)g_wqh; li = gi - NU4_X; }
    else                           { src = Wp; dst = (uint4*)g_wph; li = gi - NU4_X - NU4_WQ; }
    int row = li >> 7, rem = li & 127, b = rem >> 2, c = rem & 3;
    const float* base = src + (size_t)row * DMODEL + b * 32 + 2 * c;
    float2 f0 = *(const float2*)(base + 0);
    float2 f1 = *(const float2*)(base + 8);
    float2 f2 = *(const float2*)(base + 16);
    float2 f3 = *(const float2*)(base + 24);
    uint4 o;
    o.x = f2h2(f0.x, f0.y); o.y = f2h2(f1.x, f1.y);
    o.z = f2h2(f2.x, f2.y); o.w = f2h2(f3.x, f3.y);
    dst[li] = o;
}

// ---------------------------------------------------------------------------
// Kernel 1: QKV GEMM fp16. CTA 128x64, k-tile 32, 8 warps 4m x 2n, warp 32x32.
// ---------------------------------------------------------------------------
__global__ __launch_bounds__(256, 2) void qkv_gemm_h(const float* __restrict__ bias)
{
    __shared__ __align__(16) uint32_t As[128 * 16];
    __shared__ __align__(16) uint32_t Bs[64 * 16];

    const int tid = threadIdx.x;
    const int warp = tid >> 5, lane = tid & 31;
    const int g = lane >> 2, t = lane & 3;
    const int wm = (warp >> 1) * 32, wn = (warp & 1) * 32;
    const int mBase = blockIdx.y * 128, nBase = blockIdx.x * 64;
    const bool isV = (nBase >> 10) == 2;

    float acc[2][4][4];
#pragma unroll
    for (int mt = 0; mt < 2; mt++)
#pragma unroll
        for (int nt = 0; nt < 4; nt++)
#pragma unroll
            for (int i = 0; i < 4; i++) acc[mt][nt][i] = 0.0f;

    const int ar0 = tid >> 2, ac0 = tid & 3;
    const int ar1 = (tid + 256) >> 2, ac1 = tid & 3;
    const int br = tid >> 2, bc = tid & 3;

    uint4 ra0, ra1, rb0;
    ra0 = *(const uint4*)&g_xh[(size_t)(mBase + ar0) * 512 + ac0 * 4];
    ra1 = *(const uint4*)&g_xh[(size_t)(mBase + ar1) * 512 + ac1 * 4];
    rb0 = *(const uint4*)&g_wqh[(size_t)(nBase + br) * 512 + bc * 4];
    *(uint4*)&As[ar0 * 16 + ac0 * 4] = ra0;
    *(uint4*)&As[ar1 * 16 + ac1 * 4] = ra1;
    *(uint4*)&Bs[br * 16 + bc * 4] = rb0;
    __syncthreads();

    for (int kb = 0; kb < DMODEL; kb += 32) {
        int ub = (kb >> 1) + 16;
        if (kb + 32 < DMODEL) {
            ra0 = *(const uint4*)&g_xh[(size_t)(mBase + ar0) * 512 + ub + ac0 * 4];
            ra1 = *(const uint4*)&g_xh[(size_t)(mBase + ar1) * 512 + ub + ac1 * 4];
            rb0 = *(const uint4*)&g_wqh[(size_t)(nBase + br) * 512 + ub + bc * 4];
        }
        uint4 af[2][2], bf[4];
#pragma unroll
        for (int mt = 0; mt < 2; mt++) {
            af[mt][0] = *(const uint4*)&As[(wm + mt * 16 + g) * 16 + t * 4];
            af[mt][1] = *(const uint4*)&As[(wm + mt * 16 + g + 8) * 16 + t * 4];
        }
#pragma unroll
        for (int nt = 0; nt < 4; nt++)
            bf[nt] = *(const uint4*)&Bs[(wn + nt * 8 + g) * 16 + t * 4];
#pragma unroll
        for (int mt = 0; mt < 2; mt++)
#pragma unroll
            for (int nt = 0; nt < 4; nt++) {
                mma16(acc[mt][nt], af[mt][0].x, af[mt][1].x, af[mt][0].y, af[mt][1].y,
                      bf[nt].x, bf[nt].y);
                mma16(acc[mt][nt], af[mt][0].z, af[mt][1].z, af[mt][0].w, af[mt][1].w,
                      bf[nt].z, bf[nt].w);
            }
        __syncthreads();
        if (kb + 32 < DMODEL) {
            *(uint4*)&As[ar0 * 16 + ac0 * 4] = ra0;
            *(uint4*)&As[ar1 * 16 + ac1 * 4] = ra1;
            *(uint4*)&Bs[br * 16 + bc * 4] = rb0;
            __syncthreads();
        }
    }

#pragma unroll
    for (int mt = 0; mt < 2; mt++)
#pragma unroll
        for (int hf = 0; hf < 2; hf++) {
            int row = mBase + wm + mt * 16 + g + hf * 8;
            int bb = row >> 11, s = row & 2047;
#pragma unroll
            for (int nt = 0; nt < 4; nt++) {
                int col = nBase + wn + nt * 8 + 2 * t;
                float v0 = acc[mt][nt][hf * 2 + 0] + bias[col];
                float v1 = acc[mt][nt][hf * 2 + 1] + bias[col + 1];
                int part = col >> 10, h = (col >> 6) & 15, hd = col & 63;
                if (!isV) {
                    size_t off = ((size_t)((part * BATCH + bb) * HEADS + h) * SEQ + s) * HDIM + hd;
                    *(float2*)&g_qkv[off] = make_float2(v0, v1);
                } else {
                    int bhv = bb * HEADS + h;
                    int u = (s & 31) >> 1, hh = s & 1;
                    int ph = (s & ~31) + p16(u) * 2 + hh;
                    g_vTh[((size_t)(bhv * HDIM + hd)     * SEQ) + ph] = __float2half_rn(v0);
                    g_vTh[((size_t)(bhv * HDIM + hd + 1) * SEQ) + ph] = __float2half_rn(v1);
                }
            }
        }
}

// ---------------------------------------------------------------------------
// Kernel 2: per-head LayerNorm; Q gets 0.125*log2e; outputs permuted half.
// ---------------------------------------------------------------------------
__global__ __launch_bounds__(256) void ln_kernel(
    const float* __restrict__ qg, const float* __restrict__ qb,
    const float* __restrict__ kg, const float* __restrict__ kb)
{
    int wrow = (blockIdx.x * blockDim.x + threadIdx.x) >> 5;
    int lane = threadIdx.x & 31;
    int part = wrow >> 16;
    int rowqk = wrow & 65535;
    const float* src = g_qkv + (size_t)wrow * 64;
    const float* gamma = (part == 0) ? qg : kg;
    const float* beta  = (part == 0) ? qb : kb;
    uint32_t* dst = ((part == 0) ? g_qh : g_kh) + (size_t)rowqk * 32;
    const float sc = (part == 0) ? (0.125f * 1.4426950408889634f) : 1.0f;

    float2 x = *(const float2*)&src[2 * lane];
    float s = x.x + x.y;
#pragma unroll
    for (int o = 16; o >= 1; o >>= 1) s += __shfl_xor_sync(0xffffffffu, s, o);
    float mu = s * (1.0f / 64.0f);
    float d0 = x.x - mu, d1 = x.y - mu;
    float v = d0 * d0 + d1 * d1;
#pragma unroll
    for (int o = 16; o >= 1; o >>= 1) v += __shfl_xor_sync(0xffffffffu, v, o);
    float r = rsqrtf(v * (1.0f / 64.0f) + 1e-5f);
    float2 gm = *(const float2*)&gamma[2 * lane];
    float2 bt = *(const float2*)&beta[2 * lane];
    float y0 = (d0 * r * gm.x + bt.x) * sc;
    float y1 = (d1 * r * gm.y + bt.y) * sc;
    int outpos = ((lane >> 4) << 4) + p16(lane & 15);
    dst[outpos] = f2h2(y0, y1);
}

// ---------------------------------------------------------------------------
// Kernel 3: flash attention fp16, cp.async double-buffered K/V.
// Br=128, Bc=64, 8 warps, warp 16 rows x 64 keys. smem 64KB, 2 CTAs/SM.
// ---------------------------------------------------------------------------
#define NT (SEQ / 64)   // 32 tiles
#define ATTN_SMEM ((128 * 32 + 2 * 64 * 32 + 2 * 64 * 32 + 128 * 32) * 4)  // 65536

__global__ __launch_bounds__(256, 2) void attn_h_kernel()
{
    extern __shared__ __align__(16) uint32_t smem[];
    uint32_t* Qs = smem;                  // [128][32u]
    uint32_t* Ks = Qs + 128 * 32;         // [2][64][32u]
    uint32_t* Vt = Ks + 2 * 64 * 32;      // [2][64 hd][32u]
    uint32_t* Ps = Vt + 2 * 64 * 32;      // [128][32u]

    const int tid = threadIdx.x;
    const int warp = tid >> 5, lane = tid & 31;
    const int g = lane >> 2, t = lane & 3;
    const int wm = warp * 16;
    const int bh = blockIdx.y;
    const int qbase = blockIdx.x * 128;

    const uint32_t* Qg = g_qh + (size_t)(bh * SEQ) * 32;
    const uint32_t* Kg = g_kh + (size_t)(bh * SEQ) * 32;
    const __half*   Vg = g_vTh + (size_t)bh * HDIM * SEQ;

    // Q fill (once): 128 rows x 8 chunks
#pragma unroll
    for (int i = 0; i < 4; i++) {
        int idx = tid + i * 256, row = idx >> 3, c = idx & 7;
        uint4 v = *(const uint4*)&Qg[(size_t)(qbase + row) * 32 + c * 4];
        *(uint4*)&Qs[row * 32 + ((c * 4) ^ ((row & 1) * 16))] = v;
    }

    // Hoisted K/V fill addressing: thread covers rows fr and fr+32, chunk fc.
    const int fr = tid >> 3, fc = tid & 7;
    uint32_t kdst0 = (uint32_t)__cvta_generic_to_shared(
        &Ks[fr * 32 + ((fc * 4) ^ ((fr & 1) * 16))]);
    uint32_t kdst1 = (uint32_t)__cvta_generic_to_shared(
        &Ks[(fr + 32) * 32 + ((fc * 4) ^ ((fr & 1) * 16))]);
    uint32_t vdst0 = (uint32_t)__cvta_generic_to_shared(
        &Vt[fr * 32 + ((fc * 4) ^ ((fr & 1) * 16))]);
    uint32_t vdst1 = (uint32_t)__cvta_generic_to_shared(
        &Vt[(fr + 32) * 32 + ((fc * 4) ^ ((fr & 1) * 16))]);
    const uint32_t* ksrc0 = Kg + fr * 32 + fc * 4;
    const uint32_t* ksrc1 = Kg + (fr + 32) * 32 + fc * 4;
    const __half* vsrc0 = Vg + (size_t)fr * SEQ + fc * 8;
    const __half* vsrc1 = Vg + (size_t)(fr + 32) * SEQ + fc * 8;

    // prologue: tile 0 -> buffer 0
    cpa16(kdst0, ksrc0);
    cpa16(kdst1, ksrc1);
    cpa16(vdst0, vsrc0);
    cpa16(vdst1, vsrc1);
    CP_COMMIT();

    float m_i[2] = {-1e30f, -1e30f}, l_i[2] = {0.0f, 0.0f};
    float o[8][4];
#pragma unroll
    for (int nt = 0; nt < 8; nt++)
#pragma unroll
        for (int i = 0; i < 4; i++) o[nt][i] = 0.0f;

    for (int it = 0; it < NT; it++) {
        const int buf = it & 1;
        __syncthreads();   // all warps done reading the buffer we're about to overwrite
        if (it + 1 < NT) {
            uint32_t soff = (uint32_t)(((it + 1) & 1) * 2048 * 4);
            int gk = (it + 1) * 2048;          // u32 offset for K
            int gv = (it + 1) * 64;            // half offset for V
            cpa16(kdst0 + soff, ksrc0 + gk);
            cpa16(kdst1 + soff, ksrc1 + gk);
            cpa16(vdst0 + soff, vsrc0 + gv);
            cpa16(vdst1 + soff, vsrc1 + gv);
            CP_COMMIT();
            asm volatile("cp.async.wait_group 1;" ::: "memory");
        } else {
            asm volatile("cp.async.wait_group 0;" ::: "memory");
        }
        __syncthreads();   // current buffer visible to all warps

        const uint32_t* KsB = Ks + buf * 2048;
        const uint32_t* VtB = Vt + buf * 2048;

        // S = Q K^T
        float s[8][4];
#pragma unroll
        for (int nt = 0; nt < 8; nt++)
#pragma unroll
            for (int i = 0; i < 4; i++) s[nt][i] = 0.0f;

#pragma unroll
        for (int b2 = 0; b2 < 2; b2++) {
            int r0 = wm + g, r1 = wm + g + 8;
            uint4 qa0 = *(const uint4*)&Qs[r0 * 32 + (((b2 << 4) ^ ((r0 & 1) << 4)) + t * 4)];
            uint4 qa1 = *(const uint4*)&Qs[r1 * 32 + (((b2 << 4) ^ ((r1 & 1) << 4)) + t * 4)];
#pragma unroll
            for (int nt = 0; nt < 8; nt++) {
                int rn = nt * 8 + g;
                uint4 kb = *(const uint4*)&KsB[rn * 32 + (((b2 << 4) ^ ((rn & 1) << 4)) + t * 4)];
                mma16(s[nt], qa0.x, qa1.x, qa0.y, qa1.y, kb.x, kb.y);
                mma16(s[nt], qa0.z, qa1.z, qa0.w, qa1.w, kb.z, kb.w);
            }
        }

        // online softmax in log2 domain (log2e folded into Q)
#pragma unroll
        for (int slot = 0; slot < 2; slot++) {
            float mx = -1e30f;
#pragma unroll
            for (int nt = 0; nt < 8; nt++) {
                mx = fmaxf(mx, s[nt][slot * 2 + 0]);
                mx = fmaxf(mx, s[nt][slot * 2 + 1]);
            }
            mx = fmaxf(mx, __shfl_xor_sync(0xffffffffu, mx, 1));
            mx = fmaxf(mx, __shfl_xor_sync(0xffffffffu, mx, 2));
            float mnew = fmaxf(m_i[slot], mx);
            float alpha = ex2f(m_i[slot] - mnew);
            float rs = 0.0f;
#pragma unroll
            for (int nt = 0; nt < 8; nt++) {
                float p0 = ex2f(s[nt][slot * 2 + 0] - mnew);
                float p1 = ex2f(s[nt][slot * 2 + 1] - mnew);
                s[nt][slot * 2 + 0] = p0;
                s[nt][slot * 2 + 1] = p1;
                rs += p0 + p1;
            }
            rs += __shfl_xor_sync(0xffffffffu, rs, 1);
            rs += __shfl_xor_sync(0xffffffffu, rs, 2);
            l_i[slot] = l_i[slot] * alpha + rs;
            m_i[slot] = mnew;
#pragma unroll
            for (int nt = 0; nt < 8; nt++) {
                o[nt][slot * 2 + 0] *= alpha;
                o[nt][slot * 2 + 1] *= alpha;
            }
        }

        // P -> Ps, vectorized: nt 0..3 are adjacent units at t*4, nt 4..7 at 16+t*4
#pragma unroll
        for (int slot = 0; slot < 2; slot++) {
            int row = wm + g + slot * 8;
            int swz = (row & 1) << 4;
            uint4 lo = make_uint4(f2h2(s[0][slot*2], s[0][slot*2+1]),
                                  f2h2(s[1][slot*2], s[1][slot*2+1]),
                                  f2h2(s[2][slot*2], s[2][slot*2+1]),
                                  f2h2(s[3][slot*2], s[3][slot*2+1]));
            uint4 hi = make_uint4(f2h2(s[4][slot*2], s[4][slot*2+1]),
                                  f2h2(s[5][slot*2], s[5][slot*2+1]),
                                  f2h2(s[6][slot*2], s[6][slot*2+1]),
                                  f2h2(s[7][slot*2], s[7][slot*2+1]));
            *(uint4*)&Ps[row * 32 + ((t * 4) ^ swz)] = lo;
            *(uint4*)&Ps[row * 32 + ((16 + t * 4) ^ swz)] = hi;
        }
        __syncwarp();

        // O += P V
#pragma unroll
        for (int b2 = 0; b2 < 2; b2++) {
            int r0 = wm + g, r1 = wm + g + 8;
            uint4 pa0 = *(const uint4*)&Ps[r0 * 32 + (((b2 << 4) ^ ((r0 & 1) << 4)) + t * 4)];
            uint4 pa1 = *(const uint4*)&Ps[r1 * 32 + (((b2 << 4) ^ ((r1 & 1) << 4)) + t * 4)];
#pragma unroll
            for (int nt = 0; nt < 8; nt++) {
                int rn = nt * 8 + g;
                uint4 vb = *(const uint4*)&VtB[rn * 32 + (((b2 << 4) ^ ((rn & 1) << 4)) + t * 4)];
                mma16(o[nt], pa0.x, pa1.x, pa0.y, pa1.y, vb.x, vb.y);
                mma16(o[nt], pa0.z, pa1.z, pa0.w, pa1.w, vb.z, vb.w);
            }
        }
    }

    // epilogue: normalize, write permuted half to g_oh, vectorized
    int b = bh >> 4, h = bh & 15;
#pragma unroll
    for (int slot = 0; slot < 2; slot++) {
        float inv = 1.0f / l_i[slot];
        int row = wm + g + slot * 8;
        size_t m = (size_t)b * SEQ + qbase + row;
        uint4 lo = make_uint4(f2h2(o[0][slot*2]*inv, o[0][slot*2+1]*inv),
                              f2h2(o[1][slot*2]*inv, o[1][slot*2+1]*inv),
                              f2h2(o[2][slot*2]*inv, o[2][slot*2+1]*inv),
                              f2h2(o[3][slot*2]*inv, o[3][slot*2+1]*inv));
        uint4 hi = make_uint4(f2h2(o[4][slot*2]*inv, o[4][slot*2+1]*inv),
                              f2h2(o[5][slot*2]*inv, o[5][slot*2+1]*inv),
                              f2h2(o[6][slot*2]*inv, o[6][slot*2+1]*inv),
                              f2h2(o[7][slot*2]*inv, o[7][slot*2+1]*inv));
        *(uint4*)&g_oh[m * 512 + h * 32 + t * 4] = lo;
        *(uint4*)&g_oh[m * 512 + h * 32 + 16 + t * 4] = hi;
    }
}

// ---------------------------------------------------------------------------
// Kernel 4: projection GEMM fp16, fp32 out.
// ---------------------------------------------------------------------------
__global__ __launch_bounds__(256, 2) void proj_gemm_h(
    const float* __restrict__ bp, float* __restrict__ out)
{
    __shared__ __align__(16) uint32_t As[128 * 16];
    __shared__ __align__(16) uint32_t Bs[64 * 16];

    const int tid = threadIdx.x;
    const int warp = tid >> 5, lane = tid & 31;
    const int g = lane >> 2, t = lane & 3;
    const int wm = (warp >> 1) * 32, wn = (warp & 1) * 32;
    const int mBase = blockIdx.y * 128, nBase = blockIdx.x * 64;

    float acc[2][4][4];
#pragma unroll
    for (int mt = 0; mt < 2; mt++)
#pragma unroll
        for (int nt = 0; nt < 4; nt++)
#pragma unroll
            for (int i = 0; i < 4; i++) acc[mt][nt][i] = 0.0f;

    const int ar0 = tid >> 2, ac0 = tid & 3;
    const int ar1 = (tid + 256) >> 2, ac1 = tid & 3;
    const int br = tid >> 2, bc = tid & 3;

    uint4 ra0, ra1, rb0;
    ra0 = *(const uint4*)&g_oh[(size_t)(mBase + ar0) * 512 + ac0 * 4];
    ra1 = *(const uint4*)&g_oh[(size_t)(mBase + ar1) * 512 + ac1 * 4];
    rb0 = *(const uint4*)&g_wph[(size_t)(nBase + br) * 512 + bc * 4];
    *(uint4*)&As[ar0 * 16 + ac0 * 4] = ra0;
    *(uint4*)&As[ar1 * 16 + ac1 * 4] = ra1;
    *(uint4*)&Bs[br * 16 + bc * 4] = rb0;
    __syncthreads();

    for (int kb = 0; kb < DMODEL; kb += 32) {
        int ub = (kb >> 1) + 16;
        if (kb + 32 < DMODEL) {
            ra0 = *(const uint4*)&g_oh[(size_t)(mBase + ar0) * 512 + ub + ac0 * 4];
            ra1 = *(const uint4*)&g_oh[(size_t)(mBase + ar1) * 512 + ub + ac1 * 4];
            rb0 = *(const uint4*)&g_wph[(size_t)(nBase + br) * 512 + ub + bc * 4];
        }
        uint4 af[2][2], bf[4];
#pragma unroll
        for (int mt = 0; mt < 2; mt++) {
            af[mt][0] = *(const uint4*)&As[(wm + mt * 16 + g) * 16 + t * 4];
            af[mt][1] = *(const uint4*)&As[(wm + mt * 16 + g + 8) * 16 + t * 4];
        }
#pragma unroll
        for (int nt = 0; nt < 4; nt++)
            bf[nt] = *(const uint4*)&Bs[(wn + nt * 8 + g) * 16 + t * 4];
#pragma unroll
        for (int mt = 0; mt < 2; mt++)
#pragma unroll
            for (int nt = 0; nt < 4; nt++) {
                mma16(acc[mt][nt], af[mt][0].x, af[mt][1].x, af[mt][0].y, af[mt][1].y,
                      bf[nt].x, bf[nt].y);
                mma16(acc[mt][nt], af[mt][0].z, af[mt][1].z, af[mt][0].w, af[mt][1].w,
                      bf[nt].z, bf[nt].w);
            }
        __syncthreads();
        if (kb + 32 < DMODEL) {
            *(uint4*)&As[ar0 * 16 + ac0 * 4] = ra0;
            *(uint4*)&As[ar1 * 16 + ac1 * 4] = ra1;
            *(uint4*)&Bs[br * 16 + bc * 4] = rb0;
            __syncthreads();
        }
    }

#pragma unroll
    for (int mt = 0; mt < 2; mt++)
#pragma unroll
        for (int hf = 0; hf < 2; hf++) {
            int row = mBase + wm + mt * 16 + g + hf * 8;
#pragma unroll
            for (int nt = 0; nt < 4; nt++) {
                int col = nBase + wn + nt * 8 + 2 * t;
                float2 r = make_float2(acc[mt][nt][hf * 2 + 0] + bp[col],
                                       acc[mt][nt][hf * 2 + 1] + bp[col + 1]);
                *(float2*)&out[(size_t)row * DMODEL + col] = r;
            }
        }
}

// ---------------------------------------------------------------------------
// Launch. Inputs: 0:x 1:w_qkv 2:b_qkv 3:w_proj 4:b_proj 5:qg 6:qb 7:kg 8:kb
// ---------------------------------------------------------------------------
extern "C" void kernel_launch(void* const* d_in, const int* in_sizes, int n_in,
                              void* d_out, int out_size)
{
    const float* x      = (const float*)d_in[0];
    const float* w_qkv  = (const float*)d_in[1];
    const float* b_qkv  = (const float*)d_in[2];
    const float* w_proj = (const float*)d_in[3];
    const float* b_proj = (const float*)d_in[4];
    const float* q_g    = (const float*)d_in[5];
    const float* q_b    = (const float*)d_in[6];
    const float* k_g    = (const float*)d_in[7];
    const float* k_b    = (const float*)d_in[8];
    float* out = (float*)d_out;

    cudaFuncSetAttribute(attn_h_kernel,
                         cudaFuncAttributeMaxDynamicSharedMemorySize, ATTN_SMEM);

    prep_kernel<<<NU4_TOT / 256, 256>>>(x, w_qkv, w_proj);

    dim3 g1(NQKV / 64, MROWS / 128);    // (48, 32)
    qkv_gemm_h<<<g1, 256>>>(b_qkv);

    ln_kernel<<<131072 / 8, 256>>>(q_g, q_b, k_g, k_b);

    dim3 g3(SEQ / 128, BH);             // (16, 32)
    attn_h_kernel<<<g3, 256, ATTN_SMEM>>>();

    dim3 g4(DMODEL / 64, MROWS / 128);  // (16, 32)
    proj_gemm_h<<<g4, 256>>>(b_proj, out);
}

// round 10
// speedup vs baseline: 2.5650x; 1.1923x over previous
#include <cuda_runtime.h>
#include <cuda_fp16.h>
#include <math.h>
#include <stdint.h>

#define BATCH 2
#define SEQ   2048
#define DMODEL 1024
#define HEADS 16
#define HDIM  64
#define MROWS (BATCH * SEQ)          // 4096
#define NQKV  (3 * DMODEL)           // 3072
#define BH    (BATCH * HEADS)        // 32

// half scratch as half2 units (uint32), k-permuted for mma fragments
__device__ uint32_t g_xh [(size_t)MROWS * 512];
__device__ uint32_t g_wqh[(size_t)NQKV * 512];
__device__ uint32_t g_wph[(size_t)DMODEL * 512];
__device__ uint32_t g_qh [(size_t)BH * SEQ * 32];    // Q (LN'd, *0.125*log2e)
__device__ uint32_t g_kh [(size_t)BH * SEQ * 32];    // K (LN'd)
__device__ __half   g_vTh[(size_t)BH * HDIM * SEQ];  // V transposed, key-permuted
__device__ uint32_t g_oh [(size_t)MROWS * 512];      // attn out, dmodel-permuted

__device__ __forceinline__ uint32_t f2h2(float a, float b) {
    __half2 h = __floats2half2_rn(a, b);
    return *reinterpret_cast<uint32_t*>(&h);
}
__device__ __forceinline__ float ex2f(float x) {
    float r;
    asm("ex2.approx.ftz.f32 %0, %1;" : "=f"(r) : "f"(x));
    return r;
}
__device__ __forceinline__ int p16(int u) {
    return ((u & 3) << 2) | ((u >> 3) << 1) | ((u >> 2) & 1);
}
__device__ __forceinline__ void cpa16(uint32_t saddr, const void* gaddr) {
    asm volatile("cp.async.cg.shared.global [%0], [%1], 16;" :: "r"(saddr), "l"(gaddr) : "memory");
}
#define CP_COMMIT() asm volatile("cp.async.commit_group;" ::: "memory")

__device__ __forceinline__ void mma16(float* c, uint32_t a0, uint32_t a1,
                                      uint32_t a2, uint32_t a3,
                                      uint32_t b0, uint32_t b1) {
    asm volatile(
        "mma.sync.aligned.m16n8k16.row.col.f32.f16.f16.f32 "
        "{%0,%1,%2,%3}, {%4,%5,%6,%7}, {%8,%9}, {%0,%1,%2,%3};"
        : "+f"(c[0]), "+f"(c[1]), "+f"(c[2]), "+f"(c[3])
        : "r"(a0), "r"(a1), "r"(a2), "r"(a3), "r"(b0), "r"(b1));
}

// ---------------------------------------------------------------------------
// Kernel 0: fp32 -> permuted half for X, w_qkv, w_proj.
// ---------------------------------------------------------------------------
#define NU4_X  (MROWS * 128)
#define NU4_WQ (NQKV * 128)
#define NU4_WP (DMODEL * 128)
#define NU4_TOT (NU4_X + NU4_WQ + NU4_WP)

__global__ __launch_bounds__(256) void prep_kernel(
    const float* __restrict__ X, const float* __restrict__ Wq,
    const float* __restrict__ Wp)
{
    int gi = blockIdx.x * 256 + threadIdx.x;
    const float* src; uint4* dst; int li;
    if (gi < NU4_X)                { src = X;  dst = (uint4*)g_xh;  li = gi; }
    else if (gi < NU4_X + NU4_WQ)  { src = Wq; dst = (uint4*)g_wqh; li = gi - NU4_X; }
    else                           { src = Wp; dst = (uint4*)g_wph; li = gi - NU4_X - NU4_WQ; }
    int row = li >> 7, rem = li & 127, b = rem >> 2, c = rem & 3;
    const float* base = src + (size_t)row * DMODEL + b * 32 + 2 * c;
    float2 f0 = *(const float2*)(base + 0);
    float2 f1 = *(const float2*)(base + 8);
    float2 f2 = *(const float2*)(base + 16);
    float2 f3 = *(const float2*)(base + 24);
    uint4 o;
    o.x = f2h2(f0.x, f0.y); o.y = f2h2(f1.x, f1.y);
    o.z = f2h2(f2.x, f2.y); o.w = f2h2(f3.x, f3.y);
    dst[li] = o;
}

// ---------------------------------------------------------------------------
// Shared GEMM mainloop machinery: CTA 128x64, k-tile 64 (32u), cp.async x2.
// Stage layout: A[128][32u] swizzled, then B[64][32u] swizzled. STAGE=6144 u32.
// ---------------------------------------------------------------------------
#define STAGE 6144
#define GEMM_SMEM (2 * STAGE * 4)        // 49152 B
#define NTK (DMODEL / 64)                // 16

struct GemmAcc { float a[2][4][4]; };

__device__ __forceinline__ void gemm_mainloop(
    uint32_t* sm, const uint32_t* Asrc, const uint32_t* Bsrc,
    int mBase, int nBase, int tid, int wm, int wn, int g, int t,
    GemmAcc& A)
{
#pragma unroll
    for (int mt = 0; mt < 2; mt++)
#pragma unroll
        for (int nt = 0; nt < 4; nt++)
#pragma unroll
            for (int i = 0; i < 4; i++) A.a[mt][nt][i] = 0.0f;

    // fill addressing
    const int frA = tid >> 3, fc = tid & 7;          // A rows: frA, frA+32, frA+64, frA+96
    const int frB = tid >> 3;                        // B rows: frB, frB+32
    uint32_t adst[4], bdst[2];
    const uint32_t* asrc[4];
    const uint32_t* bsrc[2];
#pragma unroll
    for (int i = 0; i < 4; i++) {
        int row = frA + i * 32;
        adst[i] = (uint32_t)__cvta_generic_to_shared(
            &sm[row * 32 + ((fc * 4) ^ ((row & 1) * 16))]);
        asrc[i] = Asrc + (size_t)(mBase + row) * 512 + fc * 4;
    }
#pragma unroll
    for (int i = 0; i < 2; i++) {
        int row = frB + i * 32;
        bdst[i] = (uint32_t)__cvta_generic_to_shared(
            &sm[4096 + row * 32 + ((fc * 4) ^ ((row & 1) * 16))]);
        bsrc[i] = Bsrc + (size_t)(nBase + row) * 512 + fc * 4;
    }

    // prologue: tile 0 -> stage 0
#pragma unroll
    for (int i = 0; i < 4; i++) cpa16(adst[i], asrc[i]);
#pragma unroll
    for (int i = 0; i < 2; i++) cpa16(bdst[i], bsrc[i]);
    CP_COMMIT();

    for (int it = 0; it < NTK; it++) {
        const int buf = it & 1;
        __syncthreads();
        if (it + 1 < NTK) {
            uint32_t soff = (uint32_t)(((it + 1) & 1) * STAGE * 4);
            int gofs = (it + 1) * 32;
#pragma unroll
            for (int i = 0; i < 4; i++) cpa16(adst[i] + soff, asrc[i] + gofs);
#pragma unroll
            for (int i = 0; i < 2; i++) cpa16(bdst[i] + soff, bsrc[i] + gofs);
            CP_COMMIT();
            asm volatile("cp.async.wait_group 1;" ::: "memory");
        } else {
            asm volatile("cp.async.wait_group 0;" ::: "memory");
        }
        __syncthreads();

        const uint32_t* Ab = sm + buf * STAGE;
        const uint32_t* Bb = Ab + 4096;
#pragma unroll
        for (int b2 = 0; b2 < 2; b2++) {
            uint4 af[2][2], bf[4];
#pragma unroll
            for (int mt = 0; mt < 2; mt++) {
                int r0 = wm + mt * 16 + g, r1 = r0 + 8;
                af[mt][0] = *(const uint4*)&Ab[r0 * 32 + (((b2 << 4) ^ ((r0 & 1) << 4)) + t * 4)];
                af[mt][1] = *(const uint4*)&Ab[r1 * 32 + (((b2 << 4) ^ ((r1 & 1) << 4)) + t * 4)];
            }
#pragma unroll
            for (int nt = 0; nt < 4; nt++) {
                int rn = wn + nt * 8 + g;
                bf[nt] = *(const uint4*)&Bb[rn * 32 + (((b2 << 4) ^ ((rn & 1) << 4)) + t * 4)];
            }
#pragma unroll
            for (int mt = 0; mt < 2; mt++)
#pragma unroll
                for (int nt = 0; nt < 4; nt++) {
                    mma16(A.a[mt][nt], af[mt][0].x, af[mt][1].x, af[mt][0].y, af[mt][1].y,
                          bf[nt].x, bf[nt].y);
                    mma16(A.a[mt][nt], af[mt][0].z, af[mt][1].z, af[mt][0].w, af[mt][1].w,
                          bf[nt].z, bf[nt].w);
                }
        }
    }
    __syncthreads();   // protect smem before epilogue overlays it
}

// ---------------------------------------------------------------------------
// Kernel 1: QKV GEMM + fused LN. Q/K tiles: LN in epilogue -> g_qh/g_kh.
// V tiles: direct scatter -> g_vTh.
// ---------------------------------------------------------------------------
__global__ __launch_bounds__(256, 2) void qkv_gemm_h(
    const float* __restrict__ bias,
    const float* __restrict__ qg, const float* __restrict__ qb,
    const float* __restrict__ kg, const float* __restrict__ kb)
{
    extern __shared__ __align__(16) uint32_t sm[];
    const int tid = threadIdx.x;
    const int warp = tid >> 5, lane = tid & 31;
    const int g = lane >> 2, t = lane & 3;
    const int wm = (warp >> 1) * 32, wn = (warp & 1) * 32;
    const int mBase = blockIdx.y * 128, nBase = blockIdx.x * 64;
    const int part = nBase >> 10;            // 0=Q 1=K 2=V
    const int h = (nBase >> 6) & 15;

    GemmAcc A;
    gemm_mainloop(sm, g_xh, g_wqh, mBase, nBase, tid, wm, wn, g, t, A);

    if (part == 2) {
        // V: scatter transposed permuted half
#pragma unroll
        for (int mt = 0; mt < 2; mt++)
#pragma unroll
            for (int hf = 0; hf < 2; hf++) {
                int row = mBase + wm + mt * 16 + g + hf * 8;
                int bb = row >> 11, s = row & 2047;
                int bhv = bb * HEADS + h;
                int u = (s & 31) >> 1, hh = s & 1;
                int ph = (s & ~31) + p16(u) * 2 + hh;
#pragma unroll
                for (int nt = 0; nt < 4; nt++) {
                    int col = nBase + wn + nt * 8 + 2 * t;
                    float v0 = A.a[mt][nt][hf * 2 + 0] + bias[col];
                    float v1 = A.a[mt][nt][hf * 2 + 1] + bias[col + 1];
                    int hd = col & 63;
                    g_vTh[((size_t)(bhv * HDIM + hd)     * SEQ) + ph] = __float2half_rn(v0);
                    g_vTh[((size_t)(bhv * HDIM + hd + 1) * SEQ) + ph] = __float2half_rn(v1);
                }
            }
        return;
    }

    // Q/K: stage acc+bias in smem tile T[128][68], then warp-per-row LN.
    float* T = (float*)sm;
#pragma unroll
    for (int mt = 0; mt < 2; mt++)
#pragma unroll
        for (int hf = 0; hf < 2; hf++) {
            int rl = wm + mt * 16 + g + hf * 8;
#pragma unroll
            for (int nt = 0; nt < 4; nt++) {
                int col = wn + nt * 8 + 2 * t;
                float2 v = make_float2(A.a[mt][nt][hf * 2 + 0] + bias[nBase + col],
                                       A.a[mt][nt][hf * 2 + 1] + bias[nBase + col + 1]);
                *(float2*)&T[rl * 68 + col] = v;
            }
        }
    __syncthreads();

    const float* gamma = (part == 0) ? qg : kg;
    const float* beta  = (part == 0) ? qb : kb;
    uint32_t* dstbase = (part == 0) ? g_qh : g_kh;
    const float sc = (part == 0) ? (0.125f * 1.4426950408889634f) : 1.0f;
    float2 gm = *(const float2*)&gamma[2 * lane];
    float2 bt = *(const float2*)&beta[2 * lane];
    const int outpos = ((lane >> 4) << 4) + p16(lane & 15);

    for (int r16 = 0; r16 < 16; r16++) {
        int rl = warp * 16 + r16;
        float2 x = *(const float2*)&T[rl * 68 + 2 * lane];
        float s = x.x + x.y;
#pragma unroll
        for (int o = 16; o >= 1; o >>= 1) s += __shfl_xor_sync(0xffffffffu, s, o);
        float mu = s * (1.0f / 64.0f);
        float d0 = x.x - mu, d1 = x.y - mu;
        float v = d0 * d0 + d1 * d1;
#pragma unroll
        for (int o = 16; o >= 1; o >>= 1) v += __shfl_xor_sync(0xffffffffu, v, o);
        float r = rsqrtf(v * (1.0f / 64.0f) + 1e-5f);
        float y0 = (d0 * r * gm.x + bt.x) * sc;
        float y1 = (d1 * r * gm.y + bt.y) * sc;
        int m = mBase + rl;
        int bb = m >> 11, s2 = m & 2047;
        dstbase[((size_t)(bb * HEADS + h) * SEQ + s2) * 32 + outpos] = f2h2(y0, y1);
    }
}

// ---------------------------------------------------------------------------
// Kernel 3: flash attention fp16, cp.async double-buffered K/V (unchanged r9).
// ---------------------------------------------------------------------------
#define NT (SEQ / 64)
#define ATTN_SMEM ((128 * 32 + 2 * 64 * 32 + 2 * 64 * 32 + 128 * 32) * 4)  // 65536

__global__ __launch_bounds__(256, 2) void attn_h_kernel()
{
    extern __shared__ __align__(16) uint32_t smem[];
    uint32_t* Qs = smem;
    uint32_t* Ks = Qs + 128 * 32;
    uint32_t* Vt = Ks + 2 * 64 * 32;
    uint32_t* Ps = Vt + 2 * 64 * 32;

    const int tid = threadIdx.x;
    const int warp = tid >> 5, lane = tid & 31;
    const int g = lane >> 2, t = lane & 3;
    const int wm = warp * 16;
    const int bh = blockIdx.y;
    const int qbase = blockIdx.x * 128;

    const uint32_t* Qg = g_qh + (size_t)(bh * SEQ) * 32;
    const uint32_t* Kg = g_kh + (size_t)(bh * SEQ) * 32;
    const __half*   Vg = g_vTh + (size_t)bh * HDIM * SEQ;

#pragma unroll
    for (int i = 0; i < 4; i++) {
        int idx = tid + i * 256, row = idx >> 3, c = idx & 7;
        uint4 v = *(const uint4*)&Qg[(size_t)(qbase + row) * 32 + c * 4];
        *(uint4*)&Qs[row * 32 + ((c * 4) ^ ((row & 1) * 16))] = v;
    }

    const int fr = tid >> 3, fc = tid & 7;
    uint32_t kdst0 = (uint32_t)__cvta_generic_to_shared(
        &Ks[fr * 32 + ((fc * 4) ^ ((fr & 1) * 16))]);
    uint32_t kdst1 = (uint32_t)__cvta_generic_to_shared(
        &Ks[(fr + 32) * 32 + ((fc * 4) ^ ((fr & 1) * 16))]);
    uint32_t vdst0 = (uint32_t)__cvta_generic_to_shared(
        &Vt[fr * 32 + ((fc * 4) ^ ((fr & 1) * 16))]);
    uint32_t vdst1 = (uint32_t)__cvta_generic_to_shared(
        &Vt[(fr + 32) * 32 + ((fc * 4) ^ ((fr & 1) * 16))]);
    const uint32_t* ksrc0 = Kg + fr * 32 + fc * 4;
    const uint32_t* ksrc1 = Kg + (fr + 32) * 32 + fc * 4;
    const __half* vsrc0 = Vg + (size_t)fr * SEQ + fc * 8;
    const __half* vsrc1 = Vg + (size_t)(fr + 32) * SEQ + fc * 8;

    cpa16(kdst0, ksrc0);
    cpa16(kdst1, ksrc1);
    cpa16(vdst0, vsrc0);
    cpa16(vdst1, vsrc1);
    CP_COMMIT();

    float m_i[2] = {-1e30f, -1e30f}, l_i[2] = {0.0f, 0.0f};
    float o[8][4];
#pragma unroll
    for (int nt = 0; nt < 8; nt++)
#pragma unroll
        for (int i = 0; i < 4; i++) o[nt][i] = 0.0f;

    for (int it = 0; it < NT; it++) {
        const int buf = it & 1;
        __syncthreads();
        if (it + 1 < NT) {
            uint32_t soff = (uint32_t)(((it + 1) & 1) * 2048 * 4);
            int gk = (it + 1) * 2048;
            int gv = (it + 1) * 64;
            cpa16(kdst0 + soff, ksrc0 + gk);
            cpa16(kdst1 + soff, ksrc1 + gk);
            cpa16(vdst0 + soff, vsrc0 + gv);
            cpa16(vdst1 + soff, vsrc1 + gv);
            CP_COMMIT();
            asm volatile("cp.async.wait_group 1;" ::: "memory");
        } else {
            asm volatile("cp.async.wait_group 0;" ::: "memory");
        }
        __syncthreads();

        const uint32_t* KsB = Ks + buf * 2048;
        const uint32_t* VtB = Vt + buf * 2048;

        float s[8][4];
#pragma unroll
        for (int nt = 0; nt < 8; nt++)
#pragma unroll
            for (int i = 0; i < 4; i++) s[nt][i] = 0.0f;

#pragma unroll
        for (int b2 = 0; b2 < 2; b2++) {
            int r0 = wm + g, r1 = wm + g + 8;
            uint4 qa0 = *(const uint4*)&Qs[r0 * 32 + (((b2 << 4) ^ ((r0 & 1) << 4)) + t * 4)];
            uint4 qa1 = *(const uint4*)&Qs[r1 * 32 + (((b2 << 4) ^ ((r1 & 1) << 4)) + t * 4)];
#pragma unroll
            for (int nt = 0; nt < 8; nt++) {
                int rn = nt * 8 + g;
                uint4 kb = *(const uint4*)&KsB[rn * 32 + (((b2 << 4) ^ ((rn & 1) << 4)) + t * 4)];
                mma16(s[nt], qa0.x, qa1.x, qa0.y, qa1.y, kb.x, kb.y);
                mma16(s[nt], qa0.z, qa1.z, qa0.w, qa1.w, kb.z, kb.w);
            }
        }

#pragma unroll
        for (int slot = 0; slot < 2; slot++) {
            float mx = -1e30f;
#pragma unroll
            for (int nt = 0; nt < 8; nt++) {
                mx = fmaxf(mx, s[nt][slot * 2 + 0]);
                mx = fmaxf(mx, s[nt][slot * 2 + 1]);
            }
            mx = fmaxf(mx, __shfl_xor_sync(0xffffffffu, mx, 1));
            mx = fmaxf(mx, __shfl_xor_sync(0xffffffffu, mx, 2));
            float mnew = fmaxf(m_i[slot], mx);
            float alpha = ex2f(m_i[slot] - mnew);
            float rs = 0.0f;
#pragma unroll
            for (int nt = 0; nt < 8; nt++) {
                float p0 = ex2f(s[nt][slot * 2 + 0] - mnew);
                float p1 = ex2f(s[nt][slot * 2 + 1] - mnew);
                s[nt][slot * 2 + 0] = p0;
                s[nt][slot * 2 + 1] = p1;
                rs += p0 + p1;
            }
            rs += __shfl_xor_sync(0xffffffffu, rs, 1);
            rs += __shfl_xor_sync(0xffffffffu, rs, 2);
            l_i[slot] = l_i[slot] * alpha + rs;
            m_i[slot] = mnew;
#pragma unroll
            for (int nt = 0; nt < 8; nt++) {
                o[nt][slot * 2 + 0] *= alpha;
                o[nt][slot * 2 + 1] *= alpha;
            }
        }

#pragma unroll
        for (int slot = 0; slot < 2; slot++) {
            int row = wm + g + slot * 8;
            int swz = (row & 1) << 4;
            uint4 lo = make_uint4(f2h2(s[0][slot*2], s[0][slot*2+1]),
                                  f2h2(s[1][slot*2], s[1][slot*2+1]),
                                  f2h2(s[2][slot*2], s[2][slot*2+1]),
                                  f2h2(s[3][slot*2], s[3][slot*2+1]));
            uint4 hi = make_uint4(f2h2(s[4][slot*2], s[4][slot*2+1]),
                                  f2h2(s[5][slot*2], s[5][slot*2+1]),
                                  f2h2(s[6][slot*2], s[6][slot*2+1]),
                                  f2h2(s[7][slot*2], s[7][slot*2+1]));
            *(uint4*)&Ps[row * 32 + ((t * 4) ^ swz)] = lo;
            *(uint4*)&Ps[row * 32 + ((16 + t * 4) ^ swz)] = hi;
        }
        __syncwarp();

#pragma unroll
        for (int b2 = 0; b2 < 2; b2++) {
            int r0 = wm + g, r1 = wm + g + 8;
            uint4 pa0 = *(const uint4*)&Ps[r0 * 32 + (((b2 << 4) ^ ((r0 & 1) << 4)) + t * 4)];
            uint4 pa1 = *(const uint4*)&Ps[r1 * 32 + (((b2 << 4) ^ ((r1 & 1) << 4)) + t * 4)];
#pragma unroll
            for (int nt = 0; nt < 8; nt++) {
                int rn = nt * 8 + g;
                uint4 vb = *(const uint4*)&VtB[rn * 32 + (((b2 << 4) ^ ((rn & 1) << 4)) + t * 4)];
                mma16(o[nt], pa0.x, pa1.x, pa0.y, pa1.y, vb.x, vb.y);
                mma16(o[nt], pa0.z, pa1.z, pa0.w, pa1.w, vb.z, vb.w);
            }
        }
    }

    int b = bh >> 4, h = bh & 15;
#pragma unroll
    for (int slot = 0; slot < 2; slot++) {
        float inv = 1.0f / l_i[slot];
        int row = wm + g + slot * 8;
        size_t m = (size_t)b * SEQ + qbase + row;
        uint4 lo = make_uint4(f2h2(o[0][slot*2]*inv, o[0][slot*2+1]*inv),
                              f2h2(o[1][slot*2]*inv, o[1][slot*2+1]*inv),
                              f2h2(o[2][slot*2]*inv, o[2][slot*2+1]*inv),
                              f2h2(o[3][slot*2]*inv, o[3][slot*2+1]*inv));
        uint4 hi = make_uint4(f2h2(o[4][slot*2]*inv, o[4][slot*2+1]*inv),
                              f2h2(o[5][slot*2]*inv, o[5][slot*2+1]*inv),
                              f2h2(o[6][slot*2]*inv, o[6][slot*2+1]*inv),
                              f2h2(o[7][slot*2]*inv, o[7][slot*2+1]*inv));
        *(uint4*)&g_oh[m * 512 + h * 32 + t * 4] = lo;
        *(uint4*)&g_oh[m * 512 + h * 32 + 16 + t * 4] = hi;
    }
}

// ---------------------------------------------------------------------------
// Kernel 4: projection GEMM (pipelined), fp32 out.
// ---------------------------------------------------------------------------
__global__ __launch_bounds__(256, 2) void proj_gemm_h(
    const float* __restrict__ bp, float* __restrict__ out)
{
    extern __shared__ __align__(16) uint32_t sm[];
    const int tid = threadIdx.x;
    const int warp = tid >> 5, lane = tid & 31;
    const int g = lane >> 2, t = lane & 3;
    const int wm = (warp >> 1) * 32, wn = (warp & 1) * 32;
    const int mBase = blockIdx.y * 128, nBase = blockIdx.x * 64;

    GemmAcc A;
    gemm_mainloop(sm, g_oh, g_wph, mBase, nBase, tid, wm, wn, g, t, A);

#pragma unroll
    for (int mt = 0; mt < 2; mt++)
#pragma unroll
        for (int hf = 0; hf < 2; hf++) {
            int row = mBase + wm + mt * 16 + g + hf * 8;
#pragma unroll
            for (int nt = 0; nt < 4; nt++) {
                int col = nBase + wn + nt * 8 + 2 * t;
                float2 r = make_float2(A.a[mt][nt][hf * 2 + 0] + bp[col],
                                       A.a[mt][nt][hf * 2 + 1] + bp[col + 1]);
                *(float2*)&out[(size_t)row * DMODEL + col] = r;
            }
        }
}

// ---------------------------------------------------------------------------
// Launch. Inputs: 0:x 1:w_qkv 2:b_qkv 3:w_proj 4:b_proj 5:qg 6:qb 7:kg 8:kb
// ---------------------------------------------------------------------------
extern "C" void kernel_launch(void* const* d_in, const int* in_sizes, int n_in,
                              void* d_out, int out_size)
{
    const float* x      = (const float*)d_in[0];
    const float* w_qkv  = (const float*)d_in[1];
    const float* b_qkv  = (const float*)d_in[2];
    const float* w_proj = (const float*)d_in[3];
    const float* b_proj = (const float*)d_in[4];
    const float* q_g    = (const float*)d_in[5];
    const float* q_b    = (const float*)d_in[6];
    const float* k_g    = (const float*)d_in[7];
    const float* k_b    = (const float*)d_in[8];
    float* out = (float*)d_out;

    cudaFuncSetAttribute(attn_h_kernel,
                         cudaFuncAttributeMaxDynamicSharedMemorySize, ATTN_SMEM);
    cudaFuncSetAttribute(qkv_gemm_h,
                         cudaFuncAttributeMaxDynamicSharedMemorySize, GEMM_SMEM);
    cudaFuncSetAttribute(proj_gemm_h,
                         cudaFuncAttributeMaxDynamicSharedMemorySize, GEMM_SMEM);

    prep_kernel<<<NU4_TOT / 256, 256>>>(x, w_qkv, w_proj);

    dim3 g1(NQKV / 64, MROWS / 128);    // (48, 32)
    qkv_gemm_h<<<g1, 256, GEMM_SMEM>>>(b_qkv, q_g, q_b, k_g, k_b);

    dim3 g3(SEQ / 128, BH);             // (16, 32)
    attn_h_kernel<<<g3, 256, ATTN_SMEM>>>();

    dim3 g4(DMODEL / 64, MROWS / 128);  // (16, 32)
    proj_gemm_h<<<g4, 256, GEMM_SMEM>>>(b_proj, out);
}

// round 11
// speedup vs baseline: 2.9165x; 1.1371x over previous
#include <cuda_runtime.h>
#include <cuda_fp16.h>
#include <math.h>
#include <stdint.h>

#define BATCH 2
#define SEQ   2048
#define DMODEL 1024
#define HEADS 16
#define HDIM  64
#define MROWS (BATCH * SEQ)          // 4096
#define NQKV  (3 * DMODEL)           // 3072
#define BH    (BATCH * HEADS)        // 32

// half scratch as half2 units (uint32), k-permuted for mma fragments
__device__ uint32_t g_xh [(size_t)MROWS * 512];
__device__ uint32_t g_wqh[(size_t)NQKV * 512];
__device__ uint32_t g_wph[(size_t)DMODEL * 512];
__device__ uint32_t g_qh [(size_t)BH * SEQ * 32];    // Q (LN'd, *0.125*log2e)
__device__ uint32_t g_kh [(size_t)BH * SEQ * 32];    // K (LN'd)
__device__ __half   g_vTh[(size_t)BH * HDIM * SEQ];  // V transposed, key-permuted
__device__ uint32_t g_oh [(size_t)MROWS * 512];      // attn out, dmodel-permuted

__device__ __forceinline__ uint32_t f2h2(float a, float b) {
    __half2 h = __floats2half2_rn(a, b);
    return *reinterpret_cast<uint32_t*>(&h);
}
__device__ __forceinline__ float ex2f(float x) {
    float r;
    asm("ex2.approx.ftz.f32 %0, %1;" : "=f"(r) : "f"(x));
    return r;
}
__device__ __forceinline__ int p16(int u) {
    return ((u & 3) << 2) | ((u >> 3) << 1) | ((u >> 2) & 1);
}
__device__ __forceinline__ void cpa16(uint32_t saddr, const void* gaddr) {
    asm volatile("cp.async.cg.shared.global [%0], [%1], 16;" :: "r"(saddr), "l"(gaddr) : "memory");
}
#define CP_COMMIT() asm volatile("cp.async.commit_group;" ::: "memory")

__device__ __forceinline__ void mma16(float* c, uint32_t a0, uint32_t a1,
                                      uint32_t a2, uint32_t a3,
                                      uint32_t b0, uint32_t b1) {
    asm volatile(
        "mma.sync.aligned.m16n8k16.row.col.f32.f16.f16.f32 "
        "{%0,%1,%2,%3}, {%4,%5,%6,%7}, {%8,%9}, {%0,%1,%2,%3};"
        : "+f"(c[0]), "+f"(c[1]), "+f"(c[2]), "+f"(c[3])
        : "r"(a0), "r"(a1), "r"(a2), "r"(a3), "r"(b0), "r"(b1));
}

// ---------------------------------------------------------------------------
// Kernel 0: fp32 -> permuted half for X, w_qkv, w_proj.
// ---------------------------------------------------------------------------
#define NU4_X  (MROWS * 128)
#define NU4_WQ (NQKV * 128)
#define NU4_WP (DMODEL * 128)
#define NU4_TOT (NU4_X + NU4_WQ + NU4_WP)

__global__ __launch_bounds__(256) void prep_kernel(
    const float* __restrict__ X, const float* __restrict__ Wq,
    const float* __restrict__ Wp)
{
    int gi = blockIdx.x * 256 + threadIdx.x;
    const float* src; uint4* dst; int li;
    if (gi < NU4_X)                { src = X;  dst = (uint4*)g_xh;  li = gi; }
    else if (gi < NU4_X + NU4_WQ)  { src = Wq; dst = (uint4*)g_wqh; li = gi - NU4_X; }
    else                           { src = Wp; dst = (uint4*)g_wph; li = gi - NU4_X - NU4_WQ; }
    int row = li >> 7, rem = li & 127, b = rem >> 2, c = rem & 3;
    const float* base = src + (size_t)row * DMODEL + b * 32 + 2 * c;
    float2 f0 = *(const float2*)(base + 0);
    float2 f1 = *(const float2*)(base + 8);
    float2 f2 = *(const float2*)(base + 16);
    float2 f3 = *(const float2*)(base + 24);
    uint4 o;
    o.x = f2h2(f0.x, f0.y); o.y = f2h2(f1.x, f1.y);
    o.z = f2h2(f2.x, f2.y); o.w = f2h2(f3.x, f3.y);
    dst[li] = o;
}

// ---------------------------------------------------------------------------
// Shared GEMM mainloop: CTA 128x64, k-tile 64 (32u), cp.async x2.
// ---------------------------------------------------------------------------
#define STAGE 6144
#define GEMM_SMEM (2 * STAGE * 4)        // 49152 B
#define NTK (DMODEL / 64)                // 16

struct GemmAcc { float a[2][4][4]; };

__device__ __forceinline__ void gemm_mainloop(
    uint32_t* sm, const uint32_t* Asrc, const uint32_t* Bsrc,
    int mBase, int nBase, int tid, int wm, int wn, int g, int t,
    GemmAcc& A)
{
#pragma unroll
    for (int mt = 0; mt < 2; mt++)
#pragma unroll
        for (int nt = 0; nt < 4; nt++)
#pragma unroll
            for (int i = 0; i < 4; i++) A.a[mt][nt][i] = 0.0f;

    const int frA = tid >> 3, fc = tid & 7;
    const int frB = tid >> 3;
    uint32_t adst[4], bdst[2];
    const uint32_t* asrc[4];
    const uint32_t* bsrc[2];
#pragma unroll
    for (int i = 0; i < 4; i++) {
        int row = frA + i * 32;
        adst[i] = (uint32_t)__cvta_generic_to_shared(
            &sm[row * 32 + ((fc * 4) ^ ((row & 1) * 16))]);
        asrc[i] = Asrc + (size_t)(mBase + row) * 512 + fc * 4;
    }
#pragma unroll
    for (int i = 0; i < 2; i++) {
        int row = frB + i * 32;
        bdst[i] = (uint32_t)__cvta_generic_to_shared(
            &sm[4096 + row * 32 + ((fc * 4) ^ ((row & 1) * 16))]);
        bsrc[i] = Bsrc + (size_t)(nBase + row) * 512 + fc * 4;
    }

#pragma unroll
    for (int i = 0; i < 4; i++) cpa16(adst[i], asrc[i]);
#pragma unroll
    for (int i = 0; i < 2; i++) cpa16(bdst[i], bsrc[i]);
    CP_COMMIT();

    for (int it = 0; it < NTK; it++) {
        const int buf = it & 1;
        __syncthreads();
        if (it + 1 < NTK) {
            uint32_t soff = (uint32_t)(((it + 1) & 1) * STAGE * 4);
            int gofs = (it + 1) * 32;
#pragma unroll
            for (int i = 0; i < 4; i++) cpa16(adst[i] + soff, asrc[i] + gofs);
#pragma unroll
            for (int i = 0; i < 2; i++) cpa16(bdst[i] + soff, bsrc[i] + gofs);
            CP_COMMIT();
            asm volatile("cp.async.wait_group 1;" ::: "memory");
        } else {
            asm volatile("cp.async.wait_group 0;" ::: "memory");
        }
        __syncthreads();

        const uint32_t* Ab = sm + buf * STAGE;
        const uint32_t* Bb = Ab + 4096;
#pragma unroll
        for (int b2 = 0; b2 < 2; b2++) {
            uint4 af[2][2], bf[4];
#pragma unroll
            for (int mt = 0; mt < 2; mt++) {
                int r0 = wm + mt * 16 + g, r1 = r0 + 8;
                af[mt][0] = *(const uint4*)&Ab[r0 * 32 + (((b2 << 4) ^ ((r0 & 1) << 4)) + t * 4)];
                af[mt][1] = *(const uint4*)&Ab[r1 * 32 + (((b2 << 4) ^ ((r1 & 1) << 4)) + t * 4)];
            }
#pragma unroll
            for (int nt = 0; nt < 4; nt++) {
                int rn = wn + nt * 8 + g;
                bf[nt] = *(const uint4*)&Bb[rn * 32 + (((b2 << 4) ^ ((rn & 1) << 4)) + t * 4)];
            }
#pragma unroll
            for (int mt = 0; mt < 2; mt++)
#pragma unroll
                for (int nt = 0; nt < 4; nt++) {
                    mma16(A.a[mt][nt], af[mt][0].x, af[mt][1].x, af[mt][0].y, af[mt][1].y,
                          bf[nt].x, bf[nt].y);
                    mma16(A.a[mt][nt], af[mt][0].z, af[mt][1].z, af[mt][0].w, af[mt][1].w,
                          bf[nt].z, bf[nt].w);
                }
        }
    }
    __syncthreads();
}

// ---------------------------------------------------------------------------
// Kernel 1: QKV GEMM + fused LN.
// ---------------------------------------------------------------------------
__global__ __launch_bounds__(256, 2) void qkv_gemm_h(
    const float* __restrict__ bias,
    const float* __restrict__ qg, const float* __restrict__ qb,
    const float* __restrict__ kg, const float* __restrict__ kb)
{
    extern __shared__ __align__(16) uint32_t sm[];
    const int tid = threadIdx.x;
    const int warp = tid >> 5, lane = tid & 31;
    const int g = lane >> 2, t = lane & 3;
    const int wm = (warp >> 1) * 32, wn = (warp & 1) * 32;
    const int mBase = blockIdx.y * 128, nBase = blockIdx.x * 64;
    const int part = nBase >> 10;
    const int h = (nBase >> 6) & 15;

    GemmAcc A;
    gemm_mainloop(sm, g_xh, g_wqh, mBase, nBase, tid, wm, wn, g, t, A);

    if (part == 2) {
#pragma unroll
        for (int mt = 0; mt < 2; mt++)
#pragma unroll
            for (int hf = 0; hf < 2; hf++) {
                int row = mBase + wm + mt * 16 + g + hf * 8;
                int bb = row >> 11, s = row & 2047;
                int bhv = bb * HEADS + h;
                int u = (s & 31) >> 1, hh = s & 1;
                int ph = (s & ~31) + p16(u) * 2 + hh;
#pragma unroll
                for (int nt = 0; nt < 4; nt++) {
                    int col = nBase + wn + nt * 8 + 2 * t;
                    float v0 = A.a[mt][nt][hf * 2 + 0] + bias[col];
                    float v1 = A.a[mt][nt][hf * 2 + 1] + bias[col + 1];
                    int hd = col & 63;
                    g_vTh[((size_t)(bhv * HDIM + hd)     * SEQ) + ph] = __float2half_rn(v0);
                    g_vTh[((size_t)(bhv * HDIM + hd + 1) * SEQ) + ph] = __float2half_rn(v1);
                }
            }
        return;
    }

    float* T = (float*)sm;
#pragma unroll
    for (int mt = 0; mt < 2; mt++)
#pragma unroll
        for (int hf = 0; hf < 2; hf++) {
            int rl = wm + mt * 16 + g + hf * 8;
#pragma unroll
            for (int nt = 0; nt < 4; nt++) {
                int col = wn + nt * 8 + 2 * t;
                float2 v = make_float2(A.a[mt][nt][hf * 2 + 0] + bias[nBase + col],
                                       A.a[mt][nt][hf * 2 + 1] + bias[nBase + col + 1]);
                *(float2*)&T[rl * 68 + col] = v;
            }
        }
    __syncthreads();

    const float* gamma = (part == 0) ? qg : kg;
    const float* beta  = (part == 0) ? qb : kb;
    uint32_t* dstbase = (part == 0) ? g_qh : g_kh;
    const float sc = (part == 0) ? (0.125f * 1.4426950408889634f) : 1.0f;
    float2 gm = *(const float2*)&gamma[2 * lane];
    float2 bt = *(const float2*)&beta[2 * lane];
    const int outpos = ((lane >> 4) << 4) + p16(lane & 15);

    for (int r16 = 0; r16 < 16; r16++) {
        int rl = warp * 16 + r16;
        float2 x = *(const float2*)&T[rl * 68 + 2 * lane];
        float s = x.x + x.y;
#pragma unroll
        for (int o = 16; o >= 1; o >>= 1) s += __shfl_xor_sync(0xffffffffu, s, o);
        float mu = s * (1.0f / 64.0f);
        float d0 = x.x - mu, d1 = x.y - mu;
        float v = d0 * d0 + d1 * d1;
#pragma unroll
        for (int o = 16; o >= 1; o >>= 1) v += __shfl_xor_sync(0xffffffffu, v, o);
        float r = rsqrtf(v * (1.0f / 64.0f) + 1e-5f);
        float y0 = (d0 * r * gm.x + bt.x) * sc;
        float y1 = (d1 * r * gm.y + bt.y) * sc;
        int m = mBase + rl;
        int bb = m >> 11, s2 = m & 2047;
        dstbase[((size_t)(bb * HEADS + h) * SEQ + s2) * 32 + outpos] = f2h2(y0, y1);
    }
}

// ---------------------------------------------------------------------------
// Kernel 3: flash attention fp16. Register-direct P (no Ps smem), no running
// max (LN bounds |s| <= ~12 in log2 domain; ex2 cannot overflow; fp32 softmax
// is shift-invariant). cp.async double-buffered K/V. smem 48KB, 2 CTAs/SM.
// ---------------------------------------------------------------------------
#define NT (SEQ / 64)
#define ATTN_SMEM ((128 * 32 + 2 * 64 * 32 + 2 * 64 * 32) * 4)   // 49152

__global__ __launch_bounds__(256, 2) void attn_h_kernel()
{
    extern __shared__ __align__(16) uint32_t smem[];
    uint32_t* Qs = smem;
    uint32_t* Ks = Qs + 128 * 32;
    uint32_t* Vt = Ks + 2 * 64 * 32;

    const int tid = threadIdx.x;
    const int warp = tid >> 5, lane = tid & 31;
    const int g = lane >> 2, t = lane & 3;
    const int wm = warp * 16;
    const int bh = blockIdx.y;
    const int qbase = blockIdx.x * 128;

    const uint32_t* Qg = g_qh + (size_t)(bh * SEQ) * 32;
    const uint32_t* Kg = g_kh + (size_t)(bh * SEQ) * 32;
    const __half*   Vg = g_vTh + (size_t)bh * HDIM * SEQ;

#pragma unroll
    for (int i = 0; i < 4; i++) {
        int idx = tid + i * 256, row = idx >> 3, c = idx & 7;
        uint4 v = *(const uint4*)&Qg[(size_t)(qbase + row) * 32 + c * 4];
        *(uint4*)&Qs[row * 32 + ((c * 4) ^ ((row & 1) * 16))] = v;
    }

    const int fr = tid >> 3, fc = tid & 7;
    uint32_t kdst0 = (uint32_t)__cvta_generic_to_shared(
        &Ks[fr * 32 + ((fc * 4) ^ ((fr & 1) * 16))]);
    uint32_t kdst1 = (uint32_t)__cvta_generic_to_shared(
        &Ks[(fr + 32) * 32 + ((fc * 4) ^ ((fr & 1) * 16))]);
    uint32_t vdst0 = (uint32_t)__cvta_generic_to_shared(
        &Vt[fr * 32 + ((fc * 4) ^ ((fr & 1) * 16))]);
    uint32_t vdst1 = (uint32_t)__cvta_generic_to_shared(
        &Vt[(fr + 32) * 32 + ((fc * 4) ^ ((fr & 1) * 16))]);
    const uint32_t* ksrc0 = Kg + fr * 32 + fc * 4;
    const uint32_t* ksrc1 = Kg + (fr + 32) * 32 + fc * 4;
    const __half* vsrc0 = Vg + (size_t)fr * SEQ + fc * 8;
    const __half* vsrc1 = Vg + (size_t)(fr + 32) * SEQ + fc * 8;

    cpa16(kdst0, ksrc0);
    cpa16(kdst1, ksrc1);
    cpa16(vdst0, vsrc0);
    cpa16(vdst1, vsrc1);
    CP_COMMIT();

    float l_i[2] = {0.0f, 0.0f};
    float o[8][4];
#pragma unroll
    for (int nt = 0; nt < 8; nt++)
#pragma unroll
        for (int i = 0; i < 4; i++) o[nt][i] = 0.0f;

    for (int it = 0; it < NT; it++) {
        const int buf = it & 1;
        __syncthreads();
        if (it + 1 < NT) {
            uint32_t soff = (uint32_t)(((it + 1) & 1) * 2048 * 4);
            int gk = (it + 1) * 2048;
            int gv = (it + 1) * 64;
            cpa16(kdst0 + soff, ksrc0 + gk);
            cpa16(kdst1 + soff, ksrc1 + gk);
            cpa16(vdst0 + soff, vsrc0 + gv);
            cpa16(vdst1 + soff, vsrc1 + gv);
            CP_COMMIT();
            asm volatile("cp.async.wait_group 1;" ::: "memory");
        } else {
            asm volatile("cp.async.wait_group 0;" ::: "memory");
        }
        __syncthreads();

        const uint32_t* KsB = Ks + buf * 2048;
        const uint32_t* VtB = Vt + buf * 2048;

        // S = Q K^T
        float s[8][4];
#pragma unroll
        for (int nt = 0; nt < 8; nt++)
#pragma unroll
            for (int i = 0; i < 4; i++) s[nt][i] = 0.0f;

#pragma unroll
        for (int b2 = 0; b2 < 2; b2++) {
            int r0 = wm + g, r1 = wm + g + 8;
            uint4 qa0 = *(const uint4*)&Qs[r0 * 32 + (((b2 << 4) ^ ((r0 & 1) << 4)) + t * 4)];
            uint4 qa1 = *(const uint4*)&Qs[r1 * 32 + (((b2 << 4) ^ ((r1 & 1) << 4)) + t * 4)];
#pragma unroll
            for (int nt = 0; nt < 8; nt++) {
                int rn = nt * 8 + g;
                uint4 kb = *(const uint4*)&KsB[rn * 32 + (((b2 << 4) ^ ((rn & 1) << 4)) + t * 4)];
                mma16(s[nt], qa0.x, qa1.x, qa0.y, qa1.y, kb.x, kb.y);
                mma16(s[nt], qa0.z, qa1.z, qa0.w, qa1.w, kb.z, kb.w);
            }
        }

        // softmax without running max; build PV A-fragments directly
        uint32_t ah[4][4];
        float rs0 = 0.0f, rs1 = 0.0f;
#pragma unroll
        for (int kb2 = 0; kb2 < 4; kb2++) {
            float p00 = ex2f(s[2*kb2][0]),   p01 = ex2f(s[2*kb2][1]);
            float p02 = ex2f(s[2*kb2][2]),   p03 = ex2f(s[2*kb2][3]);
            float p10 = ex2f(s[2*kb2+1][0]), p11 = ex2f(s[2*kb2+1][1]);
            float p12 = ex2f(s[2*kb2+1][2]), p13 = ex2f(s[2*kb2+1][3]);
            rs0 += p00 + p01 + p10 + p11;
            rs1 += p02 + p03 + p12 + p13;
            ah[kb2][0] = f2h2(p00, p01);
            ah[kb2][1] = f2h2(p02, p03);
            ah[kb2][2] = f2h2(p10, p11);
            ah[kb2][3] = f2h2(p12, p13);
        }
        rs0 += __shfl_xor_sync(0xffffffffu, rs0, 1);
        rs0 += __shfl_xor_sync(0xffffffffu, rs0, 2);
        rs1 += __shfl_xor_sync(0xffffffffu, rs1, 1);
        rs1 += __shfl_xor_sync(0xffffffffu, rs1, 2);
        l_i[0] += rs0;
        l_i[1] += rs1;

        // O += P V  (P straight from registers)
#pragma unroll
        for (int b2 = 0; b2 < 2; b2++) {
#pragma unroll
            for (int nt = 0; nt < 8; nt++) {
                int rn = nt * 8 + g;
                uint4 vb = *(const uint4*)&VtB[rn * 32 + (((b2 << 4) ^ ((rn & 1) << 4)) + t * 4)];
                mma16(o[nt], ah[2*b2][0],   ah[2*b2][1],   ah[2*b2][2],   ah[2*b2][3],
                      vb.x, vb.y);
                mma16(o[nt], ah[2*b2+1][0], ah[2*b2+1][1], ah[2*b2+1][2], ah[2*b2+1][3],
                      vb.z, vb.w);
            }
        }
    }

    int b = bh >> 4, h = bh & 15;
#pragma unroll
    for (int slot = 0; slot < 2; slot++) {
        float inv = 1.0f / l_i[slot];
        int row = wm + g + slot * 8;
        size_t m = (size_t)b * SEQ + qbase + row;
        uint4 lo = make_uint4(f2h2(o[0][slot*2]*inv, o[0][slot*2+1]*inv),
                              f2h2(o[1][slot*2]*inv, o[1][slot*2+1]*inv),
                              f2h2(o[2][slot*2]*inv, o[2][slot*2+1]*inv),
                              f2h2(o[3][slot*2]*inv, o[3][slot*2+1]*inv));
        uint4 hi = make_uint4(f2h2(o[4][slot*2]*inv, o[4][slot*2+1]*inv),
                              f2h2(o[5][slot*2]*inv, o[5][slot*2+1]*inv),
                              f2h2(o[6][slot*2]*inv, o[6][slot*2+1]*inv),
                              f2h2(o[7][slot*2]*inv, o[7][slot*2+1]*inv));
        *(uint4*)&g_oh[m * 512 + h * 32 + t * 4] = lo;
        *(uint4*)&g_oh[m * 512 + h * 32 + 16 + t * 4] = hi;
    }
}

// ---------------------------------------------------------------------------
// Kernel 4: projection GEMM (pipelined), fp32 out.
// ---------------------------------------------------------------------------
__global__ __launch_bounds__(256, 2) void proj_gemm_h(
    const float* __restrict__ bp, float* __restrict__ out)
{
    extern __shared__ __align__(16) uint32_t sm[];
    const int tid = threadIdx.x;
    const int warp = tid >> 5, lane = tid & 31;
    const int g = lane >> 2, t = lane & 3;
    const int wm = (warp >> 1) * 32, wn = (warp & 1) * 32;
    const int mBase = blockIdx.y * 128, nBase = blockIdx.x * 64;

    GemmAcc A;
    gemm_mainloop(sm, g_oh, g_wph, mBase, nBase, tid, wm, wn, g, t, A);

#pragma unroll
    for (int mt = 0; mt < 2; mt++)
#pragma unroll
        for (int hf = 0; hf < 2; hf++) {
            int row = mBase + wm + mt * 16 + g + hf * 8;
#pragma unroll
            for (int nt = 0; nt < 4; nt++) {
                int col = nBase + wn + nt * 8 + 2 * t;
                float2 r = make_float2(A.a[mt][nt][hf * 2 + 0] + bp[col],
                                       A.a[mt][nt][hf * 2 + 1] + bp[col + 1]);
                *(float2*)&out[(size_t)row * DMODEL + col] = r;
            }
        }
}

// ---------------------------------------------------------------------------
// Launch. Inputs: 0:x 1:w_qkv 2:b_qkv 3:w_proj 4:b_proj 5:qg 6:qb 7:kg 8:kb
// ---------------------------------------------------------------------------
extern "C" void kernel_launch(void* const* d_in, const int* in_sizes, int n_in,
                              void* d_out, int out_size)
{
    const float* x      = (const float*)d_in[0];
    const float* w_qkv  = (const float*)d_in[1];
    const float* b_qkv  = (const float*)d_in[2];
    const float* w_proj = (const float*)d_in[3];
    const float* b_proj = (const float*)d_in[4];
    const float* q_g    = (const float*)d_in[5];
    const float* q_b    = (const float*)d_in[6];
    const float* k_g    = (const float*)d_in[7];
    const float* k_b    = (const float*)d_in[8];
    float* out = (float*)d_out;

    cudaFuncSetAttribute(attn_h_kernel,
                         cudaFuncAttributeMaxDynamicSharedMemorySize, ATTN_SMEM);
    cudaFuncSetAttribute(qkv_gemm_h,
                         cudaFuncAttributeMaxDynamicSharedMemorySize, GEMM_SMEM);
    cudaFuncSetAttribute(proj_gemm_h,
                         cudaFuncAttributeMaxDynamicSharedMemorySize, GEMM_SMEM);

    prep_kernel<<<NU4_TOT / 256, 256>>>(x, w_qkv, w_proj);

    dim3 g1(NQKV / 64, MROWS / 128);    // (48, 32)
    qkv_gemm_h<<<g1, 256, GEMM_SMEM>>>(b_qkv, q_g, q_b, k_g, k_b);

    dim3 g3(SEQ / 128, BH);             // (16, 32)
    attn_h_kernel<<<g3, 256, ATTN_SMEM>>>();

    dim3 g4(DMODEL / 64, MROWS / 128);  // (16, 32)
    proj_gemm_h<<<g4, 256, GEMM_SMEM>>>(b_proj, out);
}

// round 13
// speedup vs baseline: 2.9896x; 1.0250x over previous
#include <cuda_runtime.h>
#include <cuda_fp16.h>
#include <math.h>
#include <stdint.h>

#define BATCH 2
#define SEQ   2048
#define DMODEL 1024
#define HEADS 16
#define HDIM  64
#define MROWS (BATCH * SEQ)          // 4096
#define NQKV  (3 * DMODEL)           // 3072
#define BH    (BATCH * HEADS)        // 32

// half scratch as half2 units (uint32), k-permuted for mma fragments
__device__ uint32_t g_xh [(size_t)MROWS * 512];
__device__ uint32_t g_wqh[(size_t)NQKV * 512];
__device__ uint32_t g_wph[(size_t)DMODEL * 512];
__device__ uint32_t g_qh [(size_t)BH * SEQ * 32];    // Q (LN'd, *0.125*log2e)
__device__ uint32_t g_kh [(size_t)BH * SEQ * 32];    // K (LN'd)
__device__ __half   g_vTh[(size_t)BH * HDIM * SEQ];  // V transposed, key-permuted
__device__ uint32_t g_oh [(size_t)MROWS * 512];      // attn out, dmodel-permuted

__device__ __forceinline__ uint32_t f2h2(float a, float b) {
    __half2 h = __floats2half2_rn(a, b);
    return *reinterpret_cast<uint32_t*>(&h);
}
__device__ __forceinline__ float ex2f(float x) {
    float r;
    asm("ex2.approx.ftz.f32 %0, %1;" : "=f"(r) : "f"(x));
    return r;
}
__device__ __forceinline__ int p16(int u) {
    return ((u & 3) << 2) | ((u >> 3) << 1) | ((u >> 2) & 1);
}
__device__ __forceinline__ void cpa16(uint32_t saddr, const void* gaddr) {
    asm volatile("cp.async.cg.shared.global [%0], [%1], 16;" :: "r"(saddr), "l"(gaddr) : "memory");
}
#define CP_COMMIT() asm volatile("cp.async.commit_group;" ::: "memory")

__device__ __forceinline__ uint4 lds128(uint32_t addr) {
    uint4 v;
    asm volatile("ld.shared.v4.b32 {%0,%1,%2,%3}, [%4];"
        : "=r"(v.x), "=r"(v.y), "=r"(v.z), "=r"(v.w) : "r"(addr));
    return v;
}

__device__ __forceinline__ void mma16(float* c, uint32_t a0, uint32_t a1,
                                      uint32_t a2, uint32_t a3,
                                      uint32_t b0, uint32_t b1) {
    asm volatile(
        "mma.sync.aligned.m16n8k16.row.col.f32.f16.f16.f32 "
        "{%0,%1,%2,%3}, {%4,%5,%6,%7}, {%8,%9}, {%0,%1,%2,%3};"
        : "+f"(c[0]), "+f"(c[1]), "+f"(c[2]), "+f"(c[3])
        : "r"(a0), "r"(a1), "r"(a2), "r"(a3), "r"(b0), "r"(b1));
}

// ---------------------------------------------------------------------------
// Kernel 0: fp32 -> permuted half for X, w_qkv, w_proj.
// ---------------------------------------------------------------------------
#define NU4_X  (MROWS * 128)
#define NU4_WQ (NQKV * 128)
#define NU4_WP (DMODEL * 128)
#define NU4_TOT (NU4_X + NU4_WQ + NU4_WP)

__global__ __launch_bounds__(256) void prep_kernel(
    const float* __restrict__ X, const float* __restrict__ Wq,
    const float* __restrict__ Wp)
{
    int gi = blockIdx.x * 256 + threadIdx.x;
    const float* src; uint4* dst; int li;
    if (gi < NU4_X)                { src = X;  dst = (uint4*)g_xh;  li = gi; }
    else if (gi < NU4_X + NU4_WQ)  { src = Wq; dst = (uint4*)g_wqh; li = gi - NU4_X; }
    else                           { src = Wp; dst = (uint4*)g_wph; li = gi - NU4_X - NU4_WQ; }
    int row = li >> 7, rem = li & 127, b = rem >> 2, c = rem & 3;
    const float* base = src + (size_t)row * DMODEL + b * 32 + 2 * c;
    float2 f0 = *(const float2*)(base + 0);
    float2 f1 = *(const float2*)(base + 8);
    float2 f2 = *(const float2*)(base + 16);
    float2 f3 = *(const float2*)(base + 24);
    uint4 o;
    o.x = f2h2(f0.x, f0.y); o.y = f2h2(f1.x, f1.y);
    o.z = f2h2(f2.x, f2.y); o.w = f2h2(f3.x, f3.y);
    dst[li] = o;
}

// ---------------------------------------------------------------------------
// Shared GEMM mainloop: CTA 128x64, k-tile 64 (32u), cp.async x2.
// Fragment LDS addresses precomputed once; per-tile only +buf offset.
// ---------------------------------------------------------------------------
#define STAGE 6144
#define GEMM_SMEM (2 * STAGE * 4)        // 49152 B
#define NTK (DMODEL / 64)                // 16

struct GemmAcc { float a[2][4][4]; };

__device__ __forceinline__ void gemm_mainloop(
    uint32_t* sm, const uint32_t* Asrc, const uint32_t* Bsrc,
    int mBase, int nBase, int tid, int wm, int wn, int g, int t,
    GemmAcc& A)
{
#pragma unroll
    for (int mt = 0; mt < 2; mt++)
#pragma unroll
        for (int nt = 0; nt < 4; nt++)
#pragma unroll
            for (int i = 0; i < 4; i++) A.a[mt][nt][i] = 0.0f;

    const int frA = tid >> 3, fc = tid & 7;
    const int frB = tid >> 3;
    uint32_t adst[4], bdst[2];
    const uint32_t* asrc[4];
    const uint32_t* bsrc[2];
#pragma unroll
    for (int i = 0; i < 4; i++) {
        int row = frA + i * 32;
        adst[i] = (uint32_t)__cvta_generic_to_shared(
            &sm[row * 32 + ((fc * 4) ^ ((row & 1) * 16))]);
        asrc[i] = Asrc + (size_t)(mBase + row) * 512 + fc * 4;
    }
#pragma unroll
    for (int i = 0; i < 2; i++) {
        int row = frB + i * 32;
        bdst[i] = (uint32_t)__cvta_generic_to_shared(
            &sm[4096 + row * 32 + ((fc * 4) ^ ((row & 1) * 16))]);
        bsrc[i] = Bsrc + (size_t)(nBase + row) * 512 + fc * 4;
    }

    // Precomputed fragment read addresses (stage 0)
    uint32_t afa[2][2][2], bfa[2][4];
#pragma unroll
    for (int b2 = 0; b2 < 2; b2++) {
#pragma unroll
        for (int mt = 0; mt < 2; mt++) {
            int r0 = wm + mt * 16 + g, r1 = r0 + 8;
            afa[b2][mt][0] = (uint32_t)__cvta_generic_to_shared(
                &sm[r0 * 32 + (((b2 << 4) ^ ((r0 & 1) << 4)) + t * 4)]);
            afa[b2][mt][1] = (uint32_t)__cvta_generic_to_shared(
                &sm[r1 * 32 + (((b2 << 4) ^ ((r1 & 1) << 4)) + t * 4)]);
        }
#pragma unroll
        for (int nt = 0; nt < 4; nt++) {
            int rn = wn + nt * 8 + g;
            bfa[b2][nt] = (uint32_t)__cvta_generic_to_shared(
                &sm[4096 + rn * 32 + (((b2 << 4) ^ ((rn & 1) << 4)) + t * 4)]);
        }
    }

#pragma unroll
    for (int i = 0; i < 4; i++) cpa16(adst[i], asrc[i]);
#pragma unroll
    for (int i = 0; i < 2; i++) cpa16(bdst[i], bsrc[i]);
    CP_COMMIT();

    for (int it = 0; it < NTK; it++) {
        const uint32_t bo = (uint32_t)((it & 1) * (STAGE * 4));
        __syncthreads();
        if (it + 1 < NTK) {
            uint32_t soff = (uint32_t)(((it + 1) & 1) * (STAGE * 4));
            int gofs = (it + 1) * 32;
#pragma unroll
            for (int i = 0; i < 4; i++) cpa16(adst[i] + soff, asrc[i] + gofs);
#pragma unroll
            for (int i = 0; i < 2; i++) cpa16(bdst[i] + soff, bsrc[i] + gofs);
            CP_COMMIT();
            asm volatile("cp.async.wait_group 1;" ::: "memory");
        } else {
            asm volatile("cp.async.wait_group 0;" ::: "memory");
        }
        __syncthreads();

#pragma unroll
        for (int b2 = 0; b2 < 2; b2++) {
            uint4 af[2][2], bf[4];
#pragma unroll
            for (int mt = 0; mt < 2; mt++) {
                af[mt][0] = lds128(afa[b2][mt][0] + bo);
                af[mt][1] = lds128(afa[b2][mt][1] + bo);
            }
#pragma unroll
            for (int nt = 0; nt < 4; nt++)
                bf[nt] = lds128(bfa[b2][nt] + bo);
#pragma unroll
            for (int mt = 0; mt < 2; mt++)
#pragma unroll
                for (int nt = 0; nt < 4; nt++) {
                    mma16(A.a[mt][nt], af[mt][0].x, af[mt][1].x, af[mt][0].y, af[mt][1].y,
                          bf[nt].x, bf[nt].y);
                    mma16(A.a[mt][nt], af[mt][0].z, af[mt][1].z, af[mt][0].w, af[mt][1].w,
                          bf[nt].z, bf[nt].w);
                }
        }
    }
    __syncthreads();
}

// ---------------------------------------------------------------------------
// Kernel 1: QKV GEMM + fused LN.
// ---------------------------------------------------------------------------
__global__ __launch_bounds__(256, 2) void qkv_gemm_h(
    const float* __restrict__ bias,
    const float* __restrict__ qg, const float* __restrict__ qb,
    const float* __restrict__ kg, const float* __restrict__ kb)
{
    extern __shared__ __align__(16) uint32_t sm[];
    const int tid = threadIdx.x;
    const int warp = tid >> 5, lane = tid & 31;
    const int g = lane >> 2, t = lane & 3;
    const int wm = (warp >> 1) * 32, wn = (warp & 1) * 32;
    const int mBase = blockIdx.y * 128, nBase = blockIdx.x * 64;
    const int part = nBase >> 10;
    const int h = (nBase >> 6) & 15;

    GemmAcc A;
    gemm_mainloop(sm, g_xh, g_wqh, mBase, nBase, tid, wm, wn, g, t, A);

    if (part == 2) {
#pragma unroll
        for (int mt = 0; mt < 2; mt++)
#pragma unroll
            for (int hf = 0; hf < 2; hf++) {
                int row = mBase + wm + mt * 16 + g + hf * 8;
                int bb = row >> 11, s = row & 2047;
                int bhv = bb * HEADS + h;
                int u = (s & 31) >> 1, hh = s & 1;
                int ph = (s & ~31) + p16(u) * 2 + hh;
#pragma unroll
                for (int nt = 0; nt < 4; nt++) {
                    int col = nBase + wn + nt * 8 + 2 * t;
                    float v0 = A.a[mt][nt][hf * 2 + 0] + bias[col];
                    float v1 = A.a[mt][nt][hf * 2 + 1] + bias[col + 1];
                    int hd = col & 63;
                    g_vTh[((size_t)(bhv * HDIM + hd)     * SEQ) + ph] = __float2half_rn(v0);
                    g_vTh[((size_t)(bhv * HDIM + hd + 1) * SEQ) + ph] = __float2half_rn(v1);
                }
            }
        return;
    }

    float* T = (float*)sm;
#pragma unroll
    for (int mt = 0; mt < 2; mt++)
#pragma unroll
        for (int hf = 0; hf < 2; hf++) {
            int rl = wm + mt * 16 + g + hf * 8;
#pragma unroll
            for (int nt = 0; nt < 4; nt++) {
                int col = wn + nt * 8 + 2 * t;
                float2 v = make_float2(A.a[mt][nt][hf * 2 + 0] + bias[nBase + col],
                                       A.a[mt][nt][hf * 2 + 1] + bias[nBase + col + 1]);
                *(float2*)&T[rl * 68 + col] = v;
            }
        }
    __syncthreads();

    const float* gamma = (part == 0) ? qg : kg;
    const float* beta  = (part == 0) ? qb : kb;
    uint32_t* dstbase = (part == 0) ? g_qh : g_kh;
    const float sc = (part == 0) ? (0.125f * 1.4426950408889634f) : 1.0f;
    float2 gm = *(const float2*)&gamma[2 * lane];
    float2 bt = *(const float2*)&beta[2 * lane];
    const int outpos = ((lane >> 4) << 4) + p16(lane & 15);

    for (int r16 = 0; r16 < 16; r16++) {
        int rl = warp * 16 + r16;
        float2 x = *(const float2*)&T[rl * 68 + 2 * lane];
        float s = x.x + x.y;
#pragma unroll
        for (int o = 16; o >= 1; o >>= 1) s += __shfl_xor_sync(0xffffffffu, s, o);
        float mu = s * (1.0f / 64.0f);
        float d0 = x.x - mu, d1 = x.y - mu;
        float v = d0 * d0 + d1 * d1;
#pragma unroll
        for (int o = 16; o >= 1; o >>= 1) v += __shfl_xor_sync(0xffffffffu, v, o);
        float r = rsqrtf(v * (1.0f / 64.0f) + 1e-5f);
        float y0 = (d0 * r * gm.x + bt.x) * sc;
        float y1 = (d1 * r * gm.y + bt.y) * sc;
        int m = mBase + rl;
        int bb = m >> 11, s2 = m & 2047;
        dstbase[((size_t)(bb * HEADS + h) * SEQ + s2) * 32 + outpos] = f2h2(y0, y1);
    }
}

// ---------------------------------------------------------------------------
// Kernel 3: flash attention fp16. Register-direct P, no running max,
// row-sums via ones-column mma (no shfl / FADD tree). cp.async x2 K/V.
// ---------------------------------------------------------------------------
#define NT (SEQ / 64)
#define ATTN_SMEM ((128 * 32 + 2 * 64 * 32 + 2 * 64 * 32) * 4)   // 49152
#define ONES2 0x3C003C00u   // half2(1.0, 1.0)

__global__ __launch_bounds__(256, 2) void attn_h_kernel()
{
    extern __shared__ __align__(16) uint32_t smem[];
    uint32_t* Qs = smem;
    uint32_t* Ks = Qs + 128 * 32;
    uint32_t* Vt = Ks + 2 * 64 * 32;

    const int tid = threadIdx.x;
    const int warp = tid >> 5, lane = tid & 31;
    const int g = lane >> 2, t = lane & 3;
    const int wm = warp * 16;
    const int bh = blockIdx.y;
    const int qbase = blockIdx.x * 128;

    const uint32_t* Qg = g_qh + (size_t)(bh * SEQ) * 32;
    const uint32_t* Kg = g_kh + (size_t)(bh * SEQ) * 32;
    const __half*   Vg = g_vTh + (size_t)bh * HDIM * SEQ;

#pragma unroll
    for (int i = 0; i < 4; i++) {
        int idx = tid + i * 256, row = idx >> 3, c = idx & 7;
        uint4 v = *(const uint4*)&Qg[(size_t)(qbase + row) * 32 + c * 4];
        *(uint4*)&Qs[row * 32 + ((c * 4) ^ ((row & 1) * 16))] = v;
    }

    const int fr = tid >> 3, fc = tid & 7;
    uint32_t kdst0 = (uint32_t)__cvta_generic_to_shared(
        &Ks[fr * 32 + ((fc * 4) ^ ((fr & 1) * 16))]);
    uint32_t kdst1 = (uint32_t)__cvta_generic_to_shared(
        &Ks[(fr + 32) * 32 + ((fc * 4) ^ ((fr & 1) * 16))]);
    uint32_t vdst0 = (uint32_t)__cvta_generic_to_shared(
        &Vt[fr * 32 + ((fc * 4) ^ ((fr & 1) * 16))]);
    uint32_t vdst1 = (uint32_t)__cvta_generic_to_shared(
        &Vt[(fr + 32) * 32 + ((fc * 4) ^ ((fr & 1) * 16))]);
    const uint32_t* ksrc0 = Kg + fr * 32 + fc * 4;
    const uint32_t* ksrc1 = Kg + (fr + 32) * 32 + fc * 4;
    const __half* vsrc0 = Vg + (size_t)fr * SEQ + fc * 8;
    const __half* vsrc1 = Vg + (size_t)(fr + 32) * SEQ + fc * 8;

    cpa16(kdst0, ksrc0);
    cpa16(kdst1, ksrc1);
    cpa16(vdst0, vsrc0);
    cpa16(vdst1, vsrc1);
    CP_COMMIT();

    float lsum[4];
#pragma unroll
    for (int i = 0; i < 4; i++) lsum[i] = 0.0f;
    float o[8][4];
#pragma unroll
    for (int nt = 0; nt < 8; nt++)
#pragma unroll
        for (int i = 0; i < 4; i++) o[nt][i] = 0.0f;

    for (int it = 0; it < NT; it++) {
        const int buf = it & 1;
        __syncthreads();
        if (it + 1 < NT) {
            uint32_t soff = (uint32_t)(((it + 1) & 1) * 2048 * 4);
            int gk = (it + 1) * 2048;
            int gv = (it + 1) * 64;
            cpa16(kdst0 + soff, ksrc0 + gk);
            cpa16(kdst1 + soff, ksrc1 + gk);
            cpa16(vdst0 + soff, vsrc0 + gv);
            cpa16(vdst1 + soff, vsrc1 + gv);
            CP_COMMIT();
            asm volatile("cp.async.wait_group 1;" ::: "memory");
        } else {
            asm volatile("cp.async.wait_group 0;" ::: "memory");
        }
        __syncthreads();

        const uint32_t* KsB = Ks + buf * 2048;
        const uint32_t* VtB = Vt + buf * 2048;

        // S = Q K^T
        float s[8][4];
#pragma unroll
        for (int nt = 0; nt < 8; nt++)
#pragma unroll
            for (int i = 0; i < 4; i++) s[nt][i] = 0.0f;

#pragma unroll
        for (int b2 = 0; b2 < 2; b2++) {
            int r0 = wm + g, r1 = wm + g + 8;
            uint4 qa0 = *(const uint4*)&Qs[r0 * 32 + (((b2 << 4) ^ ((r0 & 1) << 4)) + t * 4)];
            uint4 qa1 = *(const uint4*)&Qs[r1 * 32 + (((b2 << 4) ^ ((r1 & 1) << 4)) + t * 4)];
#pragma unroll
            for (int nt = 0; nt < 8; nt++) {
                int rn = nt * 8 + g;
                uint4 kb = *(const uint4*)&KsB[rn * 32 + (((b2 << 4) ^ ((rn & 1) << 4)) + t * 4)];
                mma16(s[nt], qa0.x, qa1.x, qa0.y, qa1.y, kb.x, kb.y);
                mma16(s[nt], qa0.z, qa1.z, qa0.w, qa1.w, kb.z, kb.w);
            }
        }

        // p = ex2(s) -> half2 A-fragments; row sums via ones-mma
        uint32_t ah[4][4];
#pragma unroll
        for (int kb2 = 0; kb2 < 4; kb2++) {
            float p00 = ex2f(s[2*kb2][0]),   p01 = ex2f(s[2*kb2][1]);
            float p02 = ex2f(s[2*kb2][2]),   p03 = ex2f(s[2*kb2][3]);
            float p10 = ex2f(s[2*kb2+1][0]), p11 = ex2f(s[2*kb2+1][1]);
            float p12 = ex2f(s[2*kb2+1][2]), p13 = ex2f(s[2*kb2+1][3]);
            ah[kb2][0] = f2h2(p00, p01);
            ah[kb2][1] = f2h2(p02, p03);
            ah[kb2][2] = f2h2(p10, p11);
            ah[kb2][3] = f2h2(p12, p13);
            mma16(lsum, ah[kb2][0], ah[kb2][1], ah[kb2][2], ah[kb2][3], ONES2, ONES2);
        }

        // O += P V
#pragma unroll
        for (int b2 = 0; b2 < 2; b2++) {
#pragma unroll
            for (int nt = 0; nt < 8; nt++) {
                int rn = nt * 8 + g;
                uint4 vb = *(const uint4*)&VtB[rn * 32 + (((b2 << 4) ^ ((rn & 1) << 4)) + t * 4)];
                mma16(o[nt], ah[2*b2][0],   ah[2*b2][1],   ah[2*b2][2],   ah[2*b2][3],
                      vb.x, vb.y);
                mma16(o[nt], ah[2*b2+1][0], ah[2*b2+1][1], ah[2*b2+1][2], ah[2*b2+1][3],
                      vb.z, vb.w);
            }
        }
    }

    int b = bh >> 4, h = bh & 15;
    float l_i[2] = { lsum[0], lsum[2] };
#pragma unroll
    for (int slot = 0; slot < 2; slot++) {
        float inv = 1.0f / l_i[slot];
        int row = wm + g + slot * 8;
        size_t m = (size_t)b * SEQ + qbase + row;
        uint4 lo = make_uint4(f2h2(o[0][slot*2]*inv, o[0][slot*2+1]*inv),
                              f2h2(o[1][slot*2]*inv, o[1][slot*2+1]*inv),
                              f2h2(o[2][slot*2]*inv, o[2][slot*2+1]*inv),
                              f2h2(o[3][slot*2]*inv, o[3][slot*2+1]*inv));
        uint4 hi = make_uint4(f2h2(o[4][slot*2]*inv, o[4][slot*2+1]*inv),
                              f2h2(o[5][slot*2]*inv, o[5][slot*2+1]*inv),
                              f2h2(o[6][slot*2]*inv, o[6][slot*2+1]*inv),
                              f2h2(o[7][slot*2]*inv, o[7][slot*2+1]*inv));
        *(uint4*)&g_oh[m * 512 + h * 32 + t * 4] = lo;
        *(uint4*)&g_oh[m * 512 + h * 32 + 16 + t * 4] = hi;
    }
}

// ---------------------------------------------------------------------------
// Kernel 4: projection GEMM (pipelined), fp32 out.
// ---------------------------------------------------------------------------
__global__ __launch_bounds__(256, 2) void proj_gemm_h(
    const float* __restrict__ bp, float* __restrict__ out)
{
    extern __shared__ __align__(16) uint32_t sm[];
    const int tid = threadIdx.x;
    const int warp = tid >> 5, lane = tid & 31;
    const int g = lane >> 2, t = lane & 3;
    const int wm = (warp >> 1) * 32, wn = (warp & 1) * 32;
    const int mBase = blockIdx.y * 128, nBase = blockIdx.x * 64;

    GemmAcc A;
    gemm_mainloop(sm, g_oh, g_wph, mBase, nBase, tid, wm, wn, g, t, A);

#pragma unroll
    for (int mt = 0; mt < 2; mt++)
#pragma unroll
        for (int hf = 0; hf < 2; hf++) {
            int row = mBase + wm + mt * 16 + g + hf * 8;
#pragma unroll
            for (int nt = 0; nt < 4; nt++) {
                int col = nBase + wn + nt * 8 + 2 * t;
                float2 r = make_float2(A.a[mt][nt][hf * 2 + 0] + bp[col],
                                       A.a[mt][nt][hf * 2 + 1] + bp[col + 1]);
                *(float2*)&out[(size_t)row * DMODEL + col] = r;
            }
        }
}

// ---------------------------------------------------------------------------
// Launch. Inputs: 0:x 1:w_qkv 2:b_qkv 3:w_proj 4:b_proj 5:qg 6:qb 7:kg 8:kb
// ---------------------------------------------------------------------------
extern "C" void kernel_launch(void* const* d_in, const int* in_sizes, int n_in,
                              void* d_out, int out_size)
{
    const float* x      = (const float*)d_in[0];
    const float* w_qkv  = (const float*)d_in[1];
    const float* b_qkv  = (const float*)d_in[2];
    const float* w_proj = (const float*)d_in[3];
    const float* b_proj = (const float*)d_in[4];
    const float* q_g    = (const float*)d_in[5];
    const float* q_b    = (const float*)d_in[6];
    const float* k_g    = (const float*)d_in[7];
    const float* k_b    = (const float*)d_in[8];
    float* out = (float*)d_out;

    cudaFuncSetAttribute(attn_h_kernel,
                         cudaFuncAttributeMaxDynamicSharedMemorySize, ATTN_SMEM);
    cudaFuncSetAttribute(qkv_gemm_h,
                         cudaFuncAttributeMaxDynamicSharedMemorySize, GEMM_SMEM);
    cudaFuncSetAttribute(proj_gemm_h,
                         cudaFuncAttributeMaxDynamicSharedMemorySize, GEMM_SMEM);

    prep_kernel<<<NU4_TOT / 256, 256>>>(x, w_qkv, w_proj);

    dim3 g1(NQKV / 64, MROWS / 128);    // (48, 32)
    qkv_gemm_h<<<g1, 256, GEMM_SMEM>>>(b_qkv, q_g, q_b, k_g, k_b);

    dim3 g3(SEQ / 128, BH);             // (16, 32)
    attn_h_kernel<<<g3, 256, ATTN_SMEM>>>();

    dim3 g4(DMODEL / 64, MROWS / 128);  // (16, 32)
    proj_gemm_h<<<g4, 256, GEMM_SMEM>>>(b_proj, out);
}

// round 14
// speedup vs baseline: 3.0548x; 1.0218x over previous
#include <cuda_runtime.h>
#include <cuda_fp16.h>
#include <math.h>
#include <stdint.h>

#define BATCH 2
#define SEQ   2048
#define DMODEL 1024
#define HEADS 16
#define HDIM  64
#define MROWS (BATCH * SEQ)          // 4096
#define NQKV  (3 * DMODEL)           // 3072
#define BH    (BATCH * HEADS)        // 32

// half scratch as half2 units (uint32), k-permuted for mma fragments
__device__ uint32_t g_xh [(size_t)MROWS * 512];
__device__ uint32_t g_wqh[(size_t)NQKV * 512];
__device__ uint32_t g_wph[(size_t)DMODEL * 512];
__device__ uint32_t g_qh [(size_t)BH * SEQ * 32];    // Q (LN'd, *0.125*log2e)
__device__ uint32_t g_kh [(size_t)BH * SEQ * 32];    // K (LN'd)
__device__ __half   g_vTh[(size_t)BH * HDIM * SEQ];  // V transposed, key-permuted
__device__ uint32_t g_oh [(size_t)MROWS * 512];      // attn out, dmodel-permuted

__device__ __forceinline__ uint32_t f2h2(float a, float b) {
    __half2 h = __floats2half2_rn(a, b);
    return *reinterpret_cast<uint32_t*>(&h);
}
__device__ __forceinline__ float ex2f(float x) {
    float r;
    asm("ex2.approx.ftz.f32 %0, %1;" : "=f"(r) : "f"(x));
    return r;
}
__device__ __forceinline__ int p16(int u) {
    return ((u & 3) << 2) | ((u >> 3) << 1) | ((u >> 2) & 1);
}
__device__ __forceinline__ void cpa16(uint32_t saddr, const void* gaddr) {
    asm volatile("cp.async.cg.shared.global [%0], [%1], 16;" :: "r"(saddr), "l"(gaddr) : "memory");
}
#define CP_COMMIT() asm volatile("cp.async.commit_group;" ::: "memory")
#define CP_WAIT(n)  asm volatile("cp.async.wait_group %0;" :: "n"(n) : "memory")

__device__ __forceinline__ uint4 lds128(uint32_t addr) {
    uint4 v;
    asm volatile("ld.shared.v4.b32 {%0,%1,%2,%3}, [%4];"
        : "=r"(v.x), "=r"(v.y), "=r"(v.z), "=r"(v.w) : "r"(addr));
    return v;
}

__device__ __forceinline__ void mma16(float* c, uint32_t a0, uint32_t a1,
                                      uint32_t a2, uint32_t a3,
                                      uint32_t b0, uint32_t b1) {
    asm volatile(
        "mma.sync.aligned.m16n8k16.row.col.f32.f16.f16.f32 "
        "{%0,%1,%2,%3}, {%4,%5,%6,%7}, {%8,%9}, {%0,%1,%2,%3};"
        : "+f"(c[0]), "+f"(c[1]), "+f"(c[2]), "+f"(c[3])
        : "r"(a0), "r"(a1), "r"(a2), "r"(a3), "r"(b0), "r"(b1));
}

// ---------------------------------------------------------------------------
// Kernel 0: fp32 -> permuted half for X, w_qkv, w_proj.
// ---------------------------------------------------------------------------
#define NU4_X  (MROWS * 128)
#define NU4_WQ (NQKV * 128)
#define NU4_WP (DMODEL * 128)
#define NU4_TOT (NU4_X + NU4_WQ + NU4_WP)

__global__ __launch_bounds__(256) void prep_kernel(
    const float* __restrict__ X, const float* __restrict__ Wq,
    const float* __restrict__ Wp)
{
    int gi = blockIdx.x * 256 + threadIdx.x;
    const float* src; uint4* dst; int li;
    if (gi < NU4_X)                { src = X;  dst = (uint4*)g_xh;  li = gi; }
    else if (gi < NU4_X + NU4_WQ)  { src = Wq; dst = (uint4*)g_wqh; li = gi - NU4_X; }
    else                           { src = Wp; dst = (uint4*)g_wph; li = gi - NU4_X - NU4_WQ; }
    int row = li >> 7, rem = li & 127, b = rem >> 2, c = rem & 3;
    const float* base = src + (size_t)row * DMODEL + b * 32 + 2 * c;
    float2 f0 = *(const float2*)(base + 0);
    float2 f1 = *(const float2*)(base + 8);
    float2 f2 = *(const float2*)(base + 16);
    float2 f3 = *(const float2*)(base + 24);
    uint4 o;
    o.x = f2h2(f0.x, f0.y); o.y = f2h2(f1.x, f1.y);
    o.z = f2h2(f2.x, f2.y); o.w = f2h2(f3.x, f3.y);
    dst[li] = o;
}

// ---------------------------------------------------------------------------
// Shared GEMM mainloop: CTA 128x64, k-tile 64 (32u), cp.async 4-stage,
// ONE barrier per tile. Fragment LDS addrs precomputed.
// ---------------------------------------------------------------------------
#define STAGE 6144
#define GSTAGES 4
#define GEMM_SMEM (GSTAGES * STAGE * 4)   // 98304 B
#define NTK (DMODEL / 64)                 // 16

struct GemmAcc { float a[2][4][4]; };

__device__ __forceinline__ void gemm_mainloop(
    uint32_t* sm, const uint32_t* Asrc, const uint32_t* Bsrc,
    int mBase, int nBase, int tid, int wm, int wn, int g, int t,
    GemmAcc& A)
{
#pragma unroll
    for (int mt = 0; mt < 2; mt++)
#pragma unroll
        for (int nt = 0; nt < 4; nt++)
#pragma unroll
            for (int i = 0; i < 4; i++) A.a[mt][nt][i] = 0.0f;

    const int frA = tid >> 3, fc = tid & 7;
    const int frB = tid >> 3;
    uint32_t adst[4], bdst[2];
    const uint32_t* asrc[4];
    const uint32_t* bsrc[2];
#pragma unroll
    for (int i = 0; i < 4; i++) {
        int row = frA + i * 32;
        adst[i] = (uint32_t)__cvta_generic_to_shared(
            &sm[row * 32 + ((fc * 4) ^ ((row & 1) * 16))]);
        asrc[i] = Asrc + (size_t)(mBase + row) * 512 + fc * 4;
    }
#pragma unroll
    for (int i = 0; i < 2; i++) {
        int row = frB + i * 32;
        bdst[i] = (uint32_t)__cvta_generic_to_shared(
            &sm[4096 + row * 32 + ((fc * 4) ^ ((row & 1) * 16))]);
        bsrc[i] = Bsrc + (size_t)(nBase + row) * 512 + fc * 4;
    }

    // Precomputed fragment read addresses (stage 0)
    uint32_t afa[2][2][2], bfa[2][4];
#pragma unroll
    for (int b2 = 0; b2 < 2; b2++) {
#pragma unroll
        for (int mt = 0; mt < 2; mt++) {
            int r0 = wm + mt * 16 + g, r1 = r0 + 8;
            afa[b2][mt][0] = (uint32_t)__cvta_generic_to_shared(
                &sm[r0 * 32 + (((b2 << 4) ^ ((r0 & 1) << 4)) + t * 4)]);
            afa[b2][mt][1] = (uint32_t)__cvta_generic_to_shared(
                &sm[r1 * 32 + (((b2 << 4) ^ ((r1 & 1) << 4)) + t * 4)]);
        }
#pragma unroll
        for (int nt = 0; nt < 4; nt++) {
            int rn = wn + nt * 8 + g;
            bfa[b2][nt] = (uint32_t)__cvta_generic_to_shared(
                &sm[4096 + rn * 32 + (((b2 << 4) ^ ((rn & 1) << 4)) + t * 4)]);
        }
    }

    // Prologue: stage tiles 0..2
#pragma unroll
    for (int s = 0; s < 3; s++) {
        uint32_t soff = (uint32_t)(s * (STAGE * 4));
        int gofs = s * 32;
#pragma unroll
        for (int i = 0; i < 4; i++) cpa16(adst[i] + soff, asrc[i] + gofs);
#pragma unroll
        for (int i = 0; i < 2; i++) cpa16(bdst[i] + soff, bsrc[i] + gofs);
        CP_COMMIT();
    }

    for (int it = 0; it < NTK; it++) {
        if (it + 2 < NTK)      CP_WAIT(2);
        else if (it + 1 < NTK) CP_WAIT(1);
        else                   CP_WAIT(0);
        __syncthreads();

        const uint32_t bo = (uint32_t)((it & 3) * (STAGE * 4));
#pragma unroll
        for (int b2 = 0; b2 < 2; b2++) {
            uint4 af[2][2], bf[4];
#pragma unroll
            for (int mt = 0; mt < 2; mt++) {
                af[mt][0] = lds128(afa[b2][mt][0] + bo);
                af[mt][1] = lds128(afa[b2][mt][1] + bo);
            }
#pragma unroll
            for (int nt = 0; nt < 4; nt++)
                bf[nt] = lds128(bfa[b2][nt] + bo);
#pragma unroll
            for (int mt = 0; mt < 2; mt++)
#pragma unroll
                for (int nt = 0; nt < 4; nt++) {
                    mma16(A.a[mt][nt], af[mt][0].x, af[mt][1].x, af[mt][0].y, af[mt][1].y,
                          bf[nt].x, bf[nt].y);
                    mma16(A.a[mt][nt], af[mt][0].z, af[mt][1].z, af[mt][0].w, af[mt][1].w,
                          bf[nt].z, bf[nt].w);
                }
        }

        if (it + 3 < NTK) {
            uint32_t soff = (uint32_t)(((it + 3) & 3) * (STAGE * 4));
            int gofs = (it + 3) * 32;
#pragma unroll
            for (int i = 0; i < 4; i++) cpa16(adst[i] + soff, asrc[i] + gofs);
#pragma unroll
            for (int i = 0; i < 2; i++) cpa16(bdst[i] + soff, bsrc[i] + gofs);
            CP_COMMIT();
        }
    }
    __syncthreads();   // protect smem before epilogue overlays it
}

// ---------------------------------------------------------------------------
// Kernel 1: QKV GEMM + fused LN.
// ---------------------------------------------------------------------------
__global__ __launch_bounds__(256, 2) void qkv_gemm_h(
    const float* __restrict__ bias,
    const float* __restrict__ qg, const float* __restrict__ qb,
    const float* __restrict__ kg, const float* __restrict__ kb)
{
    extern __shared__ __align__(16) uint32_t sm[];
    const int tid = threadIdx.x;
    const int warp = tid >> 5, lane = tid & 31;
    const int g = lane >> 2, t = lane & 3;
    const int wm = (warp >> 1) * 32, wn = (warp & 1) * 32;
    const int mBase = blockIdx.y * 128, nBase = blockIdx.x * 64;
    const int part = nBase >> 10;
    const int h = (nBase >> 6) & 15;

    GemmAcc A;
    gemm_mainloop(sm, g_xh, g_wqh, mBase, nBase, tid, wm, wn, g, t, A);

    if (part == 2) {
#pragma unroll
        for (int mt = 0; mt < 2; mt++)
#pragma unroll
            for (int hf = 0; hf < 2; hf++) {
                int row = mBase + wm + mt * 16 + g + hf * 8;
                int bb = row >> 11, s = row & 2047;
                int bhv = bb * HEADS + h;
                int u = (s & 31) >> 1, hh = s & 1;
                int ph = (s & ~31) + p16(u) * 2 + hh;
#pragma unroll
                for (int nt = 0; nt < 4; nt++) {
                    int col = nBase + wn + nt * 8 + 2 * t;
                    float v0 = A.a[mt][nt][hf * 2 + 0] + bias[col];
                    float v1 = A.a[mt][nt][hf * 2 + 1] + bias[col + 1];
                    int hd = col & 63;
                    g_vTh[((size_t)(bhv * HDIM + hd)     * SEQ) + ph] = __float2half_rn(v0);
                    g_vTh[((size_t)(bhv * HDIM + hd + 1) * SEQ) + ph] = __float2half_rn(v1);
                }
            }
        return;
    }

    float* T = (float*)sm;
#pragma unroll
    for (int mt = 0; mt < 2; mt++)
#pragma unroll
        for (int hf = 0; hf < 2; hf++) {
            int rl = wm + mt * 16 + g + hf * 8;
#pragma unroll
            for (int nt = 0; nt < 4; nt++) {
                int col = wn + nt * 8 + 2 * t;
                float2 v = make_float2(A.a[mt][nt][hf * 2 + 0] + bias[nBase + col],
                                       A.a[mt][nt][hf * 2 + 1] + bias[nBase + col + 1]);
                *(float2*)&T[rl * 68 + col] = v;
            }
        }
    __syncthreads();

    const float* gamma = (part == 0) ? qg : kg;
    const float* beta  = (part == 0) ? qb : kb;
    uint32_t* dstbase = (part == 0) ? g_qh : g_kh;
    const float sc = (part == 0) ? (0.125f * 1.4426950408889634f) : 1.0f;
    float2 gm = *(const float2*)&gamma[2 * lane];
    float2 bt = *(const float2*)&beta[2 * lane];
    const int outpos = ((lane >> 4) << 4) + p16(lane & 15);

    for (int r16 = 0; r16 < 16; r16++) {
        int rl = warp * 16 + r16;
        float2 x = *(const float2*)&T[rl * 68 + 2 * lane];
        float s = x.x + x.y;
#pragma unroll
        for (int o = 16; o >= 1; o >>= 1) s += __shfl_xor_sync(0xffffffffu, s, o);
        float mu = s * (1.0f / 64.0f);
        float d0 = x.x - mu, d1 = x.y - mu;
        float v = d0 * d0 + d1 * d1;
#pragma unroll
        for (int o = 16; o >= 1; o >>= 1) v += __shfl_xor_sync(0xffffffffu, v, o);
        float r = rsqrtf(v * (1.0f / 64.0f) + 1e-5f);
        float y0 = (d0 * r * gm.x + bt.x) * sc;
        float y1 = (d1 * r * gm.y + bt.y) * sc;
        int m = mBase + rl;
        int bb = m >> 11, s2 = m & 2047;
        dstbase[((size_t)(bb * HEADS + h) * SEQ + s2) * 32 + outpos] = f2h2(y0, y1);
    }
}

// ---------------------------------------------------------------------------
// Kernel 3: flash attention fp16. Register-direct P, no running max,
// row-sums via ones-mma. cp.async 4-stage K/V, ONE barrier per tile.
// ---------------------------------------------------------------------------
#define NT (SEQ / 64)                     // 32
#define ASTAGE 4096                       // u32 per stage (K 2048 + V 2048)
#define ATTN_SMEM ((4096 + 4 * ASTAGE) * 4)   // 81920 B
#define ONES2 0x3C003C00u

__global__ __launch_bounds__(256, 2) void attn_h_kernel()
{
    extern __shared__ __align__(16) uint32_t smem[];
    uint32_t* Qs = smem;                 // [128][32u] = 4096 u32
    uint32_t* Kst = smem + 4096;         // 4 stages x (K[64][32] + V[64][32])

    const int tid = threadIdx.x;
    const int warp = tid >> 5, lane = tid & 31;
    const int g = lane >> 2, t = lane & 3;
    const int wm = warp * 16;
    const int bh = blockIdx.y;
    const int qbase = blockIdx.x * 128;

    const uint32_t* Qg = g_qh + (size_t)(bh * SEQ) * 32;
    const uint32_t* Kg = g_kh + (size_t)(bh * SEQ) * 32;
    const __half*   Vg = g_vTh + (size_t)bh * HDIM * SEQ;

#pragma unroll
    for (int i = 0; i < 4; i++) {
        int idx = tid + i * 256, row = idx >> 3, c = idx & 7;
        uint4 v = *(const uint4*)&Qg[(size_t)(qbase + row) * 32 + c * 4];
        *(uint4*)&Qs[row * 32 + ((c * 4) ^ ((row & 1) * 16))] = v;
    }

    const int fr = tid >> 3, fc = tid & 7;
    uint32_t kdst0 = (uint32_t)__cvta_generic_to_shared(
        &Kst[fr * 32 + ((fc * 4) ^ ((fr & 1) * 16))]);
    uint32_t kdst1 = (uint32_t)__cvta_generic_to_shared(
        &Kst[(fr + 32) * 32 + ((fc * 4) ^ ((fr & 1) * 16))]);
    uint32_t vdst0 = (uint32_t)__cvta_generic_to_shared(
        &Kst[2048 + fr * 32 + ((fc * 4) ^ ((fr & 1) * 16))]);
    uint32_t vdst1 = (uint32_t)__cvta_generic_to_shared(
        &Kst[2048 + (fr + 32) * 32 + ((fc * 4) ^ ((fr & 1) * 16))]);
    const uint32_t* ksrc0 = Kg + fr * 32 + fc * 4;
    const uint32_t* ksrc1 = Kg + (fr + 32) * 32 + fc * 4;
    const __half* vsrc0 = Vg + (size_t)fr * SEQ + fc * 8;
    const __half* vsrc1 = Vg + (size_t)(fr + 32) * SEQ + fc * 8;

    // Prologue: stage tiles 0..2
#pragma unroll
    for (int s = 0; s < 3; s++) {
        uint32_t soff = (uint32_t)(s * (ASTAGE * 4));
        int gk = s * 2048, gv = s * 64;
        cpa16(kdst0 + soff, ksrc0 + gk);
        cpa16(kdst1 + soff, ksrc1 + gk);
        cpa16(vdst0 + soff, vsrc0 + gv);
        cpa16(vdst1 + soff, vsrc1 + gv);
        CP_COMMIT();
    }

    float lsum[4];
#pragma unroll
    for (int i = 0; i < 4; i++) lsum[i] = 0.0f;
    float o[8][4];
#pragma unroll
    for (int nt = 0; nt < 8; nt++)
#pragma unroll
        for (int i = 0; i < 4; i++) o[nt][i] = 0.0f;

    for (int it = 0; it < NT; it++) {
        if (it + 2 < NT)      CP_WAIT(2);
        else if (it + 1 < NT) CP_WAIT(1);
        else                  CP_WAIT(0);
        __syncthreads();

        const uint32_t* KsB = Kst + (it & 3) * ASTAGE;
        const uint32_t* VtB = KsB + 2048;

        // S = Q K^T
        float s[8][4];
#pragma unroll
        for (int nt = 0; nt < 8; nt++)
#pragma unroll
            for (int i = 0; i < 4; i++) s[nt][i] = 0.0f;

#pragma unroll
        for (int b2 = 0; b2 < 2; b2++) {
            int r0 = wm + g, r1 = wm + g + 8;
            uint4 qa0 = *(const uint4*)&Qs[r0 * 32 + (((b2 << 4) ^ ((r0 & 1) << 4)) + t * 4)];
            uint4 qa1 = *(const uint4*)&Qs[r1 * 32 + (((b2 << 4) ^ ((r1 & 1) << 4)) + t * 4)];
#pragma unroll
            for (int nt = 0; nt < 8; nt++) {
                int rn = nt * 8 + g;
                uint4 kb = *(const uint4*)&KsB[rn * 32 + (((b2 << 4) ^ ((rn & 1) << 4)) + t * 4)];
                mma16(s[nt], qa0.x, qa1.x, qa0.y, qa1.y, kb.x, kb.y);
                mma16(s[nt], qa0.z, qa1.z, qa0.w, qa1.w, kb.z, kb.w);
            }
        }

        // p = ex2(s) -> half2 A-fragments; row sums via ones-mma
        uint32_t ah[4][4];
#pragma unroll
        for (int kb2 = 0; kb2 < 4; kb2++) {
            float p00 = ex2f(s[2*kb2][0]),   p01 = ex2f(s[2*kb2][1]);
            float p02 = ex2f(s[2*kb2][2]),   p03 = ex2f(s[2*kb2][3]);
            float p10 = ex2f(s[2*kb2+1][0]), p11 = ex2f(s[2*kb2+1][1]);
            float p12 = ex2f(s[2*kb2+1][2]), p13 = ex2f(s[2*kb2+1][3]);
            ah[kb2][0] = f2h2(p00, p01);
            ah[kb2][1] = f2h2(p02, p03);
            ah[kb2][2] = f2h2(p10, p11);
            ah[kb2][3] = f2h2(p12, p13);
            mma16(lsum, ah[kb2][0], ah[kb2][1], ah[kb2][2], ah[kb2][3], ONES2, ONES2);
        }

        // O += P V
#pragma unroll
        for (int b2 = 0; b2 < 2; b2++) {
#pragma unroll
            for (int nt = 0; nt < 8; nt++) {
                int rn = nt * 8 + g;
                uint4 vb = *(const uint4*)&VtB[rn * 32 + (((b2 << 4) ^ ((rn & 1) << 4)) + t * 4)];
                mma16(o[nt], ah[2*b2][0],   ah[2*b2][1],   ah[2*b2][2],   ah[2*b2][3],
                      vb.x, vb.y);
                mma16(o[nt], ah[2*b2+1][0], ah[2*b2+1][1], ah[2*b2+1][2], ah[2*b2+1][3],
                      vb.z, vb.w);
            }
        }

        if (it + 3 < NT) {
            uint32_t soff = (uint32_t)(((it + 3) & 3) * (ASTAGE * 4));
            int gk = (it + 3) * 2048, gv = (it + 3) * 64;
            cpa16(kdst0 + soff, ksrc0 + gk);
            cpa16(kdst1 + soff, ksrc1 + gk);
            cpa16(vdst0 + soff, vsrc0 + gv);
            cpa16(vdst1 + soff, vsrc1 + gv);
            CP_COMMIT();
        }
    }

    int b = bh >> 4, h = bh & 15;
    float l_i[2] = { lsum[0], lsum[2] };
#pragma unroll
    for (int slot = 0; slot < 2; slot++) {
        float inv = 1.0f / l_i[slot];
        int row = wm + g + slot * 8;
        size_t m = (size_t)b * SEQ + qbase + row;
        uint4 lo = make_uint4(f2h2(o[0][slot*2]*inv, o[0][slot*2+1]*inv),
                              f2h2(o[1][slot*2]*inv, o[1][slot*2+1]*inv),
                              f2h2(o[2][slot*2]*inv, o[2][slot*2+1]*inv),
                              f2h2(o[3][slot*2]*inv, o[3][slot*2+1]*inv));
        uint4 hi = make_uint4(f2h2(o[4][slot*2]*inv, o[4][slot*2+1]*inv),
                              f2h2(o[5][slot*2]*inv, o[5][slot*2+1]*inv),
                              f2h2(o[6][slot*2]*inv, o[6][slot*2+1]*inv),
                              f2h2(o[7][slot*2]*inv, o[7][slot*2+1]*inv));
        *(uint4*)&g_oh[m * 512 + h * 32 + t * 4] = lo;
        *(uint4*)&g_oh[m * 512 + h * 32 + 16 + t * 4] = hi;
    }
}

// ---------------------------------------------------------------------------
// Kernel 4: projection GEMM (pipelined), fp32 out.
// ---------------------------------------------------------------------------
__global__ __launch_bounds__(256, 2) void proj_gemm_h(
    const float* __restrict__ bp, float* __restrict__ out)
{
    extern __shared__ __align__(16) uint32_t sm[];
    const int tid = threadIdx.x;
    const int warp = tid >> 5, lane = tid & 31;
    const int g = lane >> 2, t = lane & 3;
    const int wm = (warp >> 1) * 32, wn = (warp & 1) * 32;
    const int mBase = blockIdx.y * 128, nBase = blockIdx.x * 64;

    GemmAcc A;
    gemm_mainloop(sm, g_oh, g_wph, mBase, nBase, tid, wm, wn, g, t, A);

#pragma unroll
    for (int mt = 0; mt < 2; mt++)
#pragma unroll
        for (int hf = 0; hf < 2; hf++) {
            int row = mBase + wm + mt * 16 + g + hf * 8;
#pragma unroll
            for (int nt = 0; nt < 4; nt++) {
                int col = nBase + wn + nt * 8 + 2 * t;
                float2 r = make_float2(A.a[mt][nt][hf * 2 + 0] + bp[col],
                                       A.a[mt][nt][hf * 2 + 1] + bp[col + 1]);
                *(float2*)&out[(size_t)row * DMODEL + col] = r;
            }
        }
}

// ---------------------------------------------------------------------------
// Launch. Inputs: 0:x 1:w_qkv 2:b_qkv 3:w_proj 4:b_proj 5:qg 6:qb 7:kg 8:kb
// ---------------------------------------------------------------------------
extern "C" void kernel_launch(void* const* d_in, const int* in_sizes, int n_in,
                              void* d_out, int out_size)
{
    const float* x      = (const float*)d_in[0];
    const float* w_qkv  = (const float*)d_in[1];
    const float* b_qkv  = (const float*)d_in[2];
    const float* w_proj = (const float*)d_in[3];
    const float* b_proj = (const float*)d_in[4];
    const float* q_g    = (const float*)d_in[5];
    const float* q_b    = (const float*)d_in[6];
    const float* k_g    = (const float*)d_in[7];
    const float* k_b    = (const float*)d_in[8];
    float* out = (float*)d_out;

    cudaFuncSetAttribute(attn_h_kernel,
                         cudaFuncAttributeMaxDynamicSharedMemorySize, ATTN_SMEM);
    cudaFuncSetAttribute(qkv_gemm_h,
                         cudaFuncAttributeMaxDynamicSharedMemorySize, GEMM_SMEM);
    cudaFuncSetAttribute(proj_gemm_h,
                         cudaFuncAttributeMaxDynamicSharedMemorySize, GEMM_SMEM);

    prep_kernel<<<NU4_TOT / 256, 256>>>(x, w_qkv, w_proj);

    dim3 g1(NQKV / 64, MROWS / 128);    // (48, 32)
    qkv_gemm_h<<<g1, 256, GEMM_SMEM>>>(b_qkv, q_g, q_b, k_g, k_b);

    dim3 g3(SEQ / 128, BH);             // (16, 32)
    attn_h_kernel<<<g3, 256, ATTN_SMEM>>>();

    dim3 g4(DMODEL / 64, MROWS / 128);  // (16, 32)
    proj_gemm_h<<<g4, 256, GEMM_SMEM>>>(b_proj, out);
}

// round 17
// speedup vs baseline: 3.0988x; 1.0144x over previous
#include <cuda_runtime.h>
#include <cuda_fp16.h>
#include <math.h>
#include <stdint.h>

#define BATCH 2
#define SEQ   2048
#define DMODEL 1024
#define HEADS 16
#define HDIM  64
#define MROWS (BATCH * SEQ)          // 4096
#define NQKV  (3 * DMODEL)           // 3072
#define BH    (BATCH * HEADS)        // 32

// half scratch as half2 units (uint32), k-permuted for mma fragments
__device__ uint32_t g_xh [(size_t)MROWS * 512];
__device__ uint32_t g_wqh[(size_t)NQKV * 512];
__device__ uint32_t g_wph[(size_t)DMODEL * 512];
__device__ uint32_t g_qh [(size_t)BH * SEQ * 32];    // Q (LN'd, *0.125*log2e)
__device__ uint32_t g_kh [(size_t)BH * SEQ * 32];    // K (LN'd)
__device__ __half   g_vTh[(size_t)BH * HDIM * SEQ];  // V transposed, key-permuted
__device__ uint32_t g_oh [(size_t)MROWS * 512];      // attn out, dmodel-permuted

__device__ __forceinline__ uint32_t f2h2(float a, float b) {
    __half2 h = __floats2half2_rn(a, b);
    return *reinterpret_cast<uint32_t*>(&h);
}
__device__ __forceinline__ float ex2f(float x) {
    float r;
    asm("ex2.approx.ftz.f32 %0, %1;" : "=f"(r) : "f"(x));
    return r;
}
__device__ __forceinline__ int p16(int u) {
    return ((u & 3) << 2) | ((u >> 3) << 1) | ((u >> 2) & 1);
}
__device__ __forceinline__ void cpa16(uint32_t saddr, const void* gaddr) {
    asm volatile("cp.async.cg.shared.global [%0], [%1], 16;" :: "r"(saddr), "l"(gaddr) : "memory");
}
#define CP_COMMIT() asm volatile("cp.async.commit_group;" ::: "memory")
#define CP_WAIT(n)  asm volatile("cp.async.wait_group %0;" :: "n"(n) : "memory")

__device__ __forceinline__ uint4 lds128(uint32_t addr) {
    uint4 v;
    asm volatile("ld.shared.v4.b32 {%0,%1,%2,%3}, [%4];"
        : "=r"(v.x), "=r"(v.y), "=r"(v.z), "=r"(v.w) : "r"(addr));
    return v;
}

__device__ __forceinline__ void mma16(float* c, uint32_t a0, uint32_t a1,
                                      uint32_t a2, uint32_t a3,
                                      uint32_t b0, uint32_t b1) {
    asm volatile(
        "mma.sync.aligned.m16n8k16.row.col.f32.f16.f16.f32 "
        "{%0,%1,%2,%3}, {%4,%5,%6,%7}, {%8,%9}, {%0,%1,%2,%3};"
        : "+f"(c[0]), "+f"(c[1]), "+f"(c[2]), "+f"(c[3])
        : "r"(a0), "r"(a1), "r"(a2), "r"(a3), "r"(b0), "r"(b1));
}

// ---------------------------------------------------------------------------
// Kernel 0: fp32 -> permuted half for X, w_qkv, w_proj.
// ---------------------------------------------------------------------------
#define NU4_X  (MROWS * 128)
#define NU4_WQ (NQKV * 128)
#define NU4_WP (DMODEL * 128)
#define NU4_TOT (NU4_X + NU4_WQ + NU4_WP)

__global__ __launch_bounds__(256) void prep_kernel(
    const float* __restrict__ X, const float* __restrict__ Wq,
    const float* __restrict__ Wp)
{
    int gi = blockIdx.x * 256 + threadIdx.x;
    const float* src; uint4* dst; int li;
    if (gi < NU4_X)                { src = X;  dst = (uint4*)g_xh;  li = gi; }
    else if (gi < NU4_X + NU4_WQ)  { src = Wq; dst = (uint4*)g_wqh; li = gi - NU4_X; }
    else                           { src = Wp; dst = (uint4*)g_wph; li = gi - NU4_X - NU4_WQ; }
    int row = li >> 7, rem = li & 127, b = rem >> 2, c = rem & 3;
    const float* base = src + (size_t)row * DMODEL + b * 32 + 2 * c;
    float2 f0 = *(const float2*)(base + 0);
    float2 f1 = *(const float2*)(base + 8);
    float2 f2 = *(const float2*)(base + 16);
    float2 f3 = *(const float2*)(base + 24);
    uint4 o;
    o.x = f2h2(f0.x, f0.y); o.y = f2h2(f1.x, f1.y);
    o.z = f2h2(f2.x, f2.y); o.w = f2h2(f3.x, f3.y);
    dst[li] = o;
}

// ---------------------------------------------------------------------------
// Shared GEMM mainloop: CTA 128x64, k-tile 64 (32u), cp.async 3-stage,
// ONE barrier per tile, 3 CTAs/SM. Fragment LDS addrs precomputed.
// ---------------------------------------------------------------------------
#define STAGE 6144
#define STAGE4 (STAGE * 4)
#define GSTAGES 3
#define GEMM_SMEM (GSTAGES * STAGE * 4)   // 73728 B
#define NTK (DMODEL / 64)                 // 16

struct GemmAcc { float a[2][4][4]; };

__device__ __forceinline__ void gemm_mainloop(
    uint32_t* sm, const uint32_t* Asrc, const uint32_t* Bsrc,
    int mBase, int nBase, int tid, int wm, int wn, int g, int t,
    GemmAcc& A)
{
#pragma unroll
    for (int mt = 0; mt < 2; mt++)
#pragma unroll
        for (int nt = 0; nt < 4; nt++)
#pragma unroll
            for (int i = 0; i < 4; i++) A.a[mt][nt][i] = 0.0f;

    const int frA = tid >> 3, fc = tid & 7;
    const int frB = tid >> 3;
    uint32_t adst[4], bdst[2];
    const uint32_t* asrc[4];
    const uint32_t* bsrc[2];
#pragma unroll
    for (int i = 0; i < 4; i++) {
        int row = frA + i * 32;
        adst[i] = (uint32_t)__cvta_generic_to_shared(
            &sm[row * 32 + ((fc * 4) ^ ((row & 1) * 16))]);
        asrc[i] = Asrc + (size_t)(mBase + row) * 512 + fc * 4;
    }
#pragma unroll
    for (int i = 0; i < 2; i++) {
        int row = frB + i * 32;
        bdst[i] = (uint32_t)__cvta_generic_to_shared(
            &sm[4096 + row * 32 + ((fc * 4) ^ ((row & 1) * 16))]);
        bsrc[i] = Bsrc + (size_t)(nBase + row) * 512 + fc * 4;
    }

    // Precomputed fragment read addresses (stage 0)
    uint32_t afa[2][2][2], bfa[2][4];
#pragma unroll
    for (int b2 = 0; b2 < 2; b2++) {
#pragma unroll
        for (int mt = 0; mt < 2; mt++) {
            int r0 = wm + mt * 16 + g, r1 = r0 + 8;
            afa[b2][mt][0] = (uint32_t)__cvta_generic_to_shared(
                &sm[r0 * 32 + (((b2 << 4) ^ ((r0 & 1) << 4)) + t * 4)]);
            afa[b2][mt][1] = (uint32_t)__cvta_generic_to_shared(
                &sm[r1 * 32 + (((b2 << 4) ^ ((r1 & 1) << 4)) + t * 4)]);
        }
#pragma unroll
        for (int nt = 0; nt < 4; nt++) {
            int rn = wn + nt * 8 + g;
            bfa[b2][nt] = (uint32_t)__cvta_generic_to_shared(
                &sm[4096 + rn * 32 + (((b2 << 4) ^ ((rn & 1) << 4)) + t * 4)]);
        }
    }

    // Prologue: stage tiles 0..1
#pragma unroll
    for (int s = 0; s < 2; s++) {
        uint32_t soff = (uint32_t)(s * STAGE4);
        int gofs = s * 32;
#pragma unroll
        for (int i = 0; i < 4; i++) cpa16(adst[i] + soff, asrc[i] + gofs);
#pragma unroll
        for (int i = 0; i < 2; i++) cpa16(bdst[i] + soff, bsrc[i] + gofs);
        CP_COMMIT();
    }

    uint32_t bo = 0;                     // buffer of current tile (it % 3)
    uint32_t po = 2 * STAGE4;            // buffer of prefetch tile ((it+2) % 3)
    for (int it = 0; it < NTK; it++) {
        if (it + 1 < NTK) CP_WAIT(1);
        else              CP_WAIT(0);
        __syncthreads();

#pragma unroll
        for (int b2 = 0; b2 < 2; b2++) {
            uint4 af[2][2], bf[4];
#pragma unroll
            for (int mt = 0; mt < 2; mt++) {
                af[mt][0] = lds128(afa[b2][mt][0] + bo);
                af[mt][1] = lds128(afa[b2][mt][1] + bo);
            }
#pragma unroll
            for (int nt = 0; nt < 4; nt++)
                bf[nt] = lds128(bfa[b2][nt] + bo);
#pragma unroll
            for (int mt = 0; mt < 2; mt++)
#pragma unroll
                for (int nt = 0; nt < 4; nt++) {
                    mma16(A.a[mt][nt], af[mt][0].x, af[mt][1].x, af[mt][0].y, af[mt][1].y,
                          bf[nt].x, bf[nt].y);
                    mma16(A.a[mt][nt], af[mt][0].z, af[mt][1].z, af[mt][0].w, af[mt][1].w,
                          bf[nt].z, bf[nt].w);
                }
        }

        if (it + 2 < NTK) {
            int gofs = (it + 2) * 32;
#pragma unroll
            for (int i = 0; i < 4; i++) cpa16(adst[i] + po, asrc[i] + gofs);
#pragma unroll
            for (int i = 0; i < 2; i++) cpa16(bdst[i] + po, bsrc[i] + gofs);
            CP_COMMIT();
        }
        bo += STAGE4; if (bo == 3 * STAGE4) bo = 0;
        po += STAGE4; if (po == 3 * STAGE4) po = 0;
    }
    __syncthreads();   // protect smem before epilogue overlays it
}

// ---------------------------------------------------------------------------
// Kernel 1: QKV GEMM + fused LN.
// ---------------------------------------------------------------------------
__global__ __launch_bounds__(256, 3) void qkv_gemm_h(
    const float* __restrict__ bias,
    const float* __restrict__ qg, const float* __restrict__ qb,
    const float* __restrict__ kg, const float* __restrict__ kb)
{
    extern __shared__ __align__(16) uint32_t sm[];
    const int tid = threadIdx.x;
    const int warp = tid >> 5, lane = tid & 31;
    const int g = lane >> 2, t = lane & 3;
    const int wm = (warp >> 1) * 32, wn = (warp & 1) * 32;
    const int mBase = blockIdx.y * 128, nBase = blockIdx.x * 64;
    const int part = nBase >> 10;
    const int h = (nBase >> 6) & 15;

    GemmAcc A;
    gemm_mainloop(sm, g_xh, g_wqh, mBase, nBase, tid, wm, wn, g, t, A);

    if (part == 2) {
#pragma unroll
        for (int mt = 0; mt < 2; mt++)
#pragma unroll
            for (int hf = 0; hf < 2; hf++) {
                int row = mBase + wm + mt * 16 + g + hf * 8;
                int bb = row >> 11, s = row & 2047;
                int bhv = bb * HEADS + h;
                int u = (s & 31) >> 1, hh = s & 1;
                int ph = (s & ~31) + p16(u) * 2 + hh;
#pragma unroll
                for (int nt = 0; nt < 4; nt++) {
                    int col = nBase + wn + nt * 8 + 2 * t;
                    float v0 = A.a[mt][nt][hf * 2 + 0] + bias[col];
                    float v1 = A.a[mt][nt][hf * 2 + 1] + bias[col + 1];
                    int hd = col & 63;
                    g_vTh[((size_t)(bhv * HDIM + hd)     * SEQ) + ph] = __float2half_rn(v0);
                    g_vTh[((size_t)(bhv * HDIM + hd + 1) * SEQ) + ph] = __float2half_rn(v1);
                }
            }
        return;
    }

    float* T = (float*)sm;
#pragma unroll
    for (int mt = 0; mt < 2; mt++)
#pragma unroll
        for (int hf = 0; hf < 2; hf++) {
            int rl = wm + mt * 16 + g + hf * 8;
#pragma unroll
            for (int nt = 0; nt < 4; nt++) {
                int col = wn + nt * 8 + 2 * t;
                float2 v = make_float2(A.a[mt][nt][hf * 2 + 0] + bias[nBase + col],
                                       A.a[mt][nt][hf * 2 + 1] + bias[nBase + col + 1]);
                *(float2*)&T[rl * 68 + col] = v;
            }
        }
    __syncthreads();

    const float* gamma = (part == 0) ? qg : kg;
    const float* beta  = (part == 0) ? qb : kb;
    uint32_t* dstbase = (part == 0) ? g_qh : g_kh;
    const float sc = (part == 0) ? (0.125f * 1.4426950408889634f) : 1.0f;
    float2 gm = *(const float2*)&gamma[2 * lane];
    float2 bt = *(const float2*)&beta[2 * lane];
    const int outpos = ((lane >> 4) << 4) + p16(lane & 15);

    for (int r16 = 0; r16 < 16; r16++) {
        int rl = warp * 16 + r16;
        float2 x = *(const float2*)&T[rl * 68 + 2 * lane];
        float s = x.x + x.y;
#pragma unroll
        for (int o = 16; o >= 1; o >>= 1) s += __shfl_xor_sync(0xffffffffu, s, o);
        float mu = s * (1.0f / 64.0f);
        float d0 = x.x - mu, d1 = x.y - mu;
        float v = d0 * d0 + d1 * d1;
#pragma unroll
        for (int o = 16; o >= 1; o >>= 1) v += __shfl_xor_sync(0xffffffffu, v, o);
        float r = rsqrtf(v * (1.0f / 64.0f) + 1e-5f);
        float y0 = (d0 * r * gm.x + bt.x) * sc;
        float y1 = (d1 * r * gm.y + bt.y) * sc;
        int m = mBase + rl;
        int bb = m >> 11, s2 = m & 2047;
        dstbase[((size_t)(bb * HEADS + h) * SEQ + s2) * 32 + outpos] = f2h2(y0, y1);
    }
}

// ---------------------------------------------------------------------------
// Kernel 3: flash attention fp16. Register-direct P, no running max,
// row-sums via ones-mma. cp.async 4-stage K/V, ONE barrier per tile.
// ---------------------------------------------------------------------------
#define NT (SEQ / 64)                     // 32
#define ASTAGE 4096                       // u32 per stage (K 2048 + V 2048)
#define ATTN_SMEM ((4096 + 4 * ASTAGE) * 4)   // 81920 B
#define ONES2 0x3C003C00u

__global__ __launch_bounds__(256, 2) void attn_h_kernel()
{
    extern __shared__ __align__(16) uint32_t smem[];
    uint32_t* Qs = smem;                 // [128][32u] = 4096 u32
    uint32_t* Kst = smem + 4096;         // 4 stages x (K[64][32] + V[64][32])

    const int tid = threadIdx.x;
    const int warp = tid >> 5, lane = tid & 31;
    const int g = lane >> 2, t = lane & 3;
    const int wm = warp * 16;
    const int bh = blockIdx.y;
    const int qbase = blockIdx.x * 128;

    const uint32_t* Qg = g_qh + (size_t)(bh * SEQ) * 32;
    const uint32_t* Kg = g_kh + (size_t)(bh * SEQ) * 32;
    const __half*   Vg = g_vTh + (size_t)bh * HDIM * SEQ;

#pragma unroll
    for (int i = 0; i < 4; i++) {
        int idx = tid + i * 256, row = idx >> 3, c = idx & 7;
        uint4 v = *(const uint4*)&Qg[(size_t)(qbase + row) * 32 + c * 4];
        *(uint4*)&Qs[row * 32 + ((c * 4) ^ ((row & 1) * 16))] = v;
    }

    const int fr = tid >> 3, fc = tid & 7;
    uint32_t kdst0 = (uint32_t)__cvta_generic_to_shared(
        &Kst[fr * 32 + ((fc * 4) ^ ((fr & 1) * 16))]);
    uint32_t kdst1 = (uint32_t)__cvta_generic_to_shared(
        &Kst[(fr + 32) * 32 + ((fc * 4) ^ ((fr & 1) * 16))]);
    uint32_t vdst0 = (uint32_t)__cvta_generic_to_shared(
        &Kst[2048 + fr * 32 + ((fc * 4) ^ ((fr & 1) * 16))]);
    uint32_t vdst1 = (uint32_t)__cvta_generic_to_shared(
        &Kst[2048 + (fr + 32) * 32 + ((fc * 4) ^ ((fr & 1) * 16))]);
    const uint32_t* ksrc0 = Kg + fr * 32 + fc * 4;
    const uint32_t* ksrc1 = Kg + (fr + 32) * 32 + fc * 4;
    const __half* vsrc0 = Vg + (size_t)fr * SEQ + fc * 8;
    const __half* vsrc1 = Vg + (size_t)(fr + 32) * SEQ + fc * 8;

    // Prologue: stage tiles 0..2
#pragma unroll
    for (int s = 0; s < 3; s++) {
        uint32_t soff = (uint32_t)(s * (ASTAGE * 4));
        int gk = s * 2048, gv = s * 64;
        cpa16(kdst0 + soff, ksrc0 + gk);
        cpa16(kdst1 + soff, ksrc1 + gk);
        cpa16(vdst0 + soff, vsrc0 + gv);
        cpa16(vdst1 + soff, vsrc1 + gv);
        CP_COMMIT();
    }

    float lsum[4];
#pragma unroll
    for (int i = 0; i < 4; i++) lsum[i] = 0.0f;
    float o[8][4];
#pragma unroll
    for (int nt = 0; nt < 8; nt++)
#pragma unroll
        for (int i = 0; i < 4; i++) o[nt][i] = 0.0f;

    for (int it = 0; it < NT; it++) {
        if (it + 2 < NT)      CP_WAIT(2);
        else if (it + 1 < NT) CP_WAIT(1);
        else                  CP_WAIT(0);
        __syncthreads();

        const uint32_t* KsB = Kst + (it & 3) * ASTAGE;
        const uint32_t* VtB = KsB + 2048;

        // S = Q K^T
        float s[8][4];
#pragma unroll
        for (int nt = 0; nt < 8; nt++)
#pragma unroll
            for (int i = 0; i < 4; i++) s[nt][i] = 0.0f;

#pragma unroll
        for (int b2 = 0; b2 < 2; b2++) {
            int r0 = wm + g, r1 = wm + g + 8;
            uint4 qa0 = *(const uint4*)&Qs[r0 * 32 + (((b2 << 4) ^ ((r0 & 1) << 4)) + t * 4)];
            uint4 qa1 = *(const uint4*)&Qs[r1 * 32 + (((b2 << 4) ^ ((r1 & 1) << 4)) + t * 4)];
#pragma unroll
            for (int nt = 0; nt < 8; nt++) {
                int rn = nt * 8 + g;
                uint4 kb = *(const uint4*)&KsB[rn * 32 + (((b2 << 4) ^ ((rn & 1) << 4)) + t * 4)];
                mma16(s[nt], qa0.x, qa1.x, qa0.y, qa1.y, kb.x, kb.y);
                mma16(s[nt], qa0.z, qa1.z, qa0.w, qa1.w, kb.z, kb.w);
            }
        }

        // p = ex2(s) -> half2 A-fragments; row sums via ones-mma
        uint32_t ah[4][4];
#pragma unroll
        for (int kb2 = 0; kb2 < 4; kb2++) {
            float p00 = ex2f(s[2*kb2][0]),   p01 = ex2f(s[2*kb2][1]);
            float p02 = ex2f(s[2*kb2][2]),   p03 = ex2f(s[2*kb2][3]);
            float p10 = ex2f(s[2*kb2+1][0]), p11 = ex2f(s[2*kb2+1][1]);
            float p12 = ex2f(s[2*kb2+1][2]), p13 = ex2f(s[2*kb2+1][3]);
            ah[kb2][0] = f2h2(p00, p01);
            ah[kb2][1] = f2h2(p02, p03);
            ah[kb2][2] = f2h2(p10, p11);
            ah[kb2][3] = f2h2(p12, p13);
            mma16(lsum, ah[kb2][0], ah[kb2][1], ah[kb2][2], ah[kb2][3], ONES2, ONES2);
        }

        // O += P V
#pragma unroll
        for (int b2 = 0; b2 < 2; b2++) {
#pragma unroll
            for (int nt = 0; nt < 8; nt++) {
                int rn = nt * 8 + g;
                uint4 vb = *(const uint4*)&VtB[rn * 32 + (((b2 << 4) ^ ((rn & 1) << 4)) + t * 4)];
                mma16(o[nt], ah[2*b2][0],   ah[2*b2][1],   ah[2*b2][2],   ah[2*b2][3],
                      vb.x, vb.y);
                mma16(o[nt], ah[2*b2+1][0], ah[2*b2+1][1], ah[2*b2+1][2], ah[2*b2+1][3],
                      vb.z, vb.w);
            }
        }

        if (it + 3 < NT) {
            uint32_t soff = (uint32_t)(((it + 3) & 3) * (ASTAGE * 4));
            int gk = (it + 3) * 2048, gv = (it + 3) * 64;
            cpa16(kdst0 + soff, ksrc0 + gk);
            cpa16(kdst1 + soff, ksrc1 + gk);
            cpa16(vdst0 + soff, vsrc0 + gv);
            cpa16(vdst1 + soff, vsrc1 + gv);
            CP_COMMIT();
        }
    }

    int b = bh >> 4, h = bh & 15;
    float l_i[2] = { lsum[0], lsum[2] };
#pragma unroll
    for (int slot = 0; slot < 2; slot++) {
        float inv = 1.0f / l_i[slot];
        int row = wm + g + slot * 8;
        size_t m = (size_t)b * SEQ + qbase + row;
        uint4 lo = make_uint4(f2h2(o[0][slot*2]*inv, o[0][slot*2+1]*inv),
                              f2h2(o[1][slot*2]*inv, o[1][slot*2+1]*inv),
                              f2h2(o[2][slot*2]*inv, o[2][slot*2+1]*inv),
                              f2h2(o[3][slot*2]*inv, o[3][slot*2+1]*inv));
        uint4 hi = make_uint4(f2h2(o[4][slot*2]*inv, o[4][slot*2+1]*inv),
                              f2h2(o[5][slot*2]*inv, o[5][slot*2+1]*inv),
                              f2h2(o[6][slot*2]*inv, o[6][slot*2+1]*inv),
                              f2h2(o[7][slot*2]*inv, o[7][slot*2+1]*inv));
        *(uint4*)&g_oh[m * 512 + h * 32 + t * 4] = lo;
        *(uint4*)&g_oh[m * 512 + h * 32 + 16 + t * 4] = hi;
    }
}

// ---------------------------------------------------------------------------
// Kernel 4: projection GEMM (pipelined), fp32 out.
// ---------------------------------------------------------------------------
__global__ __launch_bounds__(256, 3) void proj_gemm_h(
    const float* __restrict__ bp, float* __restrict__ out)
{
    extern __shared__ __align__(16) uint32_t sm[];
    const int tid = threadIdx.x;
    const int warp = tid >> 5, lane = tid & 31;
    const int g = lane >> 2, t = lane & 3;
    const int wm = (warp >> 1) * 32, wn = (warp & 1) * 32;
    const int mBase = blockIdx.y * 128, nBase = blockIdx.x * 64;

    GemmAcc A;
    gemm_mainloop(sm, g_oh, g_wph, mBase, nBase, tid, wm, wn, g, t, A);

#pragma unroll
    for (int mt = 0; mt < 2; mt++)
#pragma unroll
        for (int hf = 0; hf < 2; hf++) {
            int row = mBase + wm + mt * 16 + g + hf * 8;
#pragma unroll
            for (int nt = 0; nt < 4; nt++) {
                int col = nBase + wn + nt * 8 + 2 * t;
                float2 r = make_float2(A.a[mt][nt][hf * 2 + 0] + bp[col],
                                       A.a[mt][nt][hf * 2 + 1] + bp[col + 1]);
                *(float2*)&out[(size_t)row * DMODEL + col] = r;
            }
        }
}

// ---------------------------------------------------------------------------
// Launch. Inputs: 0:x 1:w_qkv 2:b_qkv 3:w_proj 4:b_proj 5:qg 6:qb 7:kg 8:kb
// ---------------------------------------------------------------------------
extern "C" void kernel_launch(void* const* d_in, const int* in_sizes, int n_in,
                              void* d_out, int out_size)
{
    const float* x      = (const float*)d_in[0];
    const float* w_qkv  = (const float*)d_in[1];
    const float* b_qkv  = (const float*)d_in[2];
    const float* w_proj = (const float*)d_in[3];
    const float* b_proj = (const float*)d_in[4];
    const float* q_g    = (const float*)d_in[5];
    const float* q_b    = (const float*)d_in[6];
    const float* k_g    = (const float*)d_in[7];
    const float* k_b    = (const float*)d_in[8];
    float* out = (float*)d_out;

    cudaFuncSetAttribute(attn_h_kernel,
                         cudaFuncAttributeMaxDynamicSharedMemorySize, ATTN_SMEM);
    cudaFuncSetAttribute(qkv_gemm_h,
                         cudaFuncAttributeMaxDynamicSharedMemorySize, GEMM_SMEM);
    cudaFuncSetAttribute(proj_gemm_h,
                         cudaFuncAttributeMaxDynamicSharedMemorySize, GEMM_SMEM);

    prep_kernel<<<NU4_TOT / 256, 256>>>(x, w_qkv, w_proj);

    dim3 g1(NQKV / 64, MROWS / 128);    // (48, 32)
    qkv_gemm_h<<<g1, 256, GEMM_SMEM>>>(b_qkv, q_g, q_b, k_g, k_b);

    dim3 g3(SEQ / 128, BH);             // (16, 32)
    attn_h_kernel<<<g3, 256, ATTN_SMEM>>>();

    dim3 g4(DMODEL / 64, MROWS / 128);  // (16, 32)
    proj_gemm_h<<<g4, 256, GEMM_SMEM>>>(b_proj, out);
}